// round 2
// baseline (speedup 1.0000x reference)
#include <cuda_runtime.h>
#include <math.h>

#define HIDDEN 1024
#define INTER  2816
#define NE     8
#define TOPK   2
#define NTASKEXP 4
#define NGEN   2
#define NTOK   8192
#define NPAIR  (NTOK*TOPK)

#define BM 64
#define BN 64
#define BK 16

// ---- scratch (static device memory; no runtime allocation) ----
__device__ int   g_active[NE];
__device__ int   g_counts[NE];
__device__ int   g_offsets[NE];
__device__ int   g_cursor[NE];
__device__ int   g_pair_token[NPAIR];
__device__ int   g_tok_e[NTOK * TOPK];
__device__ float g_tok_w[NTOK * TOPK];
__device__ int   g_tok_pair[NTOK * TOPK];
__device__ float g_act[(size_t)NPAIR * INTER];       // ~184.5 MB
__device__ float g_pair_out[(size_t)NPAIR * HIDDEN]; // ~67 MB

// ---------------------------------------------------------------------------
// K0: task-level routing. scores = task_router_w @ task_emb[task_id];
// top-4 experts + generalists {6,7} -> active mask. Also resets counters.
// ---------------------------------------------------------------------------
__global__ void k_task_route(const float* __restrict__ task_emb,
                             const int* __restrict__ task_id_p,
                             const float* __restrict__ trw) {
    __shared__ float sc[NE];
    int tid  = threadIdx.x;
    int e    = tid / 32;
    int lane = tid % 32;
    int task_id = task_id_p[0];
    const float* tv = task_emb + (size_t)task_id * HIDDEN;

    float acc = 0.f;
    if (e < NE) {
        for (int d = lane; d < HIDDEN; d += 32)
            acc += trw[(size_t)e * HIDDEN + d] * tv[d];
        #pragma unroll
        for (int o = 16; o > 0; o >>= 1)
            acc += __shfl_xor_sync(0xFFFFFFFFu, acc, o);
        if (lane == 0) sc[e] = acc;
    }
    __syncthreads();
    if (tid == 0) {
        float s[NE];
        bool  act[NE];
        for (int i = 0; i < NE; i++) { s[i] = sc[i]; act[i] = false; }
        for (int k = 0; k < NTASKEXP; k++) {
            int best = 0; float bv = -1e30f;
            for (int i = 0; i < NE; i++)
                if (!act[i] && s[i] > bv) { bv = s[i]; best = i; }
            act[best] = true;
        }
        for (int i = NE - NGEN; i < NE; i++) act[i] = true;
        for (int i = 0; i < NE; i++) {
            g_active[i] = act[i] ? 1 : 0;
            g_counts[i] = 0;
            g_cursor[i] = 0;
        }
    }
}

// ---------------------------------------------------------------------------
// K1: token gating. One warp per token. logits = (h + task_vec) @ gw^T,
// masked softmax over active experts, top-2, normalize, count per expert.
// ---------------------------------------------------------------------------
__global__ void k_gate(const float* __restrict__ hs,
                       const float* __restrict__ task_emb,
                       const int* __restrict__ task_id_p,
                       const float* __restrict__ gw) {
    int warp = (blockIdx.x * blockDim.x + threadIdx.x) / 32;
    int lane = threadIdx.x % 32;
    if (warp >= NTOK) return;
    const float* tv = task_emb + (size_t)task_id_p[0] * HIDDEN;
    const float* h  = hs + (size_t)warp * HIDDEN;

    float acc[NE];
    #pragma unroll
    for (int e = 0; e < NE; e++) acc[e] = 0.f;

    for (int d = lane; d < HIDDEN; d += 32) {
        float x = h[d] + tv[d];
        #pragma unroll
        for (int e = 0; e < NE; e++)
            acc[e] += x * gw[(size_t)e * HIDDEN + d];
    }
    #pragma unroll
    for (int e = 0; e < NE; e++) {
        #pragma unroll
        for (int o = 16; o > 0; o >>= 1)
            acc[e] += __shfl_xor_sync(0xFFFFFFFFu, acc[e], o);
    }
    if (lane == 0) {
        float m = -1e30f;
        #pragma unroll
        for (int e = 0; e < NE; e++)
            if (g_active[e] && acc[e] > m) m = acc[e];
        float p[NE]; float Z = 0.f;
        #pragma unroll
        for (int e = 0; e < NE; e++) {
            p[e] = g_active[e] ? expf(acc[e] - m) : 0.f;
            Z += p[e];
        }
        float inv = 1.f / Z;
        int   i0 = 0; float v0 = -1.f;
        #pragma unroll
        for (int e = 0; e < NE; e++) {
            float s = p[e] * inv;
            if (s > v0) { v0 = s; i0 = e; }
        }
        int i1 = -1; float v1 = -1.f;
        #pragma unroll
        for (int e = 0; e < NE; e++) {
            if (e == i0) continue;
            float s = p[e] * inv;
            if (s > v1) { v1 = s; i1 = e; }
        }
        float ws = v0 + v1 + 1e-6f;
        g_tok_e[warp * 2 + 0] = i0;
        g_tok_e[warp * 2 + 1] = i1;
        g_tok_w[warp * 2 + 0] = v0 / ws;
        g_tok_w[warp * 2 + 1] = v1 / ws;
        atomicAdd(&g_counts[i0], 1);
        atomicAdd(&g_counts[i1], 1);
    }
}

// ---------------------------------------------------------------------------
// K2: exclusive prefix over counts
// ---------------------------------------------------------------------------
__global__ void k_prefix() {
    if (threadIdx.x == 0) {
        int o = 0;
        for (int e = 0; e < NE; e++) { g_offsets[e] = o; o += g_counts[e]; }
    }
}

// ---------------------------------------------------------------------------
// K3: placement — compact per-expert token lists
// ---------------------------------------------------------------------------
__global__ void k_place() {
    int n = blockIdx.x * blockDim.x + threadIdx.x;
    if (n >= NTOK) return;
    #pragma unroll
    for (int k = 0; k < TOPK; k++) {
        int e = g_tok_e[n * 2 + k];
        int slot = atomicAdd(&g_cursor[e], 1);
        int idx = g_offsets[e] + slot;
        g_pair_token[idx] = n;
        g_tok_pair[n * 2 + k] = idx;
    }
}

// ---------------------------------------------------------------------------
// K4: GEMM1 (gate & up fused) + SwiGLU.  M=cnt[e] (gathered), N=INTER, K=HIDDEN
// ---------------------------------------------------------------------------
__global__ void __launch_bounds__(256, 2)
k_ffn1(const float* __restrict__ hs,
       const float* __restrict__ gp,
       const float* __restrict__ up) {
    int e    = blockIdx.z;
    int cnt  = g_counts[e];
    int moff = blockIdx.y * BM;
    if (moff >= cnt) return;
    int off = g_offsets[e];
    int n0  = blockIdx.x * BN;

    __shared__ float As[BK][BM + 4];
    __shared__ float Bg[BK][BN + 4];
    __shared__ float Bu[BK][BN + 4];
    __shared__ int   s_tok[BM];

    int tid = threadIdx.x;
    if (tid < BM) {
        int r = moff + tid;
        s_tok[tid] = (r < cnt) ? g_pair_token[off + r] : 0;
    }
    __syncthreads();

    int tx = tid % 16, ty = tid / 16;
    int lr = tid / 4;         // 0..63
    int lc = (tid % 4) * 4;   // 0,4,8,12

    const float* gpe = gp + (size_t)e * INTER * HIDDEN;
    const float* upe = up + (size_t)e * INTER * HIDDEN;

    float accg[4][4], accu[4][4];
    #pragma unroll
    for (int i = 0; i < 4; i++)
        #pragma unroll
        for (int j = 0; j < 4; j++) { accg[i][j] = 0.f; accu[i][j] = 0.f; }

    int my_tok = s_tok[lr];
    for (int k0 = 0; k0 < HIDDEN; k0 += BK) {
        float4 av = *(const float4*)&hs[(size_t)my_tok * HIDDEN + k0 + lc];
        float4 bg = *(const float4*)&gpe[(size_t)(n0 + lr) * HIDDEN + k0 + lc];
        float4 bu = *(const float4*)&upe[(size_t)(n0 + lr) * HIDDEN + k0 + lc];
        As[lc + 0][lr] = av.x; As[lc + 1][lr] = av.y; As[lc + 2][lr] = av.z; As[lc + 3][lr] = av.w;
        Bg[lc + 0][lr] = bg.x; Bg[lc + 1][lr] = bg.y; Bg[lc + 2][lr] = bg.z; Bg[lc + 3][lr] = bg.w;
        Bu[lc + 0][lr] = bu.x; Bu[lc + 1][lr] = bu.y; Bu[lc + 2][lr] = bu.z; Bu[lc + 3][lr] = bu.w;
        __syncthreads();
        #pragma unroll
        for (int k = 0; k < BK; k++) {
            float a[4], bgv[4], buv[4];
            *(float4*)a   = *(const float4*)&As[k][ty * 4];
            *(float4*)bgv = *(const float4*)&Bg[k][tx * 4];
            *(float4*)buv = *(const float4*)&Bu[k][tx * 4];
            #pragma unroll
            for (int i = 0; i < 4; i++)
                #pragma unroll
                for (int j = 0; j < 4; j++) {
                    accg[i][j] += a[i] * bgv[j];
                    accu[i][j] += a[i] * buv[j];
                }
        }
        __syncthreads();
    }

    #pragma unroll
    for (int i = 0; i < 4; i++) {
        int r = moff + ty * 4 + i;
        if (r >= cnt) continue;
        float* dst = g_act + (size_t)(off + r) * INTER + n0 + tx * 4;
        #pragma unroll
        for (int j = 0; j < 4; j++) {
            float g = accg[i][j];
            float u = accu[i][j];
            float sg = g / (1.f + expf(-g));
            dst[j] = sg * u;
        }
    }
}

// ---------------------------------------------------------------------------
// K5: GEMM2 (down). M=cnt[e], N=HIDDEN, K=INTER
// ---------------------------------------------------------------------------
__global__ void __launch_bounds__(256, 2)
k_ffn2(const float* __restrict__ dp) {
    int e    = blockIdx.z;
    int cnt  = g_counts[e];
    int moff = blockIdx.y * BM;
    if (moff >= cnt) return;
    int off = g_offsets[e];
    int n0  = blockIdx.x * BN;

    __shared__ float As[BK][BM + 4];
    __shared__ float Bs[BK][BN + 4];

    int tid = threadIdx.x;
    int tx = tid % 16, ty = tid / 16;
    int lr = tid / 4;
    int lc = (tid % 4) * 4;

    const float* dpe = dp + (size_t)e * HIDDEN * INTER;
    int ar = moff + lr; if (ar > cnt - 1) ar = cnt - 1;  // clamp (safe dup read)
    size_t arow = (size_t)(off + ar) * INTER;

    float acc[4][4];
    #pragma unroll
    for (int i = 0; i < 4; i++)
        #pragma unroll
        for (int j = 0; j < 4; j++) acc[i][j] = 0.f;

    for (int k0 = 0; k0 < INTER; k0 += BK) {
        float4 av = *(const float4*)&g_act[arow + k0 + lc];
        float4 bv = *(const float4*)&dpe[(size_t)(n0 + lr) * INTER + k0 + lc];
        As[lc + 0][lr] = av.x; As[lc + 1][lr] = av.y; As[lc + 2][lr] = av.z; As[lc + 3][lr] = av.w;
        Bs[lc + 0][lr] = bv.x; Bs[lc + 1][lr] = bv.y; Bs[lc + 2][lr] = bv.z; Bs[lc + 3][lr] = bv.w;
        __syncthreads();
        #pragma unroll
        for (int k = 0; k < BK; k++) {
            float a[4], b[4];
            *(float4*)a = *(const float4*)&As[k][ty * 4];
            *(float4*)b = *(const float4*)&Bs[k][tx * 4];
            #pragma unroll
            for (int i = 0; i < 4; i++)
                #pragma unroll
                for (int j = 0; j < 4; j++)
                    acc[i][j] += a[i] * b[j];
        }
        __syncthreads();
    }

    #pragma unroll
    for (int i = 0; i < 4; i++) {
        int r = moff + ty * 4 + i;
        if (r >= cnt) continue;
        float* dst = g_pair_out + (size_t)(off + r) * HIDDEN + n0 + tx * 4;
        #pragma unroll
        for (int j = 0; j < 4; j++) dst[j] = acc[i][j];
    }
}

// ---------------------------------------------------------------------------
// K6: weighted combine -> d_out
// ---------------------------------------------------------------------------
__global__ void k_combine(float* __restrict__ out) {
    int n = blockIdx.x;
    int p0 = g_tok_pair[n * 2 + 0];
    int p1 = g_tok_pair[n * 2 + 1];
    float w0 = g_tok_w[n * 2 + 0];
    float w1 = g_tok_w[n * 2 + 1];
    for (int d = threadIdx.x * 4; d < HIDDEN; d += blockDim.x * 4) {
        float4 a = *(const float4*)&g_pair_out[(size_t)p0 * HIDDEN + d];
        float4 b = *(const float4*)&g_pair_out[(size_t)p1 * HIDDEN + d];
        float4 o;
        o.x = w0 * a.x + w1 * b.x;
        o.y = w0 * a.y + w1 * b.y;
        o.z = w0 * a.z + w1 * b.z;
        o.w = w0 * a.w + w1 * b.w;
        *(float4*)&out[(size_t)n * HIDDEN + d] = o;
    }
}

// ---------------------------------------------------------------------------
extern "C" void kernel_launch(void* const* d_in, const int* in_sizes, int n_in,
                              void* d_out, int out_size) {
    const float* hs   = (const float*)d_in[0];
    const int*   tid  = (const int*)d_in[1];
    const float* temb = (const float*)d_in[2];
    const float* trw  = (const float*)d_in[3];
    const float* gw   = (const float*)d_in[4];
    const float* gp   = (const float*)d_in[5];
    const float* up   = (const float*)d_in[6];
    const float* dp   = (const float*)d_in[7];
    float* out = (float*)d_out;

    k_task_route<<<1, 256>>>(temb, tid, trw);
    k_gate<<<NTOK / 8, 256>>>(hs, temb, tid, gw);
    k_prefix<<<1, 32>>>();
    k_place<<<NTOK / 256, 256>>>();
    dim3 g1(INTER / BN, NTOK / BM, NE);   // 44 x 128 x 8
    k_ffn1<<<g1, 256>>>(hs, gp, up);
    dim3 g2(HIDDEN / BN, NTOK / BM, NE);  // 16 x 128 x 8
    k_ffn2<<<g2, 256>>>(dp);
    k_combine<<<NTOK, 256>>>(out);
}

// round 3
// speedup vs baseline: 2.3955x; 2.3955x over previous
#include <cuda_runtime.h>
#include <math.h>
#include <stdint.h>

#define HIDDEN 1024
#define INTER  2816
#define NE     8
#define TOPK   2
#define NTASKEXP 4
#define NGEN   2
#define NTOK   8192
#define NPAIR  (NTOK*TOPK)

#define BM 128
#define BN 64
#define BK 32

// ---- scratch (static device memory; no runtime allocation) ----
__device__ int   g_active[NE];
__device__ int   g_counts[NE];
__device__ int   g_offsets[NE];
__device__ int   g_cursor[NE];
__device__ int   g_pair_token[NPAIR];
__device__ int   g_tok_e[NTOK * TOPK];
__device__ float g_tok_w[NTOK * TOPK];
__device__ int   g_tok_pair[NTOK * TOPK];
__device__ float g_act[(size_t)NPAIR * INTER];       // ~184.5 MB
__device__ float g_pair_out[(size_t)NPAIR * HIDDEN]; // ~67 MB

// ---------------------------------------------------------------------------
// helpers: tf32 convert + m16n8k8 tf32 mma
// ---------------------------------------------------------------------------
__device__ __forceinline__ uint32_t f2tf32(float x) {
    uint32_t r;
    asm("cvt.rna.tf32.f32 %0, %1;" : "=r"(r) : "f"(x));
    return r;
}

__device__ __forceinline__ void mma_tf32(float* c, const uint32_t* a,
                                         uint32_t b0, uint32_t b1) {
    asm volatile(
        "mma.sync.aligned.m16n8k8.row.col.f32.tf32.tf32.f32 "
        "{%0,%1,%2,%3}, {%4,%5,%6,%7}, {%8,%9}, {%0,%1,%2,%3};"
        : "+f"(c[0]), "+f"(c[1]), "+f"(c[2]), "+f"(c[3])
        : "r"(a[0]), "r"(a[1]), "r"(a[2]), "r"(a[3]), "r"(b0), "r"(b1));
}

// ---------------------------------------------------------------------------
// K0: task-level routing (top-4 + generalists), reset counters
// ---------------------------------------------------------------------------
__global__ void k_task_route(const float* __restrict__ task_emb,
                             const int* __restrict__ task_id_p,
                             const float* __restrict__ trw) {
    __shared__ float sc[NE];
    int tid  = threadIdx.x;
    int e    = tid / 32;
    int lane = tid % 32;
    int task_id = task_id_p[0];
    const float* tv = task_emb + (size_t)task_id * HIDDEN;

    float acc = 0.f;
    if (e < NE) {
        for (int d = lane; d < HIDDEN; d += 32)
            acc += trw[(size_t)e * HIDDEN + d] * tv[d];
        #pragma unroll
        for (int o = 16; o > 0; o >>= 1)
            acc += __shfl_xor_sync(0xFFFFFFFFu, acc, o);
        if (lane == 0) sc[e] = acc;
    }
    __syncthreads();
    if (tid == 0) {
        float s[NE]; bool act[NE];
        for (int i = 0; i < NE; i++) { s[i] = sc[i]; act[i] = false; }
        for (int k = 0; k < NTASKEXP; k++) {
            int best = 0; float bv = -1e30f;
            for (int i = 0; i < NE; i++)
                if (!act[i] && s[i] > bv) { bv = s[i]; best = i; }
            act[best] = true;
        }
        for (int i = NE - NGEN; i < NE; i++) act[i] = true;
        for (int i = 0; i < NE; i++) {
            g_active[i] = act[i] ? 1 : 0;
            g_counts[i] = 0;
            g_cursor[i] = 0;
        }
    }
}

// ---------------------------------------------------------------------------
// K1: token gating (exact fp32), per-expert counts
// ---------------------------------------------------------------------------
__global__ void k_gate(const float* __restrict__ hs,
                       const float* __restrict__ task_emb,
                       const int* __restrict__ task_id_p,
                       const float* __restrict__ gw) {
    int warp = (blockIdx.x * blockDim.x + threadIdx.x) / 32;
    int lane = threadIdx.x % 32;
    if (warp >= NTOK) return;
    const float* tv = task_emb + (size_t)task_id_p[0] * HIDDEN;
    const float* h  = hs + (size_t)warp * HIDDEN;

    float acc[NE];
    #pragma unroll
    for (int e = 0; e < NE; e++) acc[e] = 0.f;

    for (int d = lane; d < HIDDEN; d += 32) {
        float x = h[d] + tv[d];
        #pragma unroll
        for (int e = 0; e < NE; e++)
            acc[e] += x * gw[(size_t)e * HIDDEN + d];
    }
    #pragma unroll
    for (int e = 0; e < NE; e++) {
        #pragma unroll
        for (int o = 16; o > 0; o >>= 1)
            acc[e] += __shfl_xor_sync(0xFFFFFFFFu, acc[e], o);
    }
    if (lane == 0) {
        float m = -1e30f;
        #pragma unroll
        for (int e = 0; e < NE; e++)
            if (g_active[e] && acc[e] > m) m = acc[e];
        float p[NE]; float Z = 0.f;
        #pragma unroll
        for (int e = 0; e < NE; e++) {
            p[e] = g_active[e] ? expf(acc[e] - m) : 0.f;
            Z += p[e];
        }
        float inv = 1.f / Z;
        int i0 = 0; float v0 = -1.f;
        #pragma unroll
        for (int e = 0; e < NE; e++) {
            float s = p[e] * inv;
            if (s > v0) { v0 = s; i0 = e; }
        }
        int i1 = -1; float v1 = -1.f;
        #pragma unroll
        for (int e = 0; e < NE; e++) {
            if (e == i0) continue;
            float s = p[e] * inv;
            if (s > v1) { v1 = s; i1 = e; }
        }
        float ws = v0 + v1 + 1e-6f;
        g_tok_e[warp * 2 + 0] = i0;
        g_tok_e[warp * 2 + 1] = i1;
        g_tok_w[warp * 2 + 0] = v0 / ws;
        g_tok_w[warp * 2 + 1] = v1 / ws;
        atomicAdd(&g_counts[i0], 1);
        atomicAdd(&g_counts[i1], 1);
    }
}

__global__ void k_prefix() {
    if (threadIdx.x == 0) {
        int o = 0;
        for (int e = 0; e < NE; e++) { g_offsets[e] = o; o += g_counts[e]; }
    }
}

__global__ void k_place() {
    int n = blockIdx.x * blockDim.x + threadIdx.x;
    if (n >= NTOK) return;
    #pragma unroll
    for (int k = 0; k < TOPK; k++) {
        int e = g_tok_e[n * 2 + k];
        int slot = atomicAdd(&g_cursor[e], 1);
        int idx = g_offsets[e] + slot;
        g_pair_token[idx] = n;
        g_tok_pair[n * 2 + k] = idx;
    }
}

// ---------------------------------------------------------------------------
// K4: GEMM1 (gate & up fused, tf32 tensor cores) + SwiGLU
//     tiles: BM=128, BN=64, BK=32; 8 warps, warp tile 32x32 (each matrix)
// ---------------------------------------------------------------------------
__global__ void __launch_bounds__(256)
k_ffn1(const float* __restrict__ hs,
       const float* __restrict__ gp,
       const float* __restrict__ up) {
    int e   = blockIdx.z;
    int cnt = g_counts[e];
    int moff = blockIdx.y * BM;
    if (moff >= cnt) return;
    int off = g_offsets[e];
    int n0  = blockIdx.x * BN;

    __shared__ uint32_t As[BM][BK + 4];
    __shared__ uint32_t Bg[BN][BK + 4];
    __shared__ uint32_t Bu[BN][BK + 4];

    int tid  = threadIdx.x;
    int warp = tid >> 5;
    int lane = tid & 31;
    int wm = warp >> 1;        // 0..3  (M)
    int wn = warp & 1;         // 0..1  (N)

    int lrow = tid >> 3;       // 0..31
    int lcol = (tid & 7) * 4;  // 0..28

    const float* gpe = gp + (size_t)e * INTER * HIDDEN;
    const float* upe = up + (size_t)e * INTER * HIDDEN;

    // A row pointers (gathered tokens, clamped duplicate reads)
    const float* aptr[4];
    #pragma unroll
    for (int i = 0; i < 4; i++) {
        int r = moff + lrow + 32 * i;
        if (r > cnt - 1) r = cnt - 1;
        aptr[i] = hs + (size_t)g_pair_token[off + r] * HIDDEN + lcol;
    }
    const float* bgp[2]; const float* bup[2];
    #pragma unroll
    for (int i = 0; i < 2; i++) {
        bgp[i] = gpe + (size_t)(n0 + lrow + 32 * i) * HIDDEN + lcol;
        bup[i] = upe + (size_t)(n0 + lrow + 32 * i) * HIDDEN + lcol;
    }

    float accg[2][4][4], accu[2][4][4];
    #pragma unroll
    for (int mt = 0; mt < 2; mt++)
        #pragma unroll
        for (int nt = 0; nt < 4; nt++)
            #pragma unroll
            for (int q = 0; q < 4; q++) { accg[mt][nt][q] = 0.f; accu[mt][nt][q] = 0.f; }

    for (int k0 = 0; k0 < HIDDEN; k0 += BK) {
        #pragma unroll
        for (int i = 0; i < 4; i++) {
            float4 v = *(const float4*)(aptr[i] + k0);
            uint4 t = make_uint4(f2tf32(v.x), f2tf32(v.y), f2tf32(v.z), f2tf32(v.w));
            *(uint4*)&As[lrow + 32 * i][lcol] = t;
        }
        #pragma unroll
        for (int i = 0; i < 2; i++) {
            float4 v = *(const float4*)(bgp[i] + k0);
            *(uint4*)&Bg[lrow + 32 * i][lcol] =
                make_uint4(f2tf32(v.x), f2tf32(v.y), f2tf32(v.z), f2tf32(v.w));
            float4 u = *(const float4*)(bup[i] + k0);
            *(uint4*)&Bu[lrow + 32 * i][lcol] =
                make_uint4(f2tf32(u.x), f2tf32(u.y), f2tf32(u.z), f2tf32(u.w));
        }
        __syncthreads();

        #pragma unroll
        for (int ks = 0; ks < 4; ks++) {
            int kb = ks * 8 + (lane & 3);
            uint32_t a0[4], a1[4];
            int r0 = wm * 32 + (lane >> 2);
            a0[0] = As[r0][kb];      a0[1] = As[r0 + 8][kb];
            a0[2] = As[r0][kb + 4];  a0[3] = As[r0 + 8][kb + 4];
            a1[0] = As[r0 + 16][kb];     a1[1] = As[r0 + 24][kb];
            a1[2] = As[r0 + 16][kb + 4]; a1[3] = As[r0 + 24][kb + 4];
            #pragma unroll
            for (int nt = 0; nt < 4; nt++) {
                int cn = wn * 32 + nt * 8 + (lane >> 2);
                uint32_t bg0 = Bg[cn][kb], bg1 = Bg[cn][kb + 4];
                uint32_t bu0 = Bu[cn][kb], bu1 = Bu[cn][kb + 4];
                mma_tf32(accg[0][nt], a0, bg0, bg1);
                mma_tf32(accg[1][nt], a1, bg0, bg1);
                mma_tf32(accu[0][nt], a0, bu0, bu1);
                mma_tf32(accu[1][nt], a1, bu0, bu1);
            }
        }
        __syncthreads();
    }

    // epilogue: SwiGLU, scatter to g_act
    #pragma unroll
    for (int mt = 0; mt < 2; mt++) {
        #pragma unroll
        for (int nt = 0; nt < 4; nt++) {
            int r0 = moff + wm * 32 + mt * 16 + (lane >> 2);
            int c  = n0 + wn * 32 + nt * 8 + 2 * (lane & 3);
            if (r0 < cnt) {
                float* dst = g_act + (size_t)(off + r0) * INTER + c;
                float g0 = accg[mt][nt][0], u0 = accu[mt][nt][0];
                float g1 = accg[mt][nt][1], u1 = accu[mt][nt][1];
                dst[0] = (g0 / (1.f + expf(-g0))) * u0;
                dst[1] = (g1 / (1.f + expf(-g1))) * u1;
            }
            int r1 = r0 + 8;
            if (r1 < cnt) {
                float* dst = g_act + (size_t)(off + r1) * INTER + c;
                float g0 = accg[mt][nt][2], u0 = accu[mt][nt][2];
                float g1 = accg[mt][nt][3], u1 = accu[mt][nt][3];
                dst[0] = (g0 / (1.f + expf(-g0))) * u0;
                dst[1] = (g1 / (1.f + expf(-g1))) * u1;
            }
        }
    }
}

// ---------------------------------------------------------------------------
// K5: GEMM2 (down, tf32). M=cnt, N=HIDDEN, K=INTER
// ---------------------------------------------------------------------------
__global__ void __launch_bounds__(256)
k_ffn2(const float* __restrict__ dp) {
    int e   = blockIdx.z;
    int cnt = g_counts[e];
    int moff = blockIdx.y * BM;
    if (moff >= cnt) return;
    int off = g_offsets[e];
    int n0  = blockIdx.x * BN;

    __shared__ uint32_t As[BM][BK + 4];
    __shared__ uint32_t Bs[BN][BK + 4];

    int tid  = threadIdx.x;
    int warp = tid >> 5;
    int lane = tid & 31;
    int wm = warp >> 1;
    int wn = warp & 1;

    int lrow = tid >> 3;
    int lcol = (tid & 7) * 4;

    const float* dpe = dp + (size_t)e * HIDDEN * INTER;

    const float* aptr[4];
    #pragma unroll
    for (int i = 0; i < 4; i++) {
        int r = moff + lrow + 32 * i;
        if (r > cnt - 1) r = cnt - 1;
        aptr[i] = g_act + (size_t)(off + r) * INTER + lcol;
    }
    const float* bptr[2];
    #pragma unroll
    for (int i = 0; i < 2; i++)
        bptr[i] = dpe + (size_t)(n0 + lrow + 32 * i) * INTER + lcol;

    float acc[2][4][4];
    #pragma unroll
    for (int mt = 0; mt < 2; mt++)
        #pragma unroll
        for (int nt = 0; nt < 4; nt++)
            #pragma unroll
            for (int q = 0; q < 4; q++) acc[mt][nt][q] = 0.f;

    for (int k0 = 0; k0 < INTER; k0 += BK) {
        #pragma unroll
        for (int i = 0; i < 4; i++) {
            float4 v = *(const float4*)(aptr[i] + k0);
            *(uint4*)&As[lrow + 32 * i][lcol] =
                make_uint4(f2tf32(v.x), f2tf32(v.y), f2tf32(v.z), f2tf32(v.w));
        }
        #pragma unroll
        for (int i = 0; i < 2; i++) {
            float4 v = *(const float4*)(bptr[i] + k0);
            *(uint4*)&Bs[lrow + 32 * i][lcol] =
                make_uint4(f2tf32(v.x), f2tf32(v.y), f2tf32(v.z), f2tf32(v.w));
        }
        __syncthreads();

        #pragma unroll
        for (int ks = 0; ks < 4; ks++) {
            int kb = ks * 8 + (lane & 3);
            uint32_t a0[4], a1[4];
            int r0 = wm * 32 + (lane >> 2);
            a0[0] = As[r0][kb];      a0[1] = As[r0 + 8][kb];
            a0[2] = As[r0][kb + 4];  a0[3] = As[r0 + 8][kb + 4];
            a1[0] = As[r0 + 16][kb];     a1[1] = As[r0 + 24][kb];
            a1[2] = As[r0 + 16][kb + 4]; a1[3] = As[r0 + 24][kb + 4];
            #pragma unroll
            for (int nt = 0; nt < 4; nt++) {
                int cn = wn * 32 + nt * 8 + (lane >> 2);
                uint32_t b0 = Bs[cn][kb], b1 = Bs[cn][kb + 4];
                mma_tf32(acc[0][nt], a0, b0, b1);
                mma_tf32(acc[1][nt], a1, b0, b1);
            }
        }
        __syncthreads();
    }

    #pragma unroll
    for (int mt = 0; mt < 2; mt++) {
        #pragma unroll
        for (int nt = 0; nt < 4; nt++) {
            int r0 = moff + wm * 32 + mt * 16 + (lane >> 2);
            int c  = n0 + wn * 32 + nt * 8 + 2 * (lane & 3);
            if (r0 < cnt) {
                float* dst = g_pair_out + (size_t)(off + r0) * HIDDEN + c;
                dst[0] = acc[mt][nt][0];
                dst[1] = acc[mt][nt][1];
            }
            int r1 = r0 + 8;
            if (r1 < cnt) {
                float* dst = g_pair_out + (size_t)(off + r1) * HIDDEN + c;
                dst[0] = acc[mt][nt][2];
                dst[1] = acc[mt][nt][3];
            }
        }
    }
}

// ---------------------------------------------------------------------------
// K6: weighted combine
// ---------------------------------------------------------------------------
__global__ void k_combine(float* __restrict__ out) {
    int n = blockIdx.x;
    int p0 = g_tok_pair[n * 2 + 0];
    int p1 = g_tok_pair[n * 2 + 1];
    float w0 = g_tok_w[n * 2 + 0];
    float w1 = g_tok_w[n * 2 + 1];
    for (int d = threadIdx.x * 4; d < HIDDEN; d += blockDim.x * 4) {
        float4 a = *(const float4*)&g_pair_out[(size_t)p0 * HIDDEN + d];
        float4 b = *(const float4*)&g_pair_out[(size_t)p1 * HIDDEN + d];
        float4 o;
        o.x = w0 * a.x + w1 * b.x;
        o.y = w0 * a.y + w1 * b.y;
        o.z = w0 * a.z + w1 * b.z;
        o.w = w0 * a.w + w1 * b.w;
        *(float4*)&out[(size_t)n * HIDDEN + d] = o;
    }
}

// ---------------------------------------------------------------------------
extern "C" void kernel_launch(void* const* d_in, const int* in_sizes, int n_in,
                              void* d_out, int out_size) {
    const float* hs   = (const float*)d_in[0];
    const int*   tid  = (const int*)d_in[1];
    const float* temb = (const float*)d_in[2];
    const float* trw  = (const float*)d_in[3];
    const float* gw   = (const float*)d_in[4];
    const float* gp   = (const float*)d_in[5];
    const float* up   = (const float*)d_in[6];
    const float* dp   = (const float*)d_in[7];
    float* out = (float*)d_out;

    k_task_route<<<1, 256>>>(temb, tid, trw);
    k_gate<<<NTOK / 8, 256>>>(hs, temb, tid, gw);
    k_prefix<<<1, 32>>>();
    k_place<<<NTOK / 256, 256>>>();
    dim3 g1(INTER / BN, NTOK / BM, NE);   // 44 x 64 x 8
    k_ffn1<<<g1, 256>>>(hs, gp, up);
    dim3 g2(HIDDEN / BN, NTOK / BM, NE);  // 16 x 64 x 8
    k_ffn2<<<g2, 256>>>(dp);
    k_combine<<<NTOK, 256>>>(out);
}

// round 4
// speedup vs baseline: 2.8965x; 1.2091x over previous
#include <cuda_runtime.h>
#include <math.h>
#include <stdint.h>

#define HIDDEN 1024
#define INTER  2816
#define NE     8
#define TOPK   2
#define NTASKEXP 4
#define NGEN   2
#define NTOK   8192
#define NPAIR  (NTOK*TOPK)

#define BM 128
#define BN 64
#define BK 16
#define PAD 4
#define LDK (BK + PAD)   // 20 floats -> 80B row stride (16B aligned)

// ---- scratch (static device memory; no runtime allocation) ----
__device__ int   g_active[NE];
__device__ int   g_counts[NE];
__device__ int   g_offsets[NE];
__device__ int   g_cursor[NE];
__device__ int   g_pair_token[NPAIR];
__device__ int   g_tok_e[NTOK * TOPK];
__device__ float g_tok_w[NTOK * TOPK];
__device__ int   g_tok_pair[NTOK * TOPK];
__device__ float g_act[(size_t)NPAIR * INTER];       // ~184.5 MB
__device__ float g_pair_out[(size_t)NPAIR * HIDDEN]; // ~67 MB

// ---------------------------------------------------------------------------
__device__ __forceinline__ uint32_t f2tf32(float x) {
    uint32_t r;
    asm("cvt.rna.tf32.f32 %0, %1;" : "=r"(r) : "f"(x));
    return r;
}

__device__ __forceinline__ void mma_tf32(float* c, const uint32_t* a,
                                         uint32_t b0, uint32_t b1) {
    asm volatile(
        "mma.sync.aligned.m16n8k8.row.col.f32.tf32.tf32.f32 "
        "{%0,%1,%2,%3}, {%4,%5,%6,%7}, {%8,%9}, {%0,%1,%2,%3};"
        : "+f"(c[0]), "+f"(c[1]), "+f"(c[2]), "+f"(c[3])
        : "r"(a[0]), "r"(a[1]), "r"(a[2]), "r"(a[3]), "r"(b0), "r"(b1));
}

__device__ __forceinline__ void cp16(void* smem_ptr, const void* gptr) {
    uint32_t s = (uint32_t)__cvta_generic_to_shared(smem_ptr);
    asm volatile("cp.async.cg.shared.global [%0], [%1], 16;\n" :: "r"(s), "l"(gptr));
}
__device__ __forceinline__ void cp_commit() {
    asm volatile("cp.async.commit_group;\n");
}
__device__ __forceinline__ void cp_wait0() {
    asm volatile("cp.async.wait_group 0;\n");
}

// ---------------------------------------------------------------------------
// K0: task-level routing (top-4 + generalists), reset counters
// ---------------------------------------------------------------------------
__global__ void k_task_route(const float* __restrict__ task_emb,
                             const int* __restrict__ task_id_p,
                             const float* __restrict__ trw) {
    __shared__ float sc[NE];
    int tid  = threadIdx.x;
    int e    = tid / 32;
    int lane = tid % 32;
    int task_id = task_id_p[0];
    const float* tv = task_emb + (size_t)task_id * HIDDEN;

    float acc = 0.f;
    if (e < NE) {
        for (int d = lane; d < HIDDEN; d += 32)
            acc += trw[(size_t)e * HIDDEN + d] * tv[d];
        #pragma unroll
        for (int o = 16; o > 0; o >>= 1)
            acc += __shfl_xor_sync(0xFFFFFFFFu, acc, o);
        if (lane == 0) sc[e] = acc;
    }
    __syncthreads();
    if (tid == 0) {
        float s[NE]; bool act[NE];
        for (int i = 0; i < NE; i++) { s[i] = sc[i]; act[i] = false; }
        for (int k = 0; k < NTASKEXP; k++) {
            int best = 0; float bv = -1e30f;
            for (int i = 0; i < NE; i++)
                if (!act[i] && s[i] > bv) { bv = s[i]; best = i; }
            act[best] = true;
        }
        for (int i = NE - NGEN; i < NE; i++) act[i] = true;
        for (int i = 0; i < NE; i++) {
            g_active[i] = act[i] ? 1 : 0;
            g_counts[i] = 0;
            g_cursor[i] = 0;
        }
    }
}

// ---------------------------------------------------------------------------
// K1: token gating (exact fp32)
// ---------------------------------------------------------------------------
__global__ void k_gate(const float* __restrict__ hs,
                       const float* __restrict__ task_emb,
                       const int* __restrict__ task_id_p,
                       const float* __restrict__ gw) {
    int warp = (blockIdx.x * blockDim.x + threadIdx.x) / 32;
    int lane = threadIdx.x % 32;
    if (warp >= NTOK) return;
    const float* tv = task_emb + (size_t)task_id_p[0] * HIDDEN;
    const float* h  = hs + (size_t)warp * HIDDEN;

    float acc[NE];
    #pragma unroll
    for (int e = 0; e < NE; e++) acc[e] = 0.f;

    for (int d = lane; d < HIDDEN; d += 32) {
        float x = h[d] + tv[d];
        #pragma unroll
        for (int e = 0; e < NE; e++)
            acc[e] += x * gw[(size_t)e * HIDDEN + d];
    }
    #pragma unroll
    for (int e = 0; e < NE; e++) {
        #pragma unroll
        for (int o = 16; o > 0; o >>= 1)
            acc[e] += __shfl_xor_sync(0xFFFFFFFFu, acc[e], o);
    }
    if (lane == 0) {
        float m = -1e30f;
        #pragma unroll
        for (int e = 0; e < NE; e++)
            if (g_active[e] && acc[e] > m) m = acc[e];
        float p[NE]; float Z = 0.f;
        #pragma unroll
        for (int e = 0; e < NE; e++) {
            p[e] = g_active[e] ? expf(acc[e] - m) : 0.f;
            Z += p[e];
        }
        float inv = 1.f / Z;
        int i0 = 0; float v0 = -1.f;
        #pragma unroll
        for (int e = 0; e < NE; e++) {
            float s = p[e] * inv;
            if (s > v0) { v0 = s; i0 = e; }
        }
        int i1 = -1; float v1 = -1.f;
        #pragma unroll
        for (int e = 0; e < NE; e++) {
            if (e == i0) continue;
            float s = p[e] * inv;
            if (s > v1) { v1 = s; i1 = e; }
        }
        float ws = v0 + v1 + 1e-6f;
        g_tok_e[warp * 2 + 0] = i0;
        g_tok_e[warp * 2 + 1] = i1;
        g_tok_w[warp * 2 + 0] = v0 / ws;
        g_tok_w[warp * 2 + 1] = v1 / ws;
        atomicAdd(&g_counts[i0], 1);
        atomicAdd(&g_counts[i1], 1);
    }
}

__global__ void k_prefix() {
    if (threadIdx.x == 0) {
        int o = 0;
        for (int e = 0; e < NE; e++) { g_offsets[e] = o; o += g_counts[e]; }
    }
}

__global__ void k_place() {
    int n = blockIdx.x * blockDim.x + threadIdx.x;
    if (n >= NTOK) return;
    #pragma unroll
    for (int k = 0; k < TOPK; k++) {
        int e = g_tok_e[n * 2 + k];
        int slot = atomicAdd(&g_cursor[e], 1);
        int idx = g_offsets[e] + slot;
        g_pair_token[idx] = n;
        g_tok_pair[n * 2 + k] = idx;
    }
}

// ---------------------------------------------------------------------------
// K4: GEMM1 (gate & up fused, tf32) + SwiGLU.  cp.async double-buffered.
// ---------------------------------------------------------------------------
__global__ void __launch_bounds__(256)
k_ffn1(const float* __restrict__ hs,
       const float* __restrict__ gp,
       const float* __restrict__ up) {
    int e   = blockIdx.z;
    int cnt = g_counts[e];
    int moff = blockIdx.y * BM;
    if (moff >= cnt) return;
    int off = g_offsets[e];
    int n0  = blockIdx.x * BN;

    __shared__ float As[2][BM][LDK];
    __shared__ float Bg[2][BN][LDK];
    __shared__ float Bu[2][BN][LDK];

    int tid  = threadIdx.x;
    int warp = tid >> 5;
    int lane = tid & 31;
    int wm = warp >> 1;
    int wn = warp & 1;

    // copy roles: A rows tid/4 and tid/4+64, col4 = (tid%4)*4; B rows tid/4
    int crow = tid >> 2;
    int ccol = (tid & 3) * 4;

    const float* gpe = gp + (size_t)e * INTER * HIDDEN;
    const float* upe = up + (size_t)e * INTER * HIDDEN;

    int r0g = moff + crow;      if (r0g > cnt - 1) r0g = cnt - 1;
    int r1g = moff + crow + 64; if (r1g > cnt - 1) r1g = cnt - 1;
    const float* aG0 = hs + (size_t)g_pair_token[off + r0g] * HIDDEN + ccol;
    const float* aG1 = hs + (size_t)g_pair_token[off + r1g] * HIDDEN + ccol;
    const float* bgG = gpe + (size_t)(n0 + crow) * HIDDEN + ccol;
    const float* buG = upe + (size_t)(n0 + crow) * HIDDEN + ccol;

    float accg[2][4][4], accu[2][4][4];
    #pragma unroll
    for (int mt = 0; mt < 2; mt++)
        #pragma unroll
        for (int nt = 0; nt < 4; nt++)
            #pragma unroll
            for (int q = 0; q < 4; q++) { accg[mt][nt][q] = 0.f; accu[mt][nt][q] = 0.f; }

    // prologue: stage 0
    cp16(&As[0][crow][ccol],      aG0);
    cp16(&As[0][crow + 64][ccol], aG1);
    cp16(&Bg[0][crow][ccol],      bgG);
    cp16(&Bu[0][crow][ccol],      buG);
    cp_commit();

    const int T = HIDDEN / BK;   // 64
    int ar = wm * 32 + (lane >> 2);

    for (int it = 0; it < T; it++) {
        cp_wait0();
        __syncthreads();
        if (it + 1 < T) {
            int s = (it + 1) & 1;
            int k0 = (it + 1) * BK;
            cp16(&As[s][crow][ccol],      aG0 + k0);
            cp16(&As[s][crow + 64][ccol], aG1 + k0);
            cp16(&Bg[s][crow][ccol],      bgG + k0);
            cp16(&Bu[s][crow][ccol],      buG + k0);
            cp_commit();
        }
        int s = it & 1;
        #pragma unroll
        for (int ks = 0; ks < 2; ks++) {
            int kb = ks * 8 + (lane & 3);
            uint32_t a0[4], a1[4];
            a0[0] = f2tf32(As[s][ar][kb]);      a0[1] = f2tf32(As[s][ar + 8][kb]);
            a0[2] = f2tf32(As[s][ar][kb + 4]);  a0[3] = f2tf32(As[s][ar + 8][kb + 4]);
            a1[0] = f2tf32(As[s][ar + 16][kb]);     a1[1] = f2tf32(As[s][ar + 24][kb]);
            a1[2] = f2tf32(As[s][ar + 16][kb + 4]); a1[3] = f2tf32(As[s][ar + 24][kb + 4]);
            #pragma unroll
            for (int nt = 0; nt < 4; nt++) {
                int cn = wn * 32 + nt * 8 + (lane >> 2);
                uint32_t bg0 = f2tf32(Bg[s][cn][kb]), bg1 = f2tf32(Bg[s][cn][kb + 4]);
                uint32_t bu0 = f2tf32(Bu[s][cn][kb]), bu1 = f2tf32(Bu[s][cn][kb + 4]);
                mma_tf32(accg[0][nt], a0, bg0, bg1);
                mma_tf32(accg[1][nt], a1, bg0, bg1);
                mma_tf32(accu[0][nt], a0, bu0, bu1);
                mma_tf32(accu[1][nt], a1, bu0, bu1);
            }
        }
    }

    // epilogue: SwiGLU -> g_act
    #pragma unroll
    for (int mt = 0; mt < 2; mt++) {
        #pragma unroll
        for (int nt = 0; nt < 4; nt++) {
            int r0 = moff + wm * 32 + mt * 16 + (lane >> 2);
            int c  = n0 + wn * 32 + nt * 8 + 2 * (lane & 3);
            if (r0 < cnt) {
                float* dst = g_act + (size_t)(off + r0) * INTER + c;
                float g0 = accg[mt][nt][0], u0 = accu[mt][nt][0];
                float g1 = accg[mt][nt][1], u1 = accu[mt][nt][1];
                dst[0] = (g0 / (1.f + __expf(-g0))) * u0;
                dst[1] = (g1 / (1.f + __expf(-g1))) * u1;
            }
            int r1 = r0 + 8;
            if (r1 < cnt) {
                float* dst = g_act + (size_t)(off + r1) * INTER + c;
                float g0 = accg[mt][nt][2], u0 = accu[mt][nt][2];
                float g1 = accg[mt][nt][3], u1 = accu[mt][nt][3];
                dst[0] = (g0 / (1.f + __expf(-g0))) * u0;
                dst[1] = (g1 / (1.f + __expf(-g1))) * u1;
            }
        }
    }
}

// ---------------------------------------------------------------------------
// K5: GEMM2 (down, tf32). cp.async double-buffered.
// ---------------------------------------------------------------------------
__global__ void __launch_bounds__(256)
k_ffn2(const float* __restrict__ dp) {
    int e   = blockIdx.z;
    int cnt = g_counts[e];
    int moff = blockIdx.y * BM;
    if (moff >= cnt) return;
    int off = g_offsets[e];
    int n0  = blockIdx.x * BN;

    __shared__ float As[2][BM][LDK];
    __shared__ float Bs[2][BN][LDK];

    int tid  = threadIdx.x;
    int warp = tid >> 5;
    int lane = tid & 31;
    int wm = warp >> 1;
    int wn = warp & 1;

    int crow = tid >> 2;
    int ccol = (tid & 3) * 4;

    const float* dpe = dp + (size_t)e * HIDDEN * INTER;

    int r0g = moff + crow;      if (r0g > cnt - 1) r0g = cnt - 1;
    int r1g = moff + crow + 64; if (r1g > cnt - 1) r1g = cnt - 1;
    const float* aG0 = g_act + (size_t)(off + r0g) * INTER + ccol;
    const float* aG1 = g_act + (size_t)(off + r1g) * INTER + ccol;
    const float* bG  = dpe + (size_t)(n0 + crow) * INTER + ccol;

    float acc[2][4][4];
    #pragma unroll
    for (int mt = 0; mt < 2; mt++)
        #pragma unroll
        for (int nt = 0; nt < 4; nt++)
            #pragma unroll
            for (int q = 0; q < 4; q++) acc[mt][nt][q] = 0.f;

    cp16(&As[0][crow][ccol],      aG0);
    cp16(&As[0][crow + 64][ccol], aG1);
    cp16(&Bs[0][crow][ccol],      bG);
    cp_commit();

    const int T = INTER / BK;   // 176
    int ar = wm * 32 + (lane >> 2);

    for (int it = 0; it < T; it++) {
        cp_wait0();
        __syncthreads();
        if (it + 1 < T) {
            int s = (it + 1) & 1;
            int k0 = (it + 1) * BK;
            cp16(&As[s][crow][ccol],      aG0 + k0);
            cp16(&As[s][crow + 64][ccol], aG1 + k0);
            cp16(&Bs[s][crow][ccol],      bG + k0);
            cp_commit();
        }
        int s = it & 1;
        #pragma unroll
        for (int ks = 0; ks < 2; ks++) {
            int kb = ks * 8 + (lane & 3);
            uint32_t a0[4], a1[4];
            a0[0] = f2tf32(As[s][ar][kb]);      a0[1] = f2tf32(As[s][ar + 8][kb]);
            a0[2] = f2tf32(As[s][ar][kb + 4]);  a0[3] = f2tf32(As[s][ar + 8][kb + 4]);
            a1[0] = f2tf32(As[s][ar + 16][kb]);     a1[1] = f2tf32(As[s][ar + 24][kb]);
            a1[2] = f2tf32(As[s][ar + 16][kb + 4]); a1[3] = f2tf32(As[s][ar + 24][kb + 4]);
            #pragma unroll
            for (int nt = 0; nt < 4; nt++) {
                int cn = wn * 32 + nt * 8 + (lane >> 2);
                uint32_t b0 = f2tf32(Bs[s][cn][kb]), b1 = f2tf32(Bs[s][cn][kb + 4]);
                mma_tf32(acc[0][nt], a0, b0, b1);
                mma_tf32(acc[1][nt], a1, b0, b1);
            }
        }
    }

    #pragma unroll
    for (int mt = 0; mt < 2; mt++) {
        #pragma unroll
        for (int nt = 0; nt < 4; nt++) {
            int r0 = moff + wm * 32 + mt * 16 + (lane >> 2);
            int c  = n0 + wn * 32 + nt * 8 + 2 * (lane & 3);
            if (r0 < cnt) {
                float* dst = g_pair_out + (size_t)(off + r0) * HIDDEN + c;
                dst[0] = acc[mt][nt][0];
                dst[1] = acc[mt][nt][1];
            }
            int r1 = r0 + 8;
            if (r1 < cnt) {
                float* dst = g_pair_out + (size_t)(off + r1) * HIDDEN + c;
                dst[0] = acc[mt][nt][2];
                dst[1] = acc[mt][nt][3];
            }
        }
    }
}

// ---------------------------------------------------------------------------
// K6: weighted combine
// ---------------------------------------------------------------------------
__global__ void k_combine(float* __restrict__ out) {
    int n = blockIdx.x;
    int p0 = g_tok_pair[n * 2 + 0];
    int p1 = g_tok_pair[n * 2 + 1];
    float w0 = g_tok_w[n * 2 + 0];
    float w1 = g_tok_w[n * 2 + 1];
    for (int d = threadIdx.x * 4; d < HIDDEN; d += blockDim.x * 4) {
        float4 a = *(const float4*)&g_pair_out[(size_t)p0 * HIDDEN + d];
        float4 b = *(const float4*)&g_pair_out[(size_t)p1 * HIDDEN + d];
        float4 o;
        o.x = w0 * a.x + w1 * b.x;
        o.y = w0 * a.y + w1 * b.y;
        o.z = w0 * a.z + w1 * b.z;
        o.w = w0 * a.w + w1 * b.w;
        *(float4*)&out[(size_t)n * HIDDEN + d] = o;
    }
}

// ---------------------------------------------------------------------------
extern "C" void kernel_launch(void* const* d_in, const int* in_sizes, int n_in,
                              void* d_out, int out_size) {
    const float* hs   = (const float*)d_in[0];
    const int*   tid  = (const int*)d_in[1];
    const float* temb = (const float*)d_in[2];
    const float* trw  = (const float*)d_in[3];
    const float* gw   = (const float*)d_in[4];
    const float* gp   = (const float*)d_in[5];
    const float* up   = (const float*)d_in[6];
    const float* dp   = (const float*)d_in[7];
    float* out = (float*)d_out;

    k_task_route<<<1, 256>>>(temb, tid, trw);
    k_gate<<<NTOK / 8, 256>>>(hs, temb, tid, gw);
    k_prefix<<<1, 32>>>();
    k_place<<<NTOK / 256, 256>>>();
    dim3 g1(INTER / BN, NTOK / BM, NE);   // 44 x 64 x 8
    k_ffn1<<<g1, 256>>>(hs, gp, up);
    dim3 g2(HIDDEN / BN, NTOK / BM, NE);  // 16 x 64 x 8
    k_ffn2<<<g2, 256>>>(dp);
    k_combine<<<NTOK, 256>>>(out);
}

// round 6
// speedup vs baseline: 4.9493x; 1.7087x over previous
#include <cuda_runtime.h>
#include <cuda_fp16.h>
#include <math.h>
#include <stdint.h>

#define HIDDEN 1024
#define INTER  2816
#define NE     8
#define TOPK   2
#define NTASKEXP 4
#define NGEN   2
#define NTOK   8192
#define NPAIR  (NTOK*TOPK)
#define WELEM  (NE*INTER*HIDDEN)

#define BM 128
#define BN 64
#define BKH 32          // K halves per stage
#define LDH 40          // padded row stride in halves (80B)
#define STG1B 20480     // A(128*80) + Bg(64*80) + Bu(64*80)
#define STG2B 15360     // A(128*80) + B(64*80)

// ---- scratch (static device memory; no runtime allocation) ----
__device__ int    g_active[NE];
__device__ int    g_counts[NE];
__device__ int    g_offsets[NE];
__device__ int    g_cursor[NE];
__device__ int    g_pair_token[NPAIR];
__device__ int    g_tok_e[NTOK * TOPK];
__device__ float  g_tok_w[NTOK * TOPK];
__device__ int    g_tok_pair[NTOK * TOPK];
__device__ __half g_act[(size_t)NPAIR * INTER];        // fp16 swiglu output (~92MB)
__device__ float  g_pair_out[(size_t)NPAIR * HIDDEN];
__device__ __half g_hs_h[(size_t)NTOK * HIDDEN];       // fp16 hidden states
__device__ __half g_gp_h[(size_t)WELEM];               // fp16 weights (~46MB each)
__device__ __half g_up_h[(size_t)WELEM];
__device__ __half g_dp_h[(size_t)WELEM];

// ---------------------------------------------------------------------------
// PTX helpers (legacy ISA only: mma.sync / ldmatrix / cp.async)
// ---------------------------------------------------------------------------
__device__ __forceinline__ void cp16(void* smem_ptr, const void* gptr) {
    uint32_t s = (uint32_t)__cvta_generic_to_shared(smem_ptr);
    asm volatile("cp.async.cg.shared.global [%0], [%1], 16;\n" :: "r"(s), "l"(gptr));
}
__device__ __forceinline__ void cp_commit() { asm volatile("cp.async.commit_group;\n"); }
__device__ __forceinline__ void cp_wait0()  { asm volatile("cp.async.wait_group 0;\n" ::: "memory"); }

__device__ __forceinline__ uint32_t smem_u32(const void* p) {
    return (uint32_t)__cvta_generic_to_shared(p);
}
__device__ __forceinline__ void ldsm4(uint32_t* r, uint32_t addr) {
    asm volatile("ldmatrix.sync.aligned.m8n8.x4.shared.b16 {%0,%1,%2,%3}, [%4];"
                 : "=r"(r[0]), "=r"(r[1]), "=r"(r[2]), "=r"(r[3]) : "r"(addr));
}
__device__ __forceinline__ void mma_f16(float* c, const uint32_t* a, const uint32_t* b) {
    asm volatile(
        "mma.sync.aligned.m16n8k16.row.col.f32.f16.f16.f32 "
        "{%0,%1,%2,%3}, {%4,%5,%6,%7}, {%8,%9}, {%0,%1,%2,%3};"
        : "+f"(c[0]), "+f"(c[1]), "+f"(c[2]), "+f"(c[3])
        : "r"(a[0]), "r"(a[1]), "r"(a[2]), "r"(a[3]), "r"(b[0]), "r"(b[1]));
}

// ---------------------------------------------------------------------------
// K0: task routing + counter reset
// ---------------------------------------------------------------------------
__global__ void k_task_route(const float* __restrict__ task_emb,
                             const int* __restrict__ task_id_p,
                             const float* __restrict__ trw) {
    __shared__ float sc[NE];
    int tid  = threadIdx.x;
    int e    = tid / 32;
    int lane = tid % 32;
    const float* tv = task_emb + (size_t)task_id_p[0] * HIDDEN;
    float acc = 0.f;
    if (e < NE) {
        for (int d = lane; d < HIDDEN; d += 32)
            acc += trw[(size_t)e * HIDDEN + d] * tv[d];
        #pragma unroll
        for (int o = 16; o > 0; o >>= 1)
            acc += __shfl_xor_sync(0xFFFFFFFFu, acc, o);
        if (lane == 0) sc[e] = acc;
    }
    __syncthreads();
    if (tid == 0) {
        float s[NE]; bool act[NE];
        for (int i = 0; i < NE; i++) { s[i] = sc[i]; act[i] = false; }
        for (int k = 0; k < NTASKEXP; k++) {
            int best = 0; float bv = -1e30f;
            for (int i = 0; i < NE; i++)
                if (!act[i] && s[i] > bv) { bv = s[i]; best = i; }
            act[best] = true;
        }
        for (int i = NE - NGEN; i < NE; i++) act[i] = true;
        for (int i = 0; i < NE; i++) {
            g_active[i] = act[i] ? 1 : 0;
            g_counts[i] = 0;
            g_cursor[i] = 0;
        }
    }
}

// ---------------------------------------------------------------------------
// K1: token gating (exact fp32) + writes fp16 copy of hs
// ---------------------------------------------------------------------------
__global__ void k_gate(const float* __restrict__ hs,
                       const float* __restrict__ task_emb,
                       const int* __restrict__ task_id_p,
                       const float* __restrict__ gw) {
    int warp = (blockIdx.x * blockDim.x + threadIdx.x) / 32;
    int lane = threadIdx.x % 32;
    if (warp >= NTOK) return;
    const float* tv = task_emb + (size_t)task_id_p[0] * HIDDEN;
    const float* h  = hs + (size_t)warp * HIDDEN;
    __half* ht = g_hs_h + (size_t)warp * HIDDEN;

    float acc[NE];
    #pragma unroll
    for (int e = 0; e < NE; e++) acc[e] = 0.f;

    for (int d = lane; d < HIDDEN; d += 32) {
        float hv = h[d];
        ht[d] = __float2half_rn(hv);
        float x = hv + tv[d];
        #pragma unroll
        for (int e = 0; e < NE; e++)
            acc[e] += x * gw[(size_t)e * HIDDEN + d];
    }
    #pragma unroll
    for (int e = 0; e < NE; e++) {
        #pragma unroll
        for (int o = 16; o > 0; o >>= 1)
            acc[e] += __shfl_xor_sync(0xFFFFFFFFu, acc[e], o);
    }
    if (lane == 0) {
        float m = -1e30f;
        #pragma unroll
        for (int e = 0; e < NE; e++)
            if (g_active[e] && acc[e] > m) m = acc[e];
        float p[NE]; float Z = 0.f;
        #pragma unroll
        for (int e = 0; e < NE; e++) {
            p[e] = g_active[e] ? expf(acc[e] - m) : 0.f;
            Z += p[e];
        }
        float inv = 1.f / Z;
        int i0 = 0; float v0 = -1.f;
        #pragma unroll
        for (int e = 0; e < NE; e++) {
            float s = p[e] * inv;
            if (s > v0) { v0 = s; i0 = e; }
        }
        int i1 = -1; float v1 = -1.f;
        #pragma unroll
        for (int e = 0; e < NE; e++) {
            if (e == i0) continue;
            float s = p[e] * inv;
            if (s > v1) { v1 = s; i1 = e; }
        }
        float ws = v0 + v1 + 1e-6f;
        g_tok_e[warp * 2 + 0] = i0;
        g_tok_e[warp * 2 + 1] = i1;
        g_tok_w[warp * 2 + 0] = v0 / ws;
        g_tok_w[warp * 2 + 1] = v1 / ws;
        atomicAdd(&g_counts[i0], 1);
        atomicAdd(&g_counts[i1], 1);
    }
}

__global__ void k_prefix() {
    if (threadIdx.x == 0) {
        int o = 0;
        for (int e = 0; e < NE; e++) { g_offsets[e] = o; o += g_counts[e]; }
    }
}

__global__ void k_place() {
    int n = blockIdx.x * blockDim.x + threadIdx.x;
    if (n >= NTOK) return;
    #pragma unroll
    for (int k = 0; k < TOPK; k++) {
        int e = g_tok_e[n * 2 + k];
        int slot = atomicAdd(&g_cursor[e], 1);
        int idx = g_offsets[e] + slot;
        g_pair_token[idx] = n;
        g_tok_pair[n * 2 + k] = idx;
    }
}

// ---------------------------------------------------------------------------
// weight fp32 -> fp16 conversion (active experts only; inactive never read)
// ---------------------------------------------------------------------------
__global__ void k_cvt_h(const float4* __restrict__ in, uint2* __restrict__ out) {
    int e = blockIdx.z;
    if (!g_active[e]) return;
    const int n4 = INTER * HIDDEN / 4;
    const float4* src = in + (size_t)e * n4;
    uint2* dst = out + (size_t)e * n4;
    for (int i = blockIdx.x * blockDim.x + threadIdx.x; i < n4; i += gridDim.x * blockDim.x) {
        float4 v = src[i];
        __half2 lo = __floats2half2_rn(v.x, v.y);
        __half2 hi = __floats2half2_rn(v.z, v.w);
        uint2 o;
        o.x = *(const uint32_t*)&lo;
        o.y = *(const uint32_t*)&hi;
        dst[i] = o;
    }
}

// ---------------------------------------------------------------------------
// K4: GEMM1 (gate & up fused, fp16 mma.sync) + SwiGLU.  cp.async double-buffer.
//     BM=128 BN=64 BK=32; 8 warps; warp tile 32Mx32N on both gate & up.
// ---------------------------------------------------------------------------
__global__ void __launch_bounds__(256)
k_ffn1() {
    __shared__ __align__(16) char sm[2 * STG1B];
    int e    = blockIdx.z;
    int cnt  = g_counts[e];
    int moff = blockIdx.y * BM;
    if (moff >= cnt) return;
    int off = g_offsets[e];
    int n0  = blockIdx.x * BN;
    int tid = threadIdx.x;

    // copy roles: 4 x 16B chunks/thread per stage (rows: 0-127 A, 128-191 Bg, 192-255 Bu)
    const char* src[4];
    uint32_t dsto[4];
    #pragma unroll
    for (int t = 0; t < 4; t++) {
        int q = tid + t * 256;
        int row = q >> 2, c16 = q & 3;
        if (row < 128) {
            dsto[t] = (uint32_t)row * 80u + c16 * 16u;
            int r = moff + row; if (r > cnt - 1) r = cnt - 1;
            src[t] = (const char*)(g_hs_h + (size_t)g_pair_token[off + r] * HIDDEN) + c16 * 16;
        } else if (row < 192) {
            int rr = row - 128;
            dsto[t] = 10240u + (uint32_t)rr * 80u + c16 * 16u;
            src[t] = (const char*)(g_gp_h + (size_t)e * INTER * HIDDEN + (size_t)(n0 + rr) * HIDDEN) + c16 * 16;
        } else {
            int rr = row - 192;
            dsto[t] = 15360u + (uint32_t)rr * 80u + c16 * 16u;
            src[t] = (const char*)(g_up_h + (size_t)e * INTER * HIDDEN + (size_t)(n0 + rr) * HIDDEN) + c16 * 16;
        }
    }

    // prologue: stage 0
    #pragma unroll
    for (int t = 0; t < 4; t++) cp16(sm + dsto[t], src[t]);
    cp_commit();

    uint32_t sb = smem_u32(sm);
    int w = tid >> 5, lane = tid & 31;
    int wm = w >> 1, wn = w & 1;
    // ldmatrix lane addressing
    uint32_t aoff = (((uint32_t)(wm * 32 + (lane & 15))) * 40u + ((lane >> 4) * 8u)) * 2u;
    uint32_t brow = (uint32_t)(wn * 32 + (lane & 7) + ((lane >> 4) << 3));
    uint32_t boff = (brow * 40u + (((lane >> 3) & 1) * 8u)) * 2u;

    float accg[2][4][4], accu[2][4][4];
    #pragma unroll
    for (int mt = 0; mt < 2; mt++)
        #pragma unroll
        for (int nt = 0; nt < 4; nt++)
            #pragma unroll
            for (int q = 0; q < 4; q++) { accg[mt][nt][q] = 0.f; accu[mt][nt][q] = 0.f; }

    const int T = HIDDEN / BKH;  // 32
    for (int j = 0; j < T; j++) {
        cp_wait0();
        __syncthreads();
        if (j + 1 < T) {
            char* dstb = sm + ((j + 1) & 1) * STG1B;
            int adv = (j + 1) * 64;
            #pragma unroll
            for (int t = 0; t < 4; t++) cp16(dstb + dsto[t], src[t] + adv);
            cp_commit();
        }
        uint32_t base = sb + (uint32_t)(j & 1) * STG1B;
        #pragma unroll
        for (int kk = 0; kk < 2; kk++) {
            uint32_t a[2][4], bg[2][4], bu[2][4];
            ldsm4(a[0], base + aoff + kk * 32);
            ldsm4(a[1], base + aoff + 16 * 80 + kk * 32);
            ldsm4(bg[0], base + 10240 + boff + kk * 32);
            ldsm4(bg[1], base + 10240 + boff + 16 * 80 + kk * 32);
            ldsm4(bu[0], base + 15360 + boff + kk * 32);
            ldsm4(bu[1], base + 15360 + boff + 16 * 80 + kk * 32);
            #pragma unroll
            for (int mt = 0; mt < 2; mt++)
                #pragma unroll
                for (int ng = 0; ng < 2; ng++)
                    #pragma unroll
                    for (int hh = 0; hh < 2; hh++) {
                        mma_f16(accg[mt][ng * 2 + hh], a[mt], &bg[ng][hh * 2]);
                        mma_f16(accu[mt][ng * 2 + hh], a[mt], &bu[ng][hh * 2]);
                    }
        }
    }

    // epilogue: SwiGLU -> g_act (fp16)
    #pragma unroll
    for (int mt = 0; mt < 2; mt++) {
        #pragma unroll
        for (int nt = 0; nt < 4; nt++) {
            int r0 = moff + wm * 32 + mt * 16 + (lane >> 2);
            int c  = n0 + wn * 32 + nt * 8 + 2 * (lane & 3);
            if (r0 < cnt) {
                __half* dst = g_act + (size_t)(off + r0) * INTER + c;
                float g0 = accg[mt][nt][0], u0 = accu[mt][nt][0];
                float g1 = accg[mt][nt][1], u1 = accu[mt][nt][1];
                *(__half2*)dst = __floats2half2_rn((g0 / (1.f + __expf(-g0))) * u0,
                                                   (g1 / (1.f + __expf(-g1))) * u1);
            }
            int r1 = r0 + 8;
            if (r1 < cnt) {
                __half* dst = g_act + (size_t)(off + r1) * INTER + c;
                float g0 = accg[mt][nt][2], u0 = accu[mt][nt][2];
                float g1 = accg[mt][nt][3], u1 = accu[mt][nt][3];
                *(__half2*)dst = __floats2half2_rn((g0 / (1.f + __expf(-g0))) * u0,
                                                   (g1 / (1.f + __expf(-g1))) * u1);
            }
        }
    }
}

// ---------------------------------------------------------------------------
// K5: GEMM2 (down, fp16 mma.sync). M=cnt, N=HIDDEN, K=INTER
// ---------------------------------------------------------------------------
__global__ void __launch_bounds__(256)
k_ffn2() {
    __shared__ __align__(16) char sm[2 * STG2B];
    int e    = blockIdx.z;
    int cnt  = g_counts[e];
    int moff = blockIdx.y * BM;
    if (moff >= cnt) return;
    int off = g_offsets[e];
    int n0  = blockIdx.x * BN;
    int tid = threadIdx.x;

    const char* src[3];
    uint32_t dsto[3];
    #pragma unroll
    for (int t = 0; t < 3; t++) {
        int q = tid + t * 256;
        int row = q >> 2, c16 = q & 3;
        if (row < 128) {
            dsto[t] = (uint32_t)row * 80u + c16 * 16u;
            int r = moff + row; if (r > cnt - 1) r = cnt - 1;
            src[t] = (const char*)(g_act + (size_t)(off + r) * INTER) + c16 * 16;
        } else {
            int rr = row - 128;
            dsto[t] = 10240u + (uint32_t)rr * 80u + c16 * 16u;
            src[t] = (const char*)(g_dp_h + (size_t)e * HIDDEN * INTER + (size_t)(n0 + rr) * INTER) + c16 * 16;
        }
    }

    #pragma unroll
    for (int t = 0; t < 3; t++) cp16(sm + dsto[t], src[t]);
    cp_commit();

    uint32_t sb = smem_u32(sm);
    int w = tid >> 5, lane = tid & 31;
    int wm = w >> 1, wn = w & 1;
    uint32_t aoff = (((uint32_t)(wm * 32 + (lane & 15))) * 40u + ((lane >> 4) * 8u)) * 2u;
    uint32_t brow = (uint32_t)(wn * 32 + (lane & 7) + ((lane >> 4) << 3));
    uint32_t boff = (brow * 40u + (((lane >> 3) & 1) * 8u)) * 2u;

    float acc[2][4][4];
    #pragma unroll
    for (int mt = 0; mt < 2; mt++)
        #pragma unroll
        for (int nt = 0; nt < 4; nt++)
            #pragma unroll
            for (int q = 0; q < 4; q++) acc[mt][nt][q] = 0.f;

    const int T = INTER / BKH;  // 88
    for (int j = 0; j < T; j++) {
        cp_wait0();
        __syncthreads();
        if (j + 1 < T) {
            char* dstb = sm + ((j + 1) & 1) * STG2B;
            int adv = (j + 1) * 64;
            #pragma unroll
            for (int t = 0; t < 3; t++) cp16(dstb + dsto[t], src[t] + adv);
            cp_commit();
        }
        uint32_t base = sb + (uint32_t)(j & 1) * STG2B;
        #pragma unroll
        for (int kk = 0; kk < 2; kk++) {
            uint32_t a[2][4], bb[2][4];
            ldsm4(a[0], base + aoff + kk * 32);
            ldsm4(a[1], base + aoff + 16 * 80 + kk * 32);
            ldsm4(bb[0], base + 10240 + boff + kk * 32);
            ldsm4(bb[1], base + 10240 + boff + 16 * 80 + kk * 32);
            #pragma unroll
            for (int mt = 0; mt < 2; mt++)
                #pragma unroll
                for (int ng = 0; ng < 2; ng++)
                    #pragma unroll
                    for (int hh = 0; hh < 2; hh++)
                        mma_f16(acc[mt][ng * 2 + hh], a[mt], &bb[ng][hh * 2]);
        }
    }

    #pragma unroll
    for (int mt = 0; mt < 2; mt++) {
        #pragma unroll
        for (int nt = 0; nt < 4; nt++) {
            int r0 = moff + wm * 32 + mt * 16 + (lane >> 2);
            int c  = n0 + wn * 32 + nt * 8 + 2 * (lane & 3);
            if (r0 < cnt) {
                float2* dst = (float2*)(g_pair_out + (size_t)(off + r0) * HIDDEN + c);
                *dst = make_float2(acc[mt][nt][0], acc[mt][nt][1]);
            }
            int r1 = r0 + 8;
            if (r1 < cnt) {
                float2* dst = (float2*)(g_pair_out + (size_t)(off + r1) * HIDDEN + c);
                *dst = make_float2(acc[mt][nt][2], acc[mt][nt][3]);
            }
        }
    }
}

// ---------------------------------------------------------------------------
// K6: weighted combine
// ---------------------------------------------------------------------------
__global__ void k_combine(float* __restrict__ out) {
    int n = blockIdx.x;
    int p0 = g_tok_pair[n * 2 + 0];
    int p1 = g_tok_pair[n * 2 + 1];
    float w0 = g_tok_w[n * 2 + 0];
    float w1 = g_tok_w[n * 2 + 1];
    for (int d = threadIdx.x * 4; d < HIDDEN; d += blockDim.x * 4) {
        float4 a = *(const float4*)&g_pair_out[(size_t)p0 * HIDDEN + d];
        float4 b = *(const float4*)&g_pair_out[(size_t)p1 * HIDDEN + d];
        float4 o;
        o.x = w0 * a.x + w1 * b.x;
        o.y = w0 * a.y + w1 * b.y;
        o.z = w0 * a.z + w1 * b.z;
        o.w = w0 * a.w + w1 * b.w;
        *(float4*)&out[(size_t)n * HIDDEN + d] = o;
    }
}

// ---------------------------------------------------------------------------
extern "C" void kernel_launch(void* const* d_in, const int* in_sizes, int n_in,
                              void* d_out, int out_size) {
    const float* hs   = (const float*)d_in[0];
    const int*   tid  = (const int*)d_in[1];
    const float* temb = (const float*)d_in[2];
    const float* trw  = (const float*)d_in[3];
    const float* gw   = (const float*)d_in[4];
    const float* gp   = (const float*)d_in[5];
    const float* up   = (const float*)d_in[6];
    const float* dp   = (const float*)d_in[7];
    float* out = (float*)d_out;

    __half* gph; __half* uph; __half* dph;
    cudaGetSymbolAddress((void**)&gph, g_gp_h);
    cudaGetSymbolAddress((void**)&uph, g_up_h);
    cudaGetSymbolAddress((void**)&dph, g_dp_h);

    k_task_route<<<1, 256>>>(temb, tid, trw);

    dim3 gc(440, 1, NE);
    k_cvt_h<<<gc, 256>>>((const float4*)gp, (uint2*)gph);
    k_cvt_h<<<gc, 256>>>((const float4*)up, (uint2*)uph);
    k_cvt_h<<<gc, 256>>>((const float4*)dp, (uint2*)dph);

    k_gate<<<NTOK / 8, 256>>>(hs, temb, tid, gw);
    k_prefix<<<1, 32>>>();
    k_place<<<NTOK / 256, 256>>>();

    dim3 g1(INTER / BN, NTOK / BM, NE);   // 44 x 64 x 8
    k_ffn1<<<g1, 256>>>();
    dim3 g2(HIDDEN / BN, NTOK / BM, NE);  // 16 x 64 x 8
    k_ffn2<<<g2, 256>>>();
    k_combine<<<NTOK, 256>>>(out);
}

// round 7
// speedup vs baseline: 5.8037x; 1.1726x over previous
#include <cuda_runtime.h>
#include <cuda_fp16.h>
#include <math.h>
#include <stdint.h>

#define HIDDEN 1024
#define INTER  2816
#define NE     8
#define TOPK   2
#define NTASKEXP 4
#define NGEN   2
#define NTOK   8192
#define NPAIR  (NTOK*TOPK)
#define WELEM  (NE*INTER*HIDDEN)

#define BM 128
#define BN 64
#define BKH 64            // K halves per stage (128B row)
#define ROWB 144          // row stride bytes (128 data + 16 pad)
#define STG1 36864        // (128+64+64) rows * 144B
#define STG2 27648        // (128+64) rows * 144B
#define SMEM1 (3*STG1)    // 110592
#define SMEM2 (3*STG2)    // 82944

// ---- scratch (static device memory; no runtime allocation) ----
__device__ int    g_active[NE];
__device__ int    g_counts[NE];
__device__ int    g_offsets[NE];
__device__ int    g_cursor[NE];
__device__ int    g_pair_token[NPAIR];
__device__ int    g_tok_e[NTOK * TOPK];
__device__ float  g_tok_w[NTOK * TOPK];
__device__ int    g_tok_pair[NTOK * TOPK];
__device__ __half g_act[(size_t)NPAIR * INTER];
__device__ float  g_pair_out[(size_t)NPAIR * HIDDEN];
__device__ __half g_hs_h[(size_t)NTOK * HIDDEN];
__device__ __half g_gp_h[(size_t)WELEM];
__device__ __half g_up_h[(size_t)WELEM];
__device__ __half g_dp_h[(size_t)WELEM];

// ---------------------------------------------------------------------------
__device__ __forceinline__ void cp16(void* smem_ptr, const void* gptr) {
    uint32_t s = (uint32_t)__cvta_generic_to_shared(smem_ptr);
    asm volatile("cp.async.cg.shared.global [%0], [%1], 16;\n" :: "r"(s), "l"(gptr));
}
__device__ __forceinline__ void cp_commit() { asm volatile("cp.async.commit_group;\n"); }
__device__ __forceinline__ void cp_wait0()  { asm volatile("cp.async.wait_group 0;\n" ::: "memory"); }
__device__ __forceinline__ void cp_wait1()  { asm volatile("cp.async.wait_group 1;\n" ::: "memory"); }

__device__ __forceinline__ uint32_t smem_u32(const void* p) {
    return (uint32_t)__cvta_generic_to_shared(p);
}
__device__ __forceinline__ void ldsm4(uint32_t* r, uint32_t addr) {
    asm volatile("ldmatrix.sync.aligned.m8n8.x4.shared.b16 {%0,%1,%2,%3}, [%4];"
                 : "=r"(r[0]), "=r"(r[1]), "=r"(r[2]), "=r"(r[3]) : "r"(addr));
}
__device__ __forceinline__ void mma_f16(float* c, const uint32_t* a, const uint32_t* b) {
    asm volatile(
        "mma.sync.aligned.m16n8k16.row.col.f32.f16.f16.f32 "
        "{%0,%1,%2,%3}, {%4,%5,%6,%7}, {%8,%9}, {%0,%1,%2,%3};"
        : "+f"(c[0]), "+f"(c[1]), "+f"(c[2]), "+f"(c[3])
        : "r"(a[0]), "r"(a[1]), "r"(a[2]), "r"(a[3]), "r"(b[0]), "r"(b[1]));
}

// ---------------------------------------------------------------------------
// K0: task routing + counter reset
// ---------------------------------------------------------------------------
__global__ void k_task_route(const float* __restrict__ task_emb,
                             const int* __restrict__ task_id_p,
                             const float* __restrict__ trw) {
    __shared__ float sc[NE];
    int tid  = threadIdx.x;
    int e    = tid / 32;
    int lane = tid % 32;
    const float* tv = task_emb + (size_t)task_id_p[0] * HIDDEN;
    float acc = 0.f;
    if (e < NE) {
        for (int d = lane; d < HIDDEN; d += 32)
            acc += trw[(size_t)e * HIDDEN + d] * tv[d];
        #pragma unroll
        for (int o = 16; o > 0; o >>= 1)
            acc += __shfl_xor_sync(0xFFFFFFFFu, acc, o);
        if (lane == 0) sc[e] = acc;
    }
    __syncthreads();
    if (tid == 0) {
        float s[NE]; bool act[NE];
        for (int i = 0; i < NE; i++) { s[i] = sc[i]; act[i] = false; }
        for (int k = 0; k < NTASKEXP; k++) {
            int best = 0; float bv = -1e30f;
            for (int i = 0; i < NE; i++)
                if (!act[i] && s[i] > bv) { bv = s[i]; best = i; }
            act[best] = true;
        }
        for (int i = NE - NGEN; i < NE; i++) act[i] = true;
        for (int i = 0; i < NE; i++) {
            g_active[i] = act[i] ? 1 : 0;
            g_counts[i] = 0;
            g_cursor[i] = 0;
        }
    }
}

// ---------------------------------------------------------------------------
// K1: token gating (exact fp32) + fp16 copy of hs
// ---------------------------------------------------------------------------
__global__ void k_gate(const float* __restrict__ hs,
                       const float* __restrict__ task_emb,
                       const int* __restrict__ task_id_p,
                       const float* __restrict__ gw) {
    int warp = (blockIdx.x * blockDim.x + threadIdx.x) / 32;
    int lane = threadIdx.x % 32;
    if (warp >= NTOK) return;
    const float* tv = task_emb + (size_t)task_id_p[0] * HIDDEN;
    const float* h  = hs + (size_t)warp * HIDDEN;
    __half* ht = g_hs_h + (size_t)warp * HIDDEN;

    float acc[NE];
    #pragma unroll
    for (int e = 0; e < NE; e++) acc[e] = 0.f;

    for (int d = lane; d < HIDDEN; d += 32) {
        float hv = h[d];
        ht[d] = __float2half_rn(hv);
        float x = hv + tv[d];
        #pragma unroll
        for (int e = 0; e < NE; e++)
            acc[e] += x * gw[(size_t)e * HIDDEN + d];
    }
    #pragma unroll
    for (int e = 0; e < NE; e++) {
        #pragma unroll
        for (int o = 16; o > 0; o >>= 1)
            acc[e] += __shfl_xor_sync(0xFFFFFFFFu, acc[e], o);
    }
    if (lane == 0) {
        float m = -1e30f;
        #pragma unroll
        for (int e = 0; e < NE; e++)
            if (g_active[e] && acc[e] > m) m = acc[e];
        float p[NE]; float Z = 0.f;
        #pragma unroll
        for (int e = 0; e < NE; e++) {
            p[e] = g_active[e] ? expf(acc[e] - m) : 0.f;
            Z += p[e];
        }
        float inv = 1.f / Z;
        int i0 = 0; float v0 = -1.f;
        #pragma unroll
        for (int e = 0; e < NE; e++) {
            float s = p[e] * inv;
            if (s > v0) { v0 = s; i0 = e; }
        }
        int i1 = -1; float v1 = -1.f;
        #pragma unroll
        for (int e = 0; e < NE; e++) {
            if (e == i0) continue;
            float s = p[e] * inv;
            if (s > v1) { v1 = s; i1 = e; }
        }
        float ws = v0 + v1 + 1e-6f;
        g_tok_e[warp * 2 + 0] = i0;
        g_tok_e[warp * 2 + 1] = i1;
        g_tok_w[warp * 2 + 0] = v0 / ws;
        g_tok_w[warp * 2 + 1] = v1 / ws;
        atomicAdd(&g_counts[i0], 1);
        atomicAdd(&g_counts[i1], 1);
    }
}

__global__ void k_prefix() {
    if (threadIdx.x == 0) {
        int o = 0;
        for (int e = 0; e < NE; e++) { g_offsets[e] = o; o += g_counts[e]; }
    }
}

__global__ void k_place() {
    int n = blockIdx.x * blockDim.x + threadIdx.x;
    if (n >= NTOK) return;
    #pragma unroll
    for (int k = 0; k < TOPK; k++) {
        int e = g_tok_e[n * 2 + k];
        int slot = atomicAdd(&g_cursor[e], 1);
        int idx = g_offsets[e] + slot;
        g_pair_token[idx] = n;
        g_tok_pair[n * 2 + k] = idx;
    }
}

// ---------------------------------------------------------------------------
// all-weights fp32 -> fp16 (active experts only), one kernel
// ---------------------------------------------------------------------------
__global__ void k_cvt3(const float4* __restrict__ gp, const float4* __restrict__ up,
                       const float4* __restrict__ dp,
                       uint2* __restrict__ gph, uint2* __restrict__ uph,
                       uint2* __restrict__ dph) {
    int e = blockIdx.z;
    if (!g_active[e]) return;
    const int n4 = INTER * HIDDEN / 4;
    const float4* in = (blockIdx.y == 0) ? gp : (blockIdx.y == 1) ? up : dp;
    uint2* out = (blockIdx.y == 0) ? gph : (blockIdx.y == 1) ? uph : dph;
    const float4* src = in + (size_t)e * n4;
    uint2* dst = out + (size_t)e * n4;
    for (int i = blockIdx.x * blockDim.x + threadIdx.x; i < n4; i += gridDim.x * blockDim.x) {
        float4 v = src[i];
        __half2 lo = __floats2half2_rn(v.x, v.y);
        __half2 hi = __floats2half2_rn(v.z, v.w);
        uint2 o;
        o.x = *(const uint32_t*)&lo;
        o.y = *(const uint32_t*)&hi;
        dst[i] = o;
    }
}

// ---------------------------------------------------------------------------
// K4: GEMM1 (gate & up fused) + SwiGLU. BK=64, 3-stage cp.async pipeline.
// ---------------------------------------------------------------------------
__global__ void __launch_bounds__(256)
k_ffn1() {
    extern __shared__ __align__(16) char sm[];
    int e    = blockIdx.z;
    int cnt  = g_counts[e];
    int moff = blockIdx.y * BM;
    if (moff >= cnt) return;
    int off = g_offsets[e];
    int n0  = blockIdx.x * BN;
    int tid = threadIdx.x;

    // copy roles: 8 x 16B chunks per thread per stage
    int c16 = tid & 7;          // 0..7 (col chunk within 128B row)
    int rb  = tid >> 3;         // 0..31
    const char* srcA[4];
    uint32_t dA[4];
    #pragma unroll
    for (int t = 0; t < 4; t++) {
        int row = rb + 32 * t;
        dA[t] = (uint32_t)row * ROWB + c16 * 16u;
        int r = moff + row; if (r > cnt - 1) r = cnt - 1;
        srcA[t] = (const char*)(g_hs_h + (size_t)g_pair_token[off + r] * HIDDEN) + c16 * 16;
    }
    const char* srcG = (const char*)(g_gp_h + (size_t)e * INTER * HIDDEN +
                                     (size_t)(n0 + rb) * HIDDEN) + c16 * 16;
    const char* srcU = (const char*)(g_up_h + (size_t)e * INTER * HIDDEN +
                                     (size_t)(n0 + rb) * HIDDEN) + c16 * 16;
    const uint32_t dG = 18432u + (uint32_t)rb * ROWB + c16 * 16u;
    const uint32_t dU = 27648u + (uint32_t)rb * ROWB + c16 * 16u;
    const size_t BROW32 = (size_t)32 * HIDDEN * 2;   // 32 B-rows advance in bytes

    // prologue: stages 0,1
    #pragma unroll
    for (int s = 0; s < 2; s++) {
        char* st = sm + s * STG1;
        int adv = s * 128;
        #pragma unroll
        for (int t = 0; t < 4; t++) cp16(st + dA[t], srcA[t] + adv);
        cp16(st + dG, srcG + adv); cp16(st + dG + 32 * ROWB, srcG + BROW32 + adv);
        cp16(st + dU, srcU + adv); cp16(st + dU + 32 * ROWB, srcU + BROW32 + adv);
        cp_commit();
    }

    uint32_t sb = smem_u32(sm);
    int w = tid >> 5, lane = tid & 31;
    int wm = w >> 1, wn = w & 1;
    uint32_t aoff = (uint32_t)(wm * 32 + (lane & 15)) * ROWB + (lane >> 4) * 16u;
    uint32_t boff = (uint32_t)(wn * 32 + (lane & 7) + ((lane >> 4) << 3)) * ROWB
                    + ((lane >> 3) & 1) * 16u;

    float accg[2][4][4], accu[2][4][4];
    #pragma unroll
    for (int mt = 0; mt < 2; mt++)
        #pragma unroll
        for (int nt = 0; nt < 4; nt++)
            #pragma unroll
            for (int q = 0; q < 4; q++) { accg[mt][nt][q] = 0.f; accu[mt][nt][q] = 0.f; }

    const int T = HIDDEN / BKH;  // 16
    for (int j = 0; j < T; j++) {
        if (j < T - 1) cp_wait1(); else cp_wait0();
        __syncthreads();
        if (j + 2 < T) {
            char* st = sm + ((j + 2) % 3) * STG1;
            int adv = (j + 2) * 128;
            #pragma unroll
            for (int t = 0; t < 4; t++) cp16(st + dA[t], srcA[t] + adv);
            cp16(st + dG, srcG + adv); cp16(st + dG + 32 * ROWB, srcG + BROW32 + adv);
            cp16(st + dU, srcU + adv); cp16(st + dU + 32 * ROWB, srcU + BROW32 + adv);
            cp_commit();
        }
        uint32_t base = sb + (uint32_t)(j % 3) * STG1;
        #pragma unroll
        for (int kk = 0; kk < 4; kk++) {
            uint32_t a[2][4], bg[2][4], bu[2][4];
            ldsm4(a[0], base + aoff + kk * 32);
            ldsm4(a[1], base + aoff + 16 * ROWB + kk * 32);
            ldsm4(bg[0], base + 18432 + boff + kk * 32);
            ldsm4(bg[1], base + 18432 + boff + 16 * ROWB + kk * 32);
            ldsm4(bu[0], base + 27648 + boff + kk * 32);
            ldsm4(bu[1], base + 27648 + boff + 16 * ROWB + kk * 32);
            #pragma unroll
            for (int mt = 0; mt < 2; mt++)
                #pragma unroll
                for (int ng = 0; ng < 2; ng++)
                    #pragma unroll
                    for (int hh = 0; hh < 2; hh++) {
                        mma_f16(accg[mt][ng * 2 + hh], a[mt], &bg[ng][hh * 2]);
                        mma_f16(accu[mt][ng * 2 + hh], a[mt], &bu[ng][hh * 2]);
                    }
        }
    }

    // epilogue: SwiGLU -> g_act (fp16)
    #pragma unroll
    for (int mt = 0; mt < 2; mt++) {
        #pragma unroll
        for (int nt = 0; nt < 4; nt++) {
            int r0 = moff + wm * 32 + mt * 16 + (lane >> 2);
            int c  = n0 + wn * 32 + nt * 8 + 2 * (lane & 3);
            if (r0 < cnt) {
                __half* dst = g_act + (size_t)(off + r0) * INTER + c;
                float g0 = accg[mt][nt][0], u0 = accu[mt][nt][0];
                float g1 = accg[mt][nt][1], u1 = accu[mt][nt][1];
                *(__half2*)dst = __floats2half2_rn((g0 / (1.f + __expf(-g0))) * u0,
                                                   (g1 / (1.f + __expf(-g1))) * u1);
            }
            int r1 = r0 + 8;
            if (r1 < cnt) {
                __half* dst = g_act + (size_t)(off + r1) * INTER + c;
                float g0 = accg[mt][nt][2], u0 = accu[mt][nt][2];
                float g1 = accg[mt][nt][3], u1 = accu[mt][nt][3];
                *(__half2*)dst = __floats2half2_rn((g0 / (1.f + __expf(-g0))) * u0,
                                                   (g1 / (1.f + __expf(-g1))) * u1);
            }
        }
    }
}

// ---------------------------------------------------------------------------
// K5: GEMM2 (down). BK=64, 3-stage pipeline. K=INTER
// ---------------------------------------------------------------------------
__global__ void __launch_bounds__(256)
k_ffn2() {
    extern __shared__ __align__(16) char sm[];
    int e    = blockIdx.z;
    int cnt  = g_counts[e];
    int moff = blockIdx.y * BM;
    if (moff >= cnt) return;
    int off = g_offsets[e];
    int n0  = blockIdx.x * BN;
    int tid = threadIdx.x;

    int c16 = tid & 7;
    int rb  = tid >> 3;
    const char* srcA[4];
    uint32_t dA[4];
    #pragma unroll
    for (int t = 0; t < 4; t++) {
        int row = rb + 32 * t;
        dA[t] = (uint32_t)row * ROWB + c16 * 16u;
        int r = moff + row; if (r > cnt - 1) r = cnt - 1;
        srcA[t] = (const char*)(g_act + (size_t)(off + r) * INTER) + c16 * 16;
    }
    const char* srcB = (const char*)(g_dp_h + (size_t)e * HIDDEN * INTER +
                                     (size_t)(n0 + rb) * INTER) + c16 * 16;
    const uint32_t dB = 18432u + (uint32_t)rb * ROWB + c16 * 16u;
    const size_t BROW32 = (size_t)32 * INTER * 2;

    #pragma unroll
    for (int s = 0; s < 2; s++) {
        char* st = sm + s * STG2;
        int adv = s * 128;
        #pragma unroll
        for (int t = 0; t < 4; t++) cp16(st + dA[t], srcA[t] + adv);
        cp16(st + dB, srcB + adv); cp16(st + dB + 32 * ROWB, srcB + BROW32 + adv);
        cp_commit();
    }

    uint32_t sb = smem_u32(sm);
    int w = tid >> 5, lane = tid & 31;
    int wm = w >> 1, wn = w & 1;
    uint32_t aoff = (uint32_t)(wm * 32 + (lane & 15)) * ROWB + (lane >> 4) * 16u;
    uint32_t boff = (uint32_t)(wn * 32 + (lane & 7) + ((lane >> 4) << 3)) * ROWB
                    + ((lane >> 3) & 1) * 16u;

    float acc[2][4][4];
    #pragma unroll
    for (int mt = 0; mt < 2; mt++)
        #pragma unroll
        for (int nt = 0; nt < 4; nt++)
            #pragma unroll
            for (int q = 0; q < 4; q++) acc[mt][nt][q] = 0.f;

    const int T = INTER / BKH;  // 44
    for (int j = 0; j < T; j++) {
        if (j < T - 1) cp_wait1(); else cp_wait0();
        __syncthreads();
        if (j + 2 < T) {
            char* st = sm + ((j + 2) % 3) * STG2;
            int adv = (j + 2) * 128;
            #pragma unroll
            for (int t = 0; t < 4; t++) cp16(st + dA[t], srcA[t] + adv);
            cp16(st + dB, srcB + adv); cp16(st + dB + 32 * ROWB, srcB + BROW32 + adv);
            cp_commit();
        }
        uint32_t base = sb + (uint32_t)(j % 3) * STG2;
        #pragma unroll
        for (int kk = 0; kk < 4; kk++) {
            uint32_t a[2][4], bb[2][4];
            ldsm4(a[0], base + aoff + kk * 32);
            ldsm4(a[1], base + aoff + 16 * ROWB + kk * 32);
            ldsm4(bb[0], base + 18432 + boff + kk * 32);
            ldsm4(bb[1], base + 18432 + boff + 16 * ROWB + kk * 32);
            #pragma unroll
            for (int mt = 0; mt < 2; mt++)
                #pragma unroll
                for (int ng = 0; ng < 2; ng++)
                    #pragma unroll
                    for (int hh = 0; hh < 2; hh++)
                        mma_f16(acc[mt][ng * 2 + hh], a[mt], &bb[ng][hh * 2]);
        }
    }

    #pragma unroll
    for (int mt = 0; mt < 2; mt++) {
        #pragma unroll
        for (int nt = 0; nt < 4; nt++) {
            int r0 = moff + wm * 32 + mt * 16 + (lane >> 2);
            int c  = n0 + wn * 32 + nt * 8 + 2 * (lane & 3);
            if (r0 < cnt) {
                float2* dst = (float2*)(g_pair_out + (size_t)(off + r0) * HIDDEN + c);
                *dst = make_float2(acc[mt][nt][0], acc[mt][nt][1]);
            }
            int r1 = r0 + 8;
            if (r1 < cnt) {
                float2* dst = (float2*)(g_pair_out + (size_t)(off + r1) * HIDDEN + c);
                *dst = make_float2(acc[mt][nt][2], acc[mt][nt][3]);
            }
        }
    }
}

// ---------------------------------------------------------------------------
// K6: weighted combine
// ---------------------------------------------------------------------------
__global__ void k_combine(float* __restrict__ out) {
    int n = blockIdx.x;
    int p0 = g_tok_pair[n * 2 + 0];
    int p1 = g_tok_pair[n * 2 + 1];
    float w0 = g_tok_w[n * 2 + 0];
    float w1 = g_tok_w[n * 2 + 1];
    for (int d = threadIdx.x * 4; d < HIDDEN; d += blockDim.x * 4) {
        float4 a = *(const float4*)&g_pair_out[(size_t)p0 * HIDDEN + d];
        float4 b = *(const float4*)&g_pair_out[(size_t)p1 * HIDDEN + d];
        float4 o;
        o.x = w0 * a.x + w1 * b.x;
        o.y = w0 * a.y + w1 * b.y;
        o.z = w0 * a.z + w1 * b.z;
        o.w = w0 * a.w + w1 * b.w;
        *(float4*)&out[(size_t)n * HIDDEN + d] = o;
    }
}

// ---------------------------------------------------------------------------
extern "C" void kernel_launch(void* const* d_in, const int* in_sizes, int n_in,
                              void* d_out, int out_size) {
    const float* hs   = (const float*)d_in[0];
    const int*   tid  = (const int*)d_in[1];
    const float* temb = (const float*)d_in[2];
    const float* trw  = (const float*)d_in[3];
    const float* gw   = (const float*)d_in[4];
    const float* gp   = (const float*)d_in[5];
    const float* up   = (const float*)d_in[6];
    const float* dp   = (const float*)d_in[7];
    float* out = (float*)d_out;

    cudaFuncSetAttribute(k_ffn1, cudaFuncAttributeMaxDynamicSharedMemorySize, SMEM1);
    cudaFuncSetAttribute(k_ffn2, cudaFuncAttributeMaxDynamicSharedMemorySize, SMEM2);

    __half* gph; __half* uph; __half* dph;
    cudaGetSymbolAddress((void**)&gph, g_gp_h);
    cudaGetSymbolAddress((void**)&uph, g_up_h);
    cudaGetSymbolAddress((void**)&dph, g_dp_h);

    k_task_route<<<1, 256>>>(temb, tid, trw);

    dim3 gc(440, 3, NE);
    k_cvt3<<<gc, 256>>>((const float4*)gp, (const float4*)up, (const float4*)dp,
                        (uint2*)gph, (uint2*)uph, (uint2*)dph);

    k_gate<<<NTOK / 8, 256>>>(hs, temb, tid, gw);
    k_prefix<<<1, 32>>>();
    k_place<<<NTOK / 256, 256>>>();

    dim3 g1(INTER / BN, NTOK / BM, NE);   // 44 x 64 x 8
    k_ffn1<<<g1, 256, SMEM1>>>();
    dim3 g2(HIDDEN / BN, NTOK / BM, NE);  // 16 x 64 x 8
    k_ffn2<<<g2, 256, SMEM2>>>();
    k_combine<<<NTOK, 256>>>(out);
}

// round 8
// speedup vs baseline: 6.3377x; 1.0920x over previous
#include <cuda_runtime.h>
#include <cuda_fp16.h>
#include <math.h>
#include <stdint.h>

#define HIDDEN 1024
#define INTER  2816
#define NE     8
#define TOPK   2
#define NTASKEXP 4
#define NGEN   2
#define NTOK   8192
#define NPAIR  (NTOK*TOPK)
#define WELEM  (NE*INTER*HIDDEN)

#define BM 128
#define BN 64
#define BKH 32            // K halves per stage (64B row)
#define ROWB 80           // row stride bytes (64 data + 16 pad)
#define STG1 20480        // (128+64+64) rows * 80B
#define STG2 15360        // (128+64) rows * 80B
#define SMEM1 (3*STG1)    // 61440  -> 2 blocks/SM
#define SMEM2 (3*STG2)    // 46080  -> 2 blocks/SM

// ---- scratch (static device memory; no runtime allocation) ----
__device__ int    g_active[NE];
__device__ int    g_counts[NE];
__device__ int    g_offsets[NE];
__device__ int    g_cursor[NE];
__device__ int    g_pair_token[NPAIR];
__device__ int    g_tok_e[NTOK * TOPK];
__device__ float  g_tok_w[NTOK * TOPK];
__device__ int    g_tok_pair[NTOK * TOPK];
__device__ __half g_act[(size_t)NPAIR * INTER];
__device__ float  g_pair_out[(size_t)NPAIR * HIDDEN];
__device__ __half g_hs_h[(size_t)NTOK * HIDDEN];
__device__ __half g_gp_h[(size_t)WELEM];
__device__ __half g_up_h[(size_t)WELEM];
__device__ __half g_dp_h[(size_t)WELEM];

// ---------------------------------------------------------------------------
__device__ __forceinline__ void cp16(void* smem_ptr, const void* gptr) {
    uint32_t s = (uint32_t)__cvta_generic_to_shared(smem_ptr);
    asm volatile("cp.async.cg.shared.global [%0], [%1], 16;\n" :: "r"(s), "l"(gptr));
}
__device__ __forceinline__ void cp_commit() { asm volatile("cp.async.commit_group;\n"); }
__device__ __forceinline__ void cp_wait0()  { asm volatile("cp.async.wait_group 0;\n" ::: "memory"); }
__device__ __forceinline__ void cp_wait1()  { asm volatile("cp.async.wait_group 1;\n" ::: "memory"); }

__device__ __forceinline__ uint32_t smem_u32(const void* p) {
    return (uint32_t)__cvta_generic_to_shared(p);
}
__device__ __forceinline__ void ldsm4(uint32_t* r, uint32_t addr) {
    asm volatile("ldmatrix.sync.aligned.m8n8.x4.shared.b16 {%0,%1,%2,%3}, [%4];"
                 : "=r"(r[0]), "=r"(r[1]), "=r"(r[2]), "=r"(r[3]) : "r"(addr));
}
__device__ __forceinline__ void mma_f16(float* c, const uint32_t* a, const uint32_t* b) {
    asm volatile(
        "mma.sync.aligned.m16n8k16.row.col.f32.f16.f16.f32 "
        "{%0,%1,%2,%3}, {%4,%5,%6,%7}, {%8,%9}, {%0,%1,%2,%3};"
        : "+f"(c[0]), "+f"(c[1]), "+f"(c[2]), "+f"(c[3])
        : "r"(a[0]), "r"(a[1]), "r"(a[2]), "r"(a[3]), "r"(b[0]), "r"(b[1]));
}

// ---------------------------------------------------------------------------
// K0: task routing + counter reset
// ---------------------------------------------------------------------------
__global__ void k_task_route(const float* __restrict__ task_emb,
                             const int* __restrict__ task_id_p,
                             const float* __restrict__ trw) {
    __shared__ float sc[NE];
    int tid  = threadIdx.x;
    int e    = tid / 32;
    int lane = tid % 32;
    const float* tv = task_emb + (size_t)task_id_p[0] * HIDDEN;
    float acc = 0.f;
    if (e < NE) {
        for (int d = lane; d < HIDDEN; d += 32)
            acc += trw[(size_t)e * HIDDEN + d] * tv[d];
        #pragma unroll
        for (int o = 16; o > 0; o >>= 1)
            acc += __shfl_xor_sync(0xFFFFFFFFu, acc, o);
        if (lane == 0) sc[e] = acc;
    }
    __syncthreads();
    if (tid == 0) {
        float s[NE]; bool act[NE];
        for (int i = 0; i < NE; i++) { s[i] = sc[i]; act[i] = false; }
        for (int k = 0; k < NTASKEXP; k++) {
            int best = 0; float bv = -1e30f;
            for (int i = 0; i < NE; i++)
                if (!act[i] && s[i] > bv) { bv = s[i]; best = i; }
            act[best] = true;
        }
        for (int i = NE - NGEN; i < NE; i++) act[i] = true;
        for (int i = 0; i < NE; i++) {
            g_active[i] = act[i] ? 1 : 0;
            g_counts[i] = 0;
            g_cursor[i] = 0;
        }
    }
}

// ---------------------------------------------------------------------------
// K1: token gating (exact fp32) + fp16 copy of hs
// ---------------------------------------------------------------------------
__global__ void k_gate(const float* __restrict__ hs,
                       const float* __restrict__ task_emb,
                       const int* __restrict__ task_id_p,
                       const float* __restrict__ gw) {
    int warp = (blockIdx.x * blockDim.x + threadIdx.x) / 32;
    int lane = threadIdx.x % 32;
    if (warp >= NTOK) return;
    const float* tv = task_emb + (size_t)task_id_p[0] * HIDDEN;
    const float* h  = hs + (size_t)warp * HIDDEN;
    __half* ht = g_hs_h + (size_t)warp * HIDDEN;

    float acc[NE];
    #pragma unroll
    for (int e = 0; e < NE; e++) acc[e] = 0.f;

    for (int d = lane; d < HIDDEN; d += 32) {
        float hv = h[d];
        ht[d] = __float2half_rn(hv);
        float x = hv + tv[d];
        #pragma unroll
        for (int e = 0; e < NE; e++)
            acc[e] += x * gw[(size_t)e * HIDDEN + d];
    }
    #pragma unroll
    for (int e = 0; e < NE; e++) {
        #pragma unroll
        for (int o = 16; o > 0; o >>= 1)
            acc[e] += __shfl_xor_sync(0xFFFFFFFFu, acc[e], o);
    }
    if (lane == 0) {
        float m = -1e30f;
        #pragma unroll
        for (int e = 0; e < NE; e++)
            if (g_active[e] && acc[e] > m) m = acc[e];
        float p[NE]; float Z = 0.f;
        #pragma unroll
        for (int e = 0; e < NE; e++) {
            p[e] = g_active[e] ? expf(acc[e] - m) : 0.f;
            Z += p[e];
        }
        float inv = 1.f / Z;
        int i0 = 0; float v0 = -1.f;
        #pragma unroll
        for (int e = 0; e < NE; e++) {
            float s = p[e] * inv;
            if (s > v0) { v0 = s; i0 = e; }
        }
        int i1 = -1; float v1 = -1.f;
        #pragma unroll
        for (int e = 0; e < NE; e++) {
            if (e == i0) continue;
            float s = p[e] * inv;
            if (s > v1) { v1 = s; i1 = e; }
        }
        float ws = v0 + v1 + 1e-6f;
        g_tok_e[warp * 2 + 0] = i0;
        g_tok_e[warp * 2 + 1] = i1;
        g_tok_w[warp * 2 + 0] = v0 / ws;
        g_tok_w[warp * 2 + 1] = v1 / ws;
        atomicAdd(&g_counts[i0], 1);
        atomicAdd(&g_counts[i1], 1);
    }
}

__global__ void k_prefix() {
    if (threadIdx.x == 0) {
        int o = 0;
        for (int e = 0; e < NE; e++) { g_offsets[e] = o; o += g_counts[e]; }
    }
}

__global__ void k_place() {
    int n = blockIdx.x * blockDim.x + threadIdx.x;
    if (n >= NTOK) return;
    #pragma unroll
    for (int k = 0; k < TOPK; k++) {
        int e = g_tok_e[n * 2 + k];
        int slot = atomicAdd(&g_cursor[e], 1);
        int idx = g_offsets[e] + slot;
        g_pair_token[idx] = n;
        g_tok_pair[n * 2 + k] = idx;
    }
}

// ---------------------------------------------------------------------------
// all-weights fp32 -> fp16 (active experts only)
// ---------------------------------------------------------------------------
__global__ void k_cvt3(const float4* __restrict__ gp, const float4* __restrict__ up,
                       const float4* __restrict__ dp,
                       uint2* __restrict__ gph, uint2* __restrict__ uph,
                       uint2* __restrict__ dph) {
    int e = blockIdx.z;
    if (!g_active[e]) return;
    const int n4 = INTER * HIDDEN / 4;
    const float4* in = (blockIdx.y == 0) ? gp : (blockIdx.y == 1) ? up : dp;
    uint2* out = (blockIdx.y == 0) ? gph : (blockIdx.y == 1) ? uph : dph;
    const float4* src = in + (size_t)e * n4;
    uint2* dst = out + (size_t)e * n4;
    for (int i = blockIdx.x * blockDim.x + threadIdx.x; i < n4; i += gridDim.x * blockDim.x) {
        float4 v = src[i];
        __half2 lo = __floats2half2_rn(v.x, v.y);
        __half2 hi = __floats2half2_rn(v.z, v.w);
        uint2 o;
        o.x = *(const uint32_t*)&lo;
        o.y = *(const uint32_t*)&hi;
        dst[i] = o;
    }
}

// ---------------------------------------------------------------------------
// K4: GEMM1 (gate & up fused) + SwiGLU. BK=32, 3-stage, 2 blocks/SM.
// ---------------------------------------------------------------------------
__global__ void __launch_bounds__(256, 2)
k_ffn1() {
    extern __shared__ __align__(16) char sm[];
    int e    = blockIdx.z;
    int cnt  = g_counts[e];
    int moff = blockIdx.y * BM;
    if (moff >= cnt) return;
    int off = g_offsets[e];
    int n0  = blockIdx.x * BN;
    int tid = threadIdx.x;

    // copy roles: 4 x 16B chunks per thread per stage (rows: 0-127 A, 128-191 Bg, 192-255 Bu)
    const char* src[4];
    uint32_t dsto[4];
    #pragma unroll
    for (int t = 0; t < 4; t++) {
        int q = tid + t * 256;
        int row = q >> 2, c16 = q & 3;
        if (row < 128) {
            dsto[t] = (uint32_t)row * ROWB + c16 * 16u;
            int r = moff + row; if (r > cnt - 1) r = cnt - 1;
            src[t] = (const char*)(g_hs_h + (size_t)g_pair_token[off + r] * HIDDEN) + c16 * 16;
        } else if (row < 192) {
            int rr = row - 128;
            dsto[t] = 10240u + (uint32_t)rr * ROWB + c16 * 16u;
            src[t] = (const char*)(g_gp_h + (size_t)e * INTER * HIDDEN + (size_t)(n0 + rr) * HIDDEN) + c16 * 16;
        } else {
            int rr = row - 192;
            dsto[t] = 15360u + (uint32_t)rr * ROWB + c16 * 16u;
            src[t] = (const char*)(g_up_h + (size_t)e * INTER * HIDDEN + (size_t)(n0 + rr) * HIDDEN) + c16 * 16;
        }
    }

    // prologue: stages 0,1
    #pragma unroll
    for (int s = 0; s < 2; s++) {
        char* st = sm + s * STG1;
        int adv = s * 64;
        #pragma unroll
        for (int t = 0; t < 4; t++) cp16(st + dsto[t], src[t] + adv);
        cp_commit();
    }

    uint32_t sb = smem_u32(sm);
    int w = tid >> 5, lane = tid & 31;
    int wm = w >> 1, wn = w & 1;
    uint32_t aoff = (uint32_t)(wm * 32 + (lane & 15)) * ROWB + (lane >> 4) * 16u;
    uint32_t boff = (uint32_t)(wn * 32 + (lane & 7) + ((lane >> 4) << 3)) * ROWB
                    + ((lane >> 3) & 1) * 16u;

    float accg[2][4][4], accu[2][4][4];
    #pragma unroll
    for (int mt = 0; mt < 2; mt++)
        #pragma unroll
        for (int nt = 0; nt < 4; nt++)
            #pragma unroll
            for (int q = 0; q < 4; q++) { accg[mt][nt][q] = 0.f; accu[mt][nt][q] = 0.f; }

    const int T = HIDDEN / BKH;  // 32
    for (int j = 0; j < T; j++) {
        if (j < T - 1) cp_wait1(); else cp_wait0();
        __syncthreads();
        if (j + 2 < T) {
            char* st = sm + ((j + 2) % 3) * STG1;
            int adv = (j + 2) * 64;
            #pragma unroll
            for (int t = 0; t < 4; t++) cp16(st + dsto[t], src[t] + adv);
            cp_commit();
        }
        uint32_t base = sb + (uint32_t)(j % 3) * STG1;
        #pragma unroll
        for (int kk = 0; kk < 2; kk++) {
            uint32_t a[2][4], bg[2][4], bu[2][4];
            ldsm4(a[0], base + aoff + kk * 32);
            ldsm4(a[1], base + aoff + 16 * ROWB + kk * 32);
            ldsm4(bg[0], base + 10240 + boff + kk * 32);
            ldsm4(bg[1], base + 10240 + boff + 16 * ROWB + kk * 32);
            ldsm4(bu[0], base + 15360 + boff + kk * 32);
            ldsm4(bu[1], base + 15360 + boff + 16 * ROWB + kk * 32);
            #pragma unroll
            for (int mt = 0; mt < 2; mt++)
                #pragma unroll
                for (int ng = 0; ng < 2; ng++)
                    #pragma unroll
                    for (int hh = 0; hh < 2; hh++) {
                        mma_f16(accg[mt][ng * 2 + hh], a[mt], &bg[ng][hh * 2]);
                        mma_f16(accu[mt][ng * 2 + hh], a[mt], &bu[ng][hh * 2]);
                    }
        }
    }

    // epilogue: SwiGLU -> g_act (fp16)
    #pragma unroll
    for (int mt = 0; mt < 2; mt++) {
        #pragma unroll
        for (int nt = 0; nt < 4; nt++) {
            int r0 = moff + wm * 32 + mt * 16 + (lane >> 2);
            int c  = n0 + wn * 32 + nt * 8 + 2 * (lane & 3);
            if (r0 < cnt) {
                __half* dst = g_act + (size_t)(off + r0) * INTER + c;
                float g0 = accg[mt][nt][0], u0 = accu[mt][nt][0];
                float g1 = accg[mt][nt][1], u1 = accu[mt][nt][1];
                *(__half2*)dst = __floats2half2_rn((g0 / (1.f + __expf(-g0))) * u0,
                                                   (g1 / (1.f + __expf(-g1))) * u1);
            }
            int r1 = r0 + 8;
            if (r1 < cnt) {
                __half* dst = g_act + (size_t)(off + r1) * INTER + c;
                float g0 = accg[mt][nt][2], u0 = accu[mt][nt][2];
                float g1 = accg[mt][nt][3], u1 = accu[mt][nt][3];
                *(__half2*)dst = __floats2half2_rn((g0 / (1.f + __expf(-g0))) * u0,
                                                   (g1 / (1.f + __expf(-g1))) * u1);
            }
        }
    }
}

// ---------------------------------------------------------------------------
// K5: GEMM2 (down). BK=32, 3-stage, 2 blocks/SM. K=INTER
// ---------------------------------------------------------------------------
__global__ void __launch_bounds__(256, 2)
k_ffn2() {
    extern __shared__ __align__(16) char sm[];
    int e    = blockIdx.z;
    int cnt  = g_counts[e];
    int moff = blockIdx.y * BM;
    if (moff >= cnt) return;
    int off = g_offsets[e];
    int n0  = blockIdx.x * BN;
    int tid = threadIdx.x;

    const char* src[3];
    uint32_t dsto[3];
    #pragma unroll
    for (int t = 0; t < 3; t++) {
        int q = tid + t * 256;
        int row = q >> 2, c16 = q & 3;
        if (row < 128) {
            dsto[t] = (uint32_t)row * ROWB + c16 * 16u;
            int r = moff + row; if (r > cnt - 1) r = cnt - 1;
            src[t] = (const char*)(g_act + (size_t)(off + r) * INTER) + c16 * 16;
        } else {
            int rr = row - 128;
            dsto[t] = 10240u + (uint32_t)rr * ROWB + c16 * 16u;
            src[t] = (const char*)(g_dp_h + (size_t)e * HIDDEN * INTER + (size_t)(n0 + rr) * INTER) + c16 * 16;
        }
    }

    #pragma unroll
    for (int s = 0; s < 2; s++) {
        char* st = sm + s * STG2;
        int adv = s * 64;
        #pragma unroll
        for (int t = 0; t < 3; t++) cp16(st + dsto[t], src[t] + adv);
        cp_commit();
    }

    uint32_t sb = smem_u32(sm);
    int w = tid >> 5, lane = tid & 31;
    int wm = w >> 1, wn = w & 1;
    uint32_t aoff = (uint32_t)(wm * 32 + (lane & 15)) * ROWB + (lane >> 4) * 16u;
    uint32_t boff = (uint32_t)(wn * 32 + (lane & 7) + ((lane >> 4) << 3)) * ROWB
                    + ((lane >> 3) & 1) * 16u;

    float acc[2][4][4];
    #pragma unroll
    for (int mt = 0; mt < 2; mt++)
        #pragma unroll
        for (int nt = 0; nt < 4; nt++)
            #pragma unroll
            for (int q = 0; q < 4; q++) acc[mt][nt][q] = 0.f;

    const int T = INTER / BKH;  // 88
    for (int j = 0; j < T; j++) {
        if (j < T - 1) cp_wait1(); else cp_wait0();
        __syncthreads();
        if (j + 2 < T) {
            char* st = sm + ((j + 2) % 3) * STG2;
            int adv = (j + 2) * 64;
            #pragma unroll
            for (int t = 0; t < 3; t++) cp16(st + dsto[t], src[t] + adv);
            cp_commit();
        }
        uint32_t base = sb + (uint32_t)(j % 3) * STG2;
        #pragma unroll
        for (int kk = 0; kk < 2; kk++) {
            uint32_t a[2][4], bb[2][4];
            ldsm4(a[0], base + aoff + kk * 32);
            ldsm4(a[1], base + aoff + 16 * ROWB + kk * 32);
            ldsm4(bb[0], base + 10240 + boff + kk * 32);
            ldsm4(bb[1], base + 10240 + boff + 16 * ROWB + kk * 32);
            #pragma unroll
            for (int mt = 0; mt < 2; mt++)
                #pragma unroll
                for (int ng = 0; ng < 2; ng++)
                    #pragma unroll
                    for (int hh = 0; hh < 2; hh++)
                        mma_f16(acc[mt][ng * 2 + hh], a[mt], &bb[ng][hh * 2]);
        }
    }

    #pragma unroll
    for (int mt = 0; mt < 2; mt++) {
        #pragma unroll
        for (int nt = 0; nt < 4; nt++) {
            int r0 = moff + wm * 32 + mt * 16 + (lane >> 2);
            int c  = n0 + wn * 32 + nt * 8 + 2 * (lane & 3);
            if (r0 < cnt) {
                float2* dst = (float2*)(g_pair_out + (size_t)(off + r0) * HIDDEN + c);
                *dst = make_float2(acc[mt][nt][0], acc[mt][nt][1]);
            }
            int r1 = r0 + 8;
            if (r1 < cnt) {
                float2* dst = (float2*)(g_pair_out + (size_t)(off + r1) * HIDDEN + c);
                *dst = make_float2(acc[mt][nt][2], acc[mt][nt][3]);
            }
        }
    }
}

// ---------------------------------------------------------------------------
// K6: weighted combine
// ---------------------------------------------------------------------------
__global__ void k_combine(float* __restrict__ out) {
    int n = blockIdx.x;
    int p0 = g_tok_pair[n * 2 + 0];
    int p1 = g_tok_pair[n * 2 + 1];
    float w0 = g_tok_w[n * 2 + 0];
    float w1 = g_tok_w[n * 2 + 1];
    for (int d = threadIdx.x * 4; d < HIDDEN; d += blockDim.x * 4) {
        float4 a = *(const float4*)&g_pair_out[(size_t)p0 * HIDDEN + d];
        float4 b = *(const float4*)&g_pair_out[(size_t)p1 * HIDDEN + d];
        float4 o;
        o.x = w0 * a.x + w1 * b.x;
        o.y = w0 * a.y + w1 * b.y;
        o.z = w0 * a.z + w1 * b.z;
        o.w = w0 * a.w + w1 * b.w;
        *(float4*)&out[(size_t)n * HIDDEN + d] = o;
    }
}

// ---------------------------------------------------------------------------
extern "C" void kernel_launch(void* const* d_in, const int* in_sizes, int n_in,
                              void* d_out, int out_size) {
    const float* hs   = (const float*)d_in[0];
    const int*   tid  = (const int*)d_in[1];
    const float* temb = (const float*)d_in[2];
    const float* trw  = (const float*)d_in[3];
    const float* gw   = (const float*)d_in[4];
    const float* gp   = (const float*)d_in[5];
    const float* up   = (const float*)d_in[6];
    const float* dp   = (const float*)d_in[7];
    float* out = (float*)d_out;

    cudaFuncSetAttribute(k_ffn1, cudaFuncAttributeMaxDynamicSharedMemorySize, SMEM1);
    cudaFuncSetAttribute(k_ffn2, cudaFuncAttributeMaxDynamicSharedMemorySize, SMEM2);

    __half* gph; __half* uph; __half* dph;
    cudaGetSymbolAddress((void**)&gph, g_gp_h);
    cudaGetSymbolAddress((void**)&uph, g_up_h);
    cudaGetSymbolAddress((void**)&dph, g_dp_h);

    k_task_route<<<1, 256>>>(temb, tid, trw);

    dim3 gc(440, 3, NE);
    k_cvt3<<<gc, 256>>>((const float4*)gp, (const float4*)up, (const float4*)dp,
                        (uint2*)gph, (uint2*)uph, (uint2*)dph);

    k_gate<<<NTOK / 8, 256>>>(hs, temb, tid, gw);
    k_prefix<<<1, 32>>>();
    k_place<<<NTOK / 256, 256>>>();

    dim3 g1(INTER / BN, NTOK / BM, NE);   // 44 x 64 x 8
    k_ffn1<<<g1, 256, SMEM1>>>();
    dim3 g2(HIDDEN / BN, NTOK / BM, NE);  // 16 x 64 x 8
    k_ffn2<<<g2, 256, SMEM2>>>();
    k_combine<<<NTOK, 256>>>(out);
}

// round 9
// speedup vs baseline: 6.4575x; 1.0189x over previous
#include <cuda_runtime.h>
#include <cuda_fp16.h>
#include <math.h>
#include <stdint.h>

#define HIDDEN 1024
#define INTER  2816
#define NE     8
#define TOPK   2
#define NTASKEXP 4
#define NGEN   2
#define NTOK   8192
#define NPAIR  (NTOK*TOPK)
#define WELEM  (NE*INTER*HIDDEN)

#define BM 128
#define BN 64
#define BKH 32            // K halves per stage (64B row)
#define ROWB 80           // row stride bytes (64 data + 16 pad)
#define STG1 20480        // (128+64+64) rows * 80B
#define STG2 15360        // (128+64) rows * 80B
#define SMEM1 (3*STG1)    // 61440  -> 2 blocks/SM
#define SMEM2 (3*STG2)    // 46080  -> 2 blocks/SM

// ---- scratch (static device memory; no runtime allocation) ----
__device__ int    g_active[NE];
__device__ int    g_counts[NE];
__device__ int    g_offsets[NE];
__device__ int    g_cursor[NE];
__device__ int    g_pair_token[NPAIR];
__device__ float  g_pair_w[NPAIR];
__device__ int    g_tok_e[NTOK * TOPK];
__device__ float  g_tok_w[NTOK * TOPK];
__device__ __half g_act[(size_t)NPAIR * INTER];
__device__ __half g_hs_h[(size_t)NTOK * HIDDEN];
__device__ __half g_gp_h[(size_t)WELEM];
__device__ __half g_up_h[(size_t)WELEM];
__device__ __half g_dp_h[(size_t)WELEM];

// ---------------------------------------------------------------------------
__device__ __forceinline__ void cp16(void* smem_ptr, const void* gptr) {
    uint32_t s = (uint32_t)__cvta_generic_to_shared(smem_ptr);
    asm volatile("cp.async.cg.shared.global [%0], [%1], 16;\n" :: "r"(s), "l"(gptr));
}
__device__ __forceinline__ void cp_commit() { asm volatile("cp.async.commit_group;\n"); }
__device__ __forceinline__ void cp_wait0()  { asm volatile("cp.async.wait_group 0;\n" ::: "memory"); }
__device__ __forceinline__ void cp_wait1()  { asm volatile("cp.async.wait_group 1;\n" ::: "memory"); }

__device__ __forceinline__ uint32_t smem_u32(const void* p) {
    return (uint32_t)__cvta_generic_to_shared(p);
}
__device__ __forceinline__ void ldsm4(uint32_t* r, uint32_t addr) {
    asm volatile("ldmatrix.sync.aligned.m8n8.x4.shared.b16 {%0,%1,%2,%3}, [%4];"
                 : "=r"(r[0]), "=r"(r[1]), "=r"(r[2]), "=r"(r[3]) : "r"(addr));
}
__device__ __forceinline__ void mma_f16(float* c, const uint32_t* a, const uint32_t* b) {
    asm volatile(
        "mma.sync.aligned.m16n8k16.row.col.f32.f16.f16.f32 "
        "{%0,%1,%2,%3}, {%4,%5,%6,%7}, {%8,%9}, {%0,%1,%2,%3};"
        : "+f"(c[0]), "+f"(c[1]), "+f"(c[2]), "+f"(c[3])
        : "r"(a[0]), "r"(a[1]), "r"(a[2]), "r"(a[3]), "r"(b[0]), "r"(b[1]));
}

// ---------------------------------------------------------------------------
// K0: zero d_out (atomic accumulation target)
// ---------------------------------------------------------------------------
__global__ void k_zero(float4* __restrict__ out) {
    int i = blockIdx.x * blockDim.x + threadIdx.x;
    const int n4 = NTOK * HIDDEN / 4;
    for (; i < n4; i += gridDim.x * blockDim.x)
        out[i] = make_float4(0.f, 0.f, 0.f, 0.f);
}

// ---------------------------------------------------------------------------
// K1: task routing + counter reset
// ---------------------------------------------------------------------------
__global__ void k_task_route(const float* __restrict__ task_emb,
                             const int* __restrict__ task_id_p,
                             const float* __restrict__ trw) {
    __shared__ float sc[NE];
    int tid  = threadIdx.x;
    int e    = tid / 32;
    int lane = tid % 32;
    const float* tv = task_emb + (size_t)task_id_p[0] * HIDDEN;
    float acc = 0.f;
    if (e < NE) {
        for (int d = lane; d < HIDDEN; d += 32)
            acc += trw[(size_t)e * HIDDEN + d] * tv[d];
        #pragma unroll
        for (int o = 16; o > 0; o >>= 1)
            acc += __shfl_xor_sync(0xFFFFFFFFu, acc, o);
        if (lane == 0) sc[e] = acc;
    }
    __syncthreads();
    if (tid == 0) {
        float s[NE]; bool act[NE];
        for (int i = 0; i < NE; i++) { s[i] = sc[i]; act[i] = false; }
        for (int k = 0; k < NTASKEXP; k++) {
            int best = 0; float bv = -1e30f;
            for (int i = 0; i < NE; i++)
                if (!act[i] && s[i] > bv) { bv = s[i]; best = i; }
            act[best] = true;
        }
        for (int i = NE - NGEN; i < NE; i++) act[i] = true;
        for (int i = 0; i < NE; i++) {
            g_active[i] = act[i] ? 1 : 0;
            g_counts[i] = 0;
            g_cursor[i] = 0;
        }
    }
}

// ---------------------------------------------------------------------------
// K2: token gating (exact fp32) + fp16 copy of hs
// ---------------------------------------------------------------------------
__global__ void k_gate(const float* __restrict__ hs,
                       const float* __restrict__ task_emb,
                       const int* __restrict__ task_id_p,
                       const float* __restrict__ gw) {
    int warp = (blockIdx.x * blockDim.x + threadIdx.x) / 32;
    int lane = threadIdx.x % 32;
    if (warp >= NTOK) return;
    const float* tv = task_emb + (size_t)task_id_p[0] * HIDDEN;
    const float* h  = hs + (size_t)warp * HIDDEN;
    __half* ht = g_hs_h + (size_t)warp * HIDDEN;

    float acc[NE];
    #pragma unroll
    for (int e = 0; e < NE; e++) acc[e] = 0.f;

    for (int d = lane; d < HIDDEN; d += 32) {
        float hv = h[d];
        ht[d] = __float2half_rn(hv);
        float x = hv + tv[d];
        #pragma unroll
        for (int e = 0; e < NE; e++)
            acc[e] += x * gw[(size_t)e * HIDDEN + d];
    }
    #pragma unroll
    for (int e = 0; e < NE; e++) {
        #pragma unroll
        for (int o = 16; o > 0; o >>= 1)
            acc[e] += __shfl_xor_sync(0xFFFFFFFFu, acc[e], o);
    }
    if (lane == 0) {
        float m = -1e30f;
        #pragma unroll
        for (int e = 0; e < NE; e++)
            if (g_active[e] && acc[e] > m) m = acc[e];
        float p[NE]; float Z = 0.f;
        #pragma unroll
        for (int e = 0; e < NE; e++) {
            p[e] = g_active[e] ? expf(acc[e] - m) : 0.f;
            Z += p[e];
        }
        float inv = 1.f / Z;
        int i0 = 0; float v0 = -1.f;
        #pragma unroll
        for (int e = 0; e < NE; e++) {
            float s = p[e] * inv;
            if (s > v0) { v0 = s; i0 = e; }
        }
        int i1 = -1; float v1 = -1.f;
        #pragma unroll
        for (int e = 0; e < NE; e++) {
            if (e == i0) continue;
            float s = p[e] * inv;
            if (s > v1) { v1 = s; i1 = e; }
        }
        float ws = v0 + v1 + 1e-6f;
        g_tok_e[warp * 2 + 0] = i0;
        g_tok_e[warp * 2 + 1] = i1;
        g_tok_w[warp * 2 + 0] = v0 / ws;
        g_tok_w[warp * 2 + 1] = v1 / ws;
        atomicAdd(&g_counts[i0], 1);
        atomicAdd(&g_counts[i1], 1);
    }
}

__global__ void k_prefix() {
    if (threadIdx.x == 0) {
        int o = 0;
        for (int e = 0; e < NE; e++) { g_offsets[e] = o; o += g_counts[e]; }
    }
}

__global__ void k_place() {
    int n = blockIdx.x * blockDim.x + threadIdx.x;
    if (n >= NTOK) return;
    #pragma unroll
    for (int k = 0; k < TOPK; k++) {
        int e = g_tok_e[n * 2 + k];
        int slot = atomicAdd(&g_cursor[e], 1);
        int idx = g_offsets[e] + slot;
        g_pair_token[idx] = n;
        g_pair_w[idx] = g_tok_w[n * 2 + k];
    }
}

// ---------------------------------------------------------------------------
// all-weights fp32 -> fp16 (active experts only)
// ---------------------------------------------------------------------------
__global__ void k_cvt3(const float4* __restrict__ gp, const float4* __restrict__ up,
                       const float4* __restrict__ dp,
                       uint2* __restrict__ gph, uint2* __restrict__ uph,
                       uint2* __restrict__ dph) {
    int e = blockIdx.z;
    if (!g_active[e]) return;
    const int n4 = INTER * HIDDEN / 4;
    const float4* in = (blockIdx.y == 0) ? gp : (blockIdx.y == 1) ? up : dp;
    uint2* out = (blockIdx.y == 0) ? gph : (blockIdx.y == 1) ? uph : dph;
    const float4* src = in + (size_t)e * n4;
    uint2* dst = out + (size_t)e * n4;
    for (int i = blockIdx.x * blockDim.x + threadIdx.x; i < n4; i += gridDim.x * blockDim.x) {
        float4 v = src[i];
        __half2 lo = __floats2half2_rn(v.x, v.y);
        __half2 hi = __floats2half2_rn(v.z, v.w);
        uint2 o;
        o.x = *(const uint32_t*)&lo;
        o.y = *(const uint32_t*)&hi;
        dst[i] = o;
    }
}

// ---------------------------------------------------------------------------
// K5: GEMM1 (gate & up fused) + SwiGLU. BK=32, 3-stage, 2 blocks/SM.
//     grid.x = M-tile (fastest) so concurrent blocks share weight tiles in L2.
// ---------------------------------------------------------------------------
__global__ void __launch_bounds__(256, 2)
k_ffn1() {
    extern __shared__ __align__(16) char sm[];
    int e    = blockIdx.z;
    int cnt  = g_counts[e];
    int moff = blockIdx.x * BM;
    if (moff >= cnt) return;
    int off = g_offsets[e];
    int n0  = blockIdx.y * BN;
    int tid = threadIdx.x;

    const char* src[4];
    uint32_t dsto[4];
    #pragma unroll
    for (int t = 0; t < 4; t++) {
        int q = tid + t * 256;
        int row = q >> 2, c16 = q & 3;
        if (row < 128) {
            dsto[t] = (uint32_t)row * ROWB + c16 * 16u;
            int r = moff + row; if (r > cnt - 1) r = cnt - 1;
            src[t] = (const char*)(g_hs_h + (size_t)g_pair_token[off + r] * HIDDEN) + c16 * 16;
        } else if (row < 192) {
            int rr = row - 128;
            dsto[t] = 10240u + (uint32_t)rr * ROWB + c16 * 16u;
            src[t] = (const char*)(g_gp_h + (size_t)e * INTER * HIDDEN + (size_t)(n0 + rr) * HIDDEN) + c16 * 16;
        } else {
            int rr = row - 192;
            dsto[t] = 15360u + (uint32_t)rr * ROWB + c16 * 16u;
            src[t] = (const char*)(g_up_h + (size_t)e * INTER * HIDDEN + (size_t)(n0 + rr) * HIDDEN) + c16 * 16;
        }
    }

    #pragma unroll
    for (int s = 0; s < 2; s++) {
        char* st = sm + s * STG1;
        int adv = s * 64;
        #pragma unroll
        for (int t = 0; t < 4; t++) cp16(st + dsto[t], src[t] + adv);
        cp_commit();
    }

    uint32_t sb = smem_u32(sm);
    int w = tid >> 5, lane = tid & 31;
    int wm = w >> 1, wn = w & 1;
    uint32_t aoff = (uint32_t)(wm * 32 + (lane & 15)) * ROWB + (lane >> 4) * 16u;
    uint32_t boff = (uint32_t)(wn * 32 + (lane & 7) + ((lane >> 4) << 3)) * ROWB
                    + ((lane >> 3) & 1) * 16u;

    float accg[2][4][4], accu[2][4][4];
    #pragma unroll
    for (int mt = 0; mt < 2; mt++)
        #pragma unroll
        for (int nt = 0; nt < 4; nt++)
            #pragma unroll
            for (int q = 0; q < 4; q++) { accg[mt][nt][q] = 0.f; accu[mt][nt][q] = 0.f; }

    const int T = HIDDEN / BKH;  // 32
    for (int j = 0; j < T; j++) {
        if (j < T - 1) cp_wait1(); else cp_wait0();
        __syncthreads();
        if (j + 2 < T) {
            char* st = sm + ((j + 2) % 3) * STG1;
            int adv = (j + 2) * 64;
            #pragma unroll
            for (int t = 0; t < 4; t++) cp16(st + dsto[t], src[t] + adv);
            cp_commit();
        }
        uint32_t base = sb + (uint32_t)(j % 3) * STG1;
        #pragma unroll
        for (int kk = 0; kk < 2; kk++) {
            uint32_t a[2][4], bg[2][4], bu[2][4];
            ldsm4(a[0], base + aoff + kk * 32);
            ldsm4(a[1], base + aoff + 16 * ROWB + kk * 32);
            ldsm4(bg[0], base + 10240 + boff + kk * 32);
            ldsm4(bg[1], base + 10240 + boff + 16 * ROWB + kk * 32);
            ldsm4(bu[0], base + 15360 + boff + kk * 32);
            ldsm4(bu[1], base + 15360 + boff + 16 * ROWB + kk * 32);
            #pragma unroll
            for (int mt = 0; mt < 2; mt++)
                #pragma unroll
                for (int ng = 0; ng < 2; ng++)
                    #pragma unroll
                    for (int hh = 0; hh < 2; hh++) {
                        mma_f16(accg[mt][ng * 2 + hh], a[mt], &bg[ng][hh * 2]);
                        mma_f16(accu[mt][ng * 2 + hh], a[mt], &bu[ng][hh * 2]);
                    }
        }
    }

    // epilogue: SwiGLU -> g_act (fp16)
    #pragma unroll
    for (int mt = 0; mt < 2; mt++) {
        #pragma unroll
        for (int nt = 0; nt < 4; nt++) {
            int r0 = moff + wm * 32 + mt * 16 + (lane >> 2);
            int c  = n0 + wn * 32 + nt * 8 + 2 * (lane & 3);
            if (r0 < cnt) {
                __half* dst = g_act + (size_t)(off + r0) * INTER + c;
                float g0 = accg[mt][nt][0], u0 = accu[mt][nt][0];
                float g1 = accg[mt][nt][1], u1 = accu[mt][nt][1];
                *(__half2*)dst = __floats2half2_rn((g0 / (1.f + __expf(-g0))) * u0,
                                                   (g1 / (1.f + __expf(-g1))) * u1);
            }
            int r1 = r0 + 8;
            if (r1 < cnt) {
                __half* dst = g_act + (size_t)(off + r1) * INTER + c;
                float g0 = accg[mt][nt][2], u0 = accu[mt][nt][2];
                float g1 = accg[mt][nt][3], u1 = accu[mt][nt][3];
                *(__half2*)dst = __floats2half2_rn((g0 / (1.f + __expf(-g0))) * u0,
                                                   (g1 / (1.f + __expf(-g1))) * u1);
            }
        }
    }
}

// ---------------------------------------------------------------------------
// K6: GEMM2 (down) + fused weighted combine via atomicAdd.
//     grid.x = M-tile (fastest).
// ---------------------------------------------------------------------------
__global__ void __launch_bounds__(256, 2)
k_ffn2(float* __restrict__ out) {
    extern __shared__ __align__(16) char sm[];
    int e    = blockIdx.z;
    int cnt  = g_counts[e];
    int moff = blockIdx.x * BM;
    if (moff >= cnt) return;
    int off = g_offsets[e];
    int n0  = blockIdx.y * BN;
    int tid = threadIdx.x;

    const char* src[3];
    uint32_t dsto[3];
    #pragma unroll
    for (int t = 0; t < 3; t++) {
        int q = tid + t * 256;
        int row = q >> 2, c16 = q & 3;
        if (row < 128) {
            dsto[t] = (uint32_t)row * ROWB + c16 * 16u;
            int r = moff + row; if (r > cnt - 1) r = cnt - 1;
            src[t] = (const char*)(g_act + (size_t)(off + r) * INTER) + c16 * 16;
        } else {
            int rr = row - 128;
            dsto[t] = 10240u + (uint32_t)rr * ROWB + c16 * 16u;
            src[t] = (const char*)(g_dp_h + (size_t)e * HIDDEN * INTER + (size_t)(n0 + rr) * INTER) + c16 * 16;
        }
    }

    #pragma unroll
    for (int s = 0; s < 2; s++) {
        char* st = sm + s * STG2;
        int adv = s * 64;
        #pragma unroll
        for (int t = 0; t < 3; t++) cp16(st + dsto[t], src[t] + adv);
        cp_commit();
    }

    uint32_t sb = smem_u32(sm);
    int w = tid >> 5, lane = tid & 31;
    int wm = w >> 1, wn = w & 1;
    uint32_t aoff = (uint32_t)(wm * 32 + (lane & 15)) * ROWB + (lane >> 4) * 16u;
    uint32_t boff = (uint32_t)(wn * 32 + (lane & 7) + ((lane >> 4) << 3)) * ROWB
                    + ((lane >> 3) & 1) * 16u;

    float acc[2][4][4];
    #pragma unroll
    for (int mt = 0; mt < 2; mt++)
        #pragma unroll
        for (int nt = 0; nt < 4; nt++)
            #pragma unroll
            for (int q = 0; q < 4; q++) acc[mt][nt][q] = 0.f;

    const int T = INTER / BKH;  // 88
    for (int j = 0; j < T; j++) {
        if (j < T - 1) cp_wait1(); else cp_wait0();
        __syncthreads();
        if (j + 2 < T) {
            char* st = sm + ((j + 2) % 3) * STG2;
            int adv = (j + 2) * 64;
            #pragma unroll
            for (int t = 0; t < 3; t++) cp16(st + dsto[t], src[t] + adv);
            cp_commit();
        }
        uint32_t base = sb + (uint32_t)(j % 3) * STG2;
        #pragma unroll
        for (int kk = 0; kk < 2; kk++) {
            uint32_t a[2][4], bb[2][4];
            ldsm4(a[0], base + aoff + kk * 32);
            ldsm4(a[1], base + aoff + 16 * ROWB + kk * 32);
            ldsm4(bb[0], base + 10240 + boff + kk * 32);
            ldsm4(bb[1], base + 10240 + boff + 16 * ROWB + kk * 32);
            #pragma unroll
            for (int mt = 0; mt < 2; mt++)
                #pragma unroll
                for (int ng = 0; ng < 2; ng++)
                    #pragma unroll
                    for (int hh = 0; hh < 2; hh++)
                        mma_f16(acc[mt][ng * 2 + hh], a[mt], &bb[ng][hh * 2]);
        }
    }

    // epilogue: scatter-accumulate weighted result directly into out
    #pragma unroll
    for (int mt = 0; mt < 2; mt++) {
        int r0 = moff + wm * 32 + mt * 16 + (lane >> 2);
        int r1 = r0 + 8;
        int   t0 = 0, t1 = 0;
        float w0 = 0.f, w1 = 0.f;
        bool ok0 = r0 < cnt, ok1 = r1 < cnt;
        if (ok0) { t0 = g_pair_token[off + r0]; w0 = g_pair_w[off + r0]; }
        if (ok1) { t1 = g_pair_token[off + r1]; w1 = g_pair_w[off + r1]; }
        #pragma unroll
        for (int nt = 0; nt < 4; nt++) {
            int c = n0 + wn * 32 + nt * 8 + 2 * (lane & 3);
            if (ok0) {
                float* dst = out + (size_t)t0 * HIDDEN + c;
                atomicAdd(dst + 0, w0 * acc[mt][nt][0]);
                atomicAdd(dst + 1, w0 * acc[mt][nt][1]);
            }
            if (ok1) {
                float* dst = out + (size_t)t1 * HIDDEN + c;
                atomicAdd(dst + 0, w1 * acc[mt][nt][2]);
                atomicAdd(dst + 1, w1 * acc[mt][nt][3]);
            }
        }
    }
}

// ---------------------------------------------------------------------------
extern "C" void kernel_launch(void* const* d_in, const int* in_sizes, int n_in,
                              void* d_out, int out_size) {
    const float* hs   = (const float*)d_in[0];
    const int*   tid  = (const int*)d_in[1];
    const float* temb = (const float*)d_in[2];
    const float* trw  = (const float*)d_in[3];
    const float* gw   = (const float*)d_in[4];
    const float* gp   = (const float*)d_in[5];
    const float* up   = (const float*)d_in[6];
    const float* dp   = (const float*)d_in[7];
    float* out = (float*)d_out;

    cudaFuncSetAttribute(k_ffn1, cudaFuncAttributeMaxDynamicSharedMemorySize, SMEM1);
    cudaFuncSetAttribute(k_ffn2, cudaFuncAttributeMaxDynamicSharedMemorySize, SMEM2);

    __half* gph; __half* uph; __half* dph;
    cudaGetSymbolAddress((void**)&gph, g_gp_h);
    cudaGetSymbolAddress((void**)&uph, g_up_h);
    cudaGetSymbolAddress((void**)&dph, g_dp_h);

    k_zero<<<1024, 256>>>((float4*)out);
    k_task_route<<<1, 256>>>(temb, tid, trw);

    dim3 gc(440, 3, NE);
    k_cvt3<<<gc, 256>>>((const float4*)gp, (const float4*)up, (const float4*)dp,
                        (uint2*)gph, (uint2*)uph, (uint2*)dph);

    k_gate<<<NTOK / 8, 256>>>(hs, temb, tid, gw);
    k_prefix<<<1, 32>>>();
    k_place<<<NTOK / 256, 256>>>();

    dim3 g1(NTOK / BM, INTER / BN, NE);   // 64 x 44 x 8, M fastest
    k_ffn1<<<g1, 256, SMEM1>>>();
    dim3 g2(NTOK / BM, HIDDEN / BN, NE);  // 64 x 16 x 8, M fastest
    k_ffn2<<<g2, 256, SMEM2>>>(out);
}

// round 10
// speedup vs baseline: 7.1780x; 1.1116x over previous
#include <cuda_runtime.h>
#include <cuda_fp16.h>
#include <math.h>
#include <stdint.h>

#define HIDDEN 1024
#define INTER  2816
#define NE     8
#define TOPK   2
#define NTASKEXP 4
#define NGEN   2
#define NTOK   8192
#define NPAIR  (NTOK*TOPK)
#define WELEM  (NE*INTER*HIDDEN)

#define BM 128
#define BN 64
#define BKH 64            // K halves per stage (128B row)
#define ROWB 144          // row stride bytes (128 data + 16 pad)
#define STG1 36864        // (128+64+64) rows * 144B
#define STG2 27648        // (128+64) rows * 144B
#define SMEM1 (3*STG1)    // 110592 -> 2 blocks/SM (221184 <= 228KB)
#define SMEM2 (3*STG2)    // 82944  -> 2 blocks/SM

// ---- scratch (static device memory; no runtime allocation) ----
__device__ int    g_active[NE];
__device__ int    g_counts[NE];
__device__ int    g_offsets[NE];
__device__ int    g_cursor[NE];
__device__ int    g_pair_token[NPAIR];
__device__ float  g_pair_w[NPAIR];
__device__ int    g_tok_e[NTOK * TOPK];
__device__ float  g_tok_w[NTOK * TOPK];
__device__ __half g_act[(size_t)NPAIR * INTER];
__device__ __half g_hs_h[(size_t)NTOK * HIDDEN];
__device__ __half g_gp_h[(size_t)WELEM];
__device__ __half g_up_h[(size_t)WELEM];
__device__ __half g_dp_h[(size_t)WELEM];

// ---------------------------------------------------------------------------
__device__ __forceinline__ void cp16(void* smem_ptr, const void* gptr) {
    uint32_t s = (uint32_t)__cvta_generic_to_shared(smem_ptr);
    asm volatile("cp.async.cg.shared.global [%0], [%1], 16;\n" :: "r"(s), "l"(gptr));
}
__device__ __forceinline__ void cp_commit() { asm volatile("cp.async.commit_group;\n"); }
__device__ __forceinline__ void cp_wait0()  { asm volatile("cp.async.wait_group 0;\n" ::: "memory"); }
__device__ __forceinline__ void cp_wait1()  { asm volatile("cp.async.wait_group 1;\n" ::: "memory"); }

__device__ __forceinline__ uint32_t smem_u32(const void* p) {
    return (uint32_t)__cvta_generic_to_shared(p);
}
__device__ __forceinline__ void ldsm4(uint32_t* r, uint32_t addr) {
    asm volatile("ldmatrix.sync.aligned.m8n8.x4.shared.b16 {%0,%1,%2,%3}, [%4];"
                 : "=r"(r[0]), "=r"(r[1]), "=r"(r[2]), "=r"(r[3]) : "r"(addr));
}
__device__ __forceinline__ void mma_f16(float* c, const uint32_t* a, const uint32_t* b) {
    asm volatile(
        "mma.sync.aligned.m16n8k16.row.col.f32.f16.f16.f32 "
        "{%0,%1,%2,%3}, {%4,%5,%6,%7}, {%8,%9}, {%0,%1,%2,%3};"
        : "+f"(c[0]), "+f"(c[1]), "+f"(c[2]), "+f"(c[3])
        : "r"(a[0]), "r"(a[1]), "r"(a[2]), "r"(a[3]), "r"(b[0]), "r"(b[1]));
}

// ---------------------------------------------------------------------------
// K0: zero d_out (atomic accumulation target)
// ---------------------------------------------------------------------------
__global__ void k_zero(float4* __restrict__ out) {
    int i = blockIdx.x * blockDim.x + threadIdx.x;
    const int n4 = NTOK * HIDDEN / 4;
    for (; i < n4; i += gridDim.x * blockDim.x)
        out[i] = make_float4(0.f, 0.f, 0.f, 0.f);
}

// ---------------------------------------------------------------------------
// K1: task routing + counter reset
// ---------------------------------------------------------------------------
__global__ void k_task_route(const float* __restrict__ task_emb,
                             const int* __restrict__ task_id_p,
                             const float* __restrict__ trw) {
    __shared__ float sc[NE];
    int tid  = threadIdx.x;
    int e    = tid / 32;
    int lane = tid % 32;
    const float* tv = task_emb + (size_t)task_id_p[0] * HIDDEN;
    float acc = 0.f;
    if (e < NE) {
        for (int d = lane; d < HIDDEN; d += 32)
            acc += trw[(size_t)e * HIDDEN + d] * tv[d];
        #pragma unroll
        for (int o = 16; o > 0; o >>= 1)
            acc += __shfl_xor_sync(0xFFFFFFFFu, acc, o);
        if (lane == 0) sc[e] = acc;
    }
    __syncthreads();
    if (tid == 0) {
        float s[NE]; bool act[NE];
        for (int i = 0; i < NE; i++) { s[i] = sc[i]; act[i] = false; }
        for (int k = 0; k < NTASKEXP; k++) {
            int best = 0; float bv = -1e30f;
            for (int i = 0; i < NE; i++)
                if (!act[i] && s[i] > bv) { bv = s[i]; best = i; }
            act[best] = true;
        }
        for (int i = NE - NGEN; i < NE; i++) act[i] = true;
        for (int i = 0; i < NE; i++) {
            g_active[i] = act[i] ? 1 : 0;
            g_counts[i] = 0;
            g_cursor[i] = 0;
        }
    }
}

// ---------------------------------------------------------------------------
// K2: token gating (exact fp32, float4-vectorized) + fp16 copy of hs
// ---------------------------------------------------------------------------
__global__ void k_gate(const float* __restrict__ hs,
                       const float* __restrict__ task_emb,
                       const int* __restrict__ task_id_p,
                       const float* __restrict__ gw) {
    int warp = (blockIdx.x * blockDim.x + threadIdx.x) / 32;
    int lane = threadIdx.x % 32;
    if (warp >= NTOK) return;
    const float4* tv4 = (const float4*)(task_emb + (size_t)task_id_p[0] * HIDDEN);
    const float4* h4  = (const float4*)(hs + (size_t)warp * HIDDEN);
    const float4* gw4 = (const float4*)gw;
    uint2* ht4 = (uint2*)(g_hs_h + (size_t)warp * HIDDEN);

    float acc[NE];
    #pragma unroll
    for (int e = 0; e < NE; e++) acc[e] = 0.f;

    #pragma unroll 2
    for (int d4 = lane; d4 < HIDDEN / 4; d4 += 32) {
        float4 hv = h4[d4];
        float4 tq = tv4[d4];
        __half2 lo = __floats2half2_rn(hv.x, hv.y);
        __half2 hi = __floats2half2_rn(hv.z, hv.w);
        uint2 o;
        o.x = *(const uint32_t*)&lo;
        o.y = *(const uint32_t*)&hi;
        ht4[d4] = o;
        float x0 = hv.x + tq.x, x1 = hv.y + tq.y, x2 = hv.z + tq.z, x3 = hv.w + tq.w;
        #pragma unroll
        for (int e = 0; e < NE; e++) {
            float4 wv = gw4[e * (HIDDEN / 4) + d4];
            acc[e] += x0 * wv.x + x1 * wv.y + x2 * wv.z + x3 * wv.w;
        }
    }
    #pragma unroll
    for (int e = 0; e < NE; e++) {
        #pragma unroll
        for (int o = 16; o > 0; o >>= 1)
            acc[e] += __shfl_xor_sync(0xFFFFFFFFu, acc[e], o);
    }
    if (lane == 0) {
        float m = -1e30f;
        #pragma unroll
        for (int e = 0; e < NE; e++)
            if (g_active[e] && acc[e] > m) m = acc[e];
        float p[NE]; float Z = 0.f;
        #pragma unroll
        for (int e = 0; e < NE; e++) {
            p[e] = g_active[e] ? expf(acc[e] - m) : 0.f;
            Z += p[e];
        }
        float inv = 1.f / Z;
        int i0 = 0; float v0 = -1.f;
        #pragma unroll
        for (int e = 0; e < NE; e++) {
            float s = p[e] * inv;
            if (s > v0) { v0 = s; i0 = e; }
        }
        int i1 = -1; float v1 = -1.f;
        #pragma unroll
        for (int e = 0; e < NE; e++) {
            if (e == i0) continue;
            float s = p[e] * inv;
            if (s > v1) { v1 = s; i1 = e; }
        }
        float ws = v0 + v1 + 1e-6f;
        g_tok_e[warp * 2 + 0] = i0;
        g_tok_e[warp * 2 + 1] = i1;
        g_tok_w[warp * 2 + 0] = v0 / ws;
        g_tok_w[warp * 2 + 1] = v1 / ws;
        atomicAdd(&g_counts[i0], 1);
        atomicAdd(&g_counts[i1], 1);
    }
}

__global__ void k_prefix() {
    if (threadIdx.x == 0) {
        int o = 0;
        for (int e = 0; e < NE; e++) { g_offsets[e] = o; o += g_counts[e]; }
    }
}

__global__ void k_place() {
    int n = blockIdx.x * blockDim.x + threadIdx.x;
    if (n >= NTOK) return;
    #pragma unroll
    for (int k = 0; k < TOPK; k++) {
        int e = g_tok_e[n * 2 + k];
        int slot = atomicAdd(&g_cursor[e], 1);
        int idx = g_offsets[e] + slot;
        g_pair_token[idx] = n;
        g_pair_w[idx] = g_tok_w[n * 2 + k];
    }
}

// ---------------------------------------------------------------------------
// all-weights fp32 -> fp16 (active experts only)
// ---------------------------------------------------------------------------
__global__ void k_cvt3(const float4* __restrict__ gp, const float4* __restrict__ up,
                       const float4* __restrict__ dp,
                       uint2* __restrict__ gph, uint2* __restrict__ uph,
                       uint2* __restrict__ dph) {
    int e = blockIdx.z;
    if (!g_active[e]) return;
    const int n4 = INTER * HIDDEN / 4;
    const float4* in = (blockIdx.y == 0) ? gp : (blockIdx.y == 1) ? up : dp;
    uint2* out = (blockIdx.y == 0) ? gph : (blockIdx.y == 1) ? uph : dph;
    const float4* src = in + (size_t)e * n4;
    uint2* dst = out + (size_t)e * n4;
    for (int i = blockIdx.x * blockDim.x + threadIdx.x; i < n4; i += gridDim.x * blockDim.x) {
        float4 v = src[i];
        __half2 lo = __floats2half2_rn(v.x, v.y);
        __half2 hi = __floats2half2_rn(v.z, v.w);
        uint2 o;
        o.x = *(const uint32_t*)&lo;
        o.y = *(const uint32_t*)&hi;
        dst[i] = o;
    }
}

// ---------------------------------------------------------------------------
// K5: GEMM1 (gate & up fused) + SwiGLU. BK=64, 3-stage, 2 blocks/SM.
//     grid.x = M-tile (fastest) for weight L2 reuse.
// ---------------------------------------------------------------------------
__global__ void __launch_bounds__(256, 2)
k_ffn1() {
    extern __shared__ __align__(16) char sm[];
    int e    = blockIdx.z;
    int cnt  = g_counts[e];
    int moff = blockIdx.x * BM;
    if (moff >= cnt) return;
    int off = g_offsets[e];
    int n0  = blockIdx.y * BN;
    int tid = threadIdx.x;

    // copy roles: 8 x 16B chunks per thread per stage
    int c16 = tid & 7;          // 0..7 (16B chunk within 128B row)
    int rb  = tid >> 3;         // 0..31
    const char* srcA[4];
    uint32_t dA[4];
    #pragma unroll
    for (int t = 0; t < 4; t++) {
        int row = rb + 32 * t;
        dA[t] = (uint32_t)row * ROWB + c16 * 16u;
        int r = moff + row; if (r > cnt - 1) r = cnt - 1;
        srcA[t] = (const char*)(g_hs_h + (size_t)g_pair_token[off + r] * HIDDEN) + c16 * 16;
    }
    const char* srcG = (const char*)(g_gp_h + (size_t)e * INTER * HIDDEN +
                                     (size_t)(n0 + rb) * HIDDEN) + c16 * 16;
    const char* srcU = (const char*)(g_up_h + (size_t)e * INTER * HIDDEN +
                                     (size_t)(n0 + rb) * HIDDEN) + c16 * 16;
    const uint32_t dG = 18432u + (uint32_t)rb * ROWB + c16 * 16u;
    const uint32_t dU = 27648u + (uint32_t)rb * ROWB + c16 * 16u;
    const size_t BROW32 = (size_t)32 * HIDDEN * 2;

    // prologue: stages 0,1
    #pragma unroll
    for (int s = 0; s < 2; s++) {
        char* st = sm + s * STG1;
        int adv = s * 128;
        #pragma unroll
        for (int t = 0; t < 4; t++) cp16(st + dA[t], srcA[t] + adv);
        cp16(st + dG, srcG + adv); cp16(st + dG + 32 * ROWB, srcG + BROW32 + adv);
        cp16(st + dU, srcU + adv); cp16(st + dU + 32 * ROWB, srcU + BROW32 + adv);
        cp_commit();
    }

    uint32_t sb = smem_u32(sm);
    int w = tid >> 5, lane = tid & 31;
    int wm = w >> 1, wn = w & 1;
    uint32_t aoff = (uint32_t)(wm * 32 + (lane & 15)) * ROWB + (lane >> 4) * 16u;
    uint32_t boff = (uint32_t)(wn * 32 + (lane & 7) + ((lane >> 4) << 3)) * ROWB
                    + ((lane >> 3) & 1) * 16u;

    float accg[2][4][4], accu[2][4][4];
    #pragma unroll
    for (int mt = 0; mt < 2; mt++)
        #pragma unroll
        for (int nt = 0; nt < 4; nt++)
            #pragma unroll
            for (int q = 0; q < 4; q++) { accg[mt][nt][q] = 0.f; accu[mt][nt][q] = 0.f; }

    const int T = HIDDEN / BKH;  // 16
    for (int j = 0; j < T; j++) {
        if (j < T - 1) cp_wait1(); else cp_wait0();
        __syncthreads();
        if (j + 2 < T) {
            char* st = sm + ((j + 2) % 3) * STG1;
            int adv = (j + 2) * 128;
            #pragma unroll
            for (int t = 0; t < 4; t++) cp16(st + dA[t], srcA[t] + adv);
            cp16(st + dG, srcG + adv); cp16(st + dG + 32 * ROWB, srcG + BROW32 + adv);
            cp16(st + dU, srcU + adv); cp16(st + dU + 32 * ROWB, srcU + BROW32 + adv);
            cp_commit();
        }
        uint32_t base = sb + (uint32_t)(j % 3) * STG1;
        #pragma unroll
        for (int kk = 0; kk < 4; kk++) {
            uint32_t a[2][4], bg[2][4], bu[2][4];
            ldsm4(a[0], base + aoff + kk * 32);
            ldsm4(a[1], base + aoff + 16 * ROWB + kk * 32);
            ldsm4(bg[0], base + 18432 + boff + kk * 32);
            ldsm4(bg[1], base + 18432 + boff + 16 * ROWB + kk * 32);
            ldsm4(bu[0], base + 27648 + boff + kk * 32);
            ldsm4(bu[1], base + 27648 + boff + 16 * ROWB + kk * 32);
            #pragma unroll
            for (int mt = 0; mt < 2; mt++)
                #pragma unroll
                for (int ng = 0; ng < 2; ng++)
                    #pragma unroll
                    for (int hh = 0; hh < 2; hh++) {
                        mma_f16(accg[mt][ng * 2 + hh], a[mt], &bg[ng][hh * 2]);
                        mma_f16(accu[mt][ng * 2 + hh], a[mt], &bu[ng][hh * 2]);
                    }
        }
    }

    // epilogue: SwiGLU -> g_act (fp16)
    #pragma unroll
    for (int mt = 0; mt < 2; mt++) {
        #pragma unroll
        for (int nt = 0; nt < 4; nt++) {
            int r0 = moff + wm * 32 + mt * 16 + (lane >> 2);
            int c  = n0 + wn * 32 + nt * 8 + 2 * (lane & 3);
            if (r0 < cnt) {
                __half* dst = g_act + (size_t)(off + r0) * INTER + c;
                float g0 = accg[mt][nt][0], u0 = accu[mt][nt][0];
                float g1 = accg[mt][nt][1], u1 = accu[mt][nt][1];
                *(__half2*)dst = __floats2half2_rn((g0 / (1.f + __expf(-g0))) * u0,
                                                   (g1 / (1.f + __expf(-g1))) * u1);
            }
            int r1 = r0 + 8;
            if (r1 < cnt) {
                __half* dst = g_act + (size_t)(off + r1) * INTER + c;
                float g0 = accg[mt][nt][2], u0 = accu[mt][nt][2];
                float g1 = accg[mt][nt][3], u1 = accu[mt][nt][3];
                *(__half2*)dst = __floats2half2_rn((g0 / (1.f + __expf(-g0))) * u0,
                                                   (g1 / (1.f + __expf(-g1))) * u1);
            }
        }
    }
}

// ---------------------------------------------------------------------------
// K6: GEMM2 (down) + fused weighted combine via atomicAdd.
//     BK=64, 3-stage, 2 blocks/SM. grid.x = M-tile (fastest).
// ---------------------------------------------------------------------------
__global__ void __launch_bounds__(256, 2)
k_ffn2(float* __restrict__ out) {
    extern __shared__ __align__(16) char sm[];
    int e    = blockIdx.z;
    int cnt  = g_counts[e];
    int moff = blockIdx.x * BM;
    if (moff >= cnt) return;
    int off = g_offsets[e];
    int n0  = blockIdx.y * BN;
    int tid = threadIdx.x;

    int c16 = tid & 7;
    int rb  = tid >> 3;
    const char* srcA[4];
    uint32_t dA[4];
    #pragma unroll
    for (int t = 0; t < 4; t++) {
        int row = rb + 32 * t;
        dA[t] = (uint32_t)row * ROWB + c16 * 16u;
        int r = moff + row; if (r > cnt - 1) r = cnt - 1;
        srcA[t] = (const char*)(g_act + (size_t)(off + r) * INTER) + c16 * 16;
    }
    const char* srcB = (const char*)(g_dp_h + (size_t)e * HIDDEN * INTER +
                                     (size_t)(n0 + rb) * INTER) + c16 * 16;
    const uint32_t dB = 18432u + (uint32_t)rb * ROWB + c16 * 16u;
    const size_t BROW32 = (size_t)32 * INTER * 2;

    #pragma unroll
    for (int s = 0; s < 2; s++) {
        char* st = sm + s * STG2;
        int adv = s * 128;
        #pragma unroll
        for (int t = 0; t < 4; t++) cp16(st + dA[t], srcA[t] + adv);
        cp16(st + dB, srcB + adv); cp16(st + dB + 32 * ROWB, srcB + BROW32 + adv);
        cp_commit();
    }

    uint32_t sb = smem_u32(sm);
    int w = tid >> 5, lane = tid & 31;
    int wm = w >> 1, wn = w & 1;
    uint32_t aoff = (uint32_t)(wm * 32 + (lane & 15)) * ROWB + (lane >> 4) * 16u;
    uint32_t boff = (uint32_t)(wn * 32 + (lane & 7) + ((lane >> 4) << 3)) * ROWB
                    + ((lane >> 3) & 1) * 16u;

    float acc[2][4][4];
    #pragma unroll
    for (int mt = 0; mt < 2; mt++)
        #pragma unroll
        for (int nt = 0; nt < 4; nt++)
            #pragma unroll
            for (int q = 0; q < 4; q++) acc[mt][nt][q] = 0.f;

    const int T = INTER / BKH;  // 44
    for (int j = 0; j < T; j++) {
        if (j < T - 1) cp_wait1(); else cp_wait0();
        __syncthreads();
        if (j + 2 < T) {
            char* st = sm + ((j + 2) % 3) * STG2;
            int adv = (j + 2) * 128;
            #pragma unroll
            for (int t = 0; t < 4; t++) cp16(st + dA[t], srcA[t] + adv);
            cp16(st + dB, srcB + adv); cp16(st + dB + 32 * ROWB, srcB + BROW32 + adv);
            cp_commit();
        }
        uint32_t base = sb + (uint32_t)(j % 3) * STG2;
        #pragma unroll
        for (int kk = 0; kk < 4; kk++) {
            uint32_t a[2][4], bb[2][4];
            ldsm4(a[0], base + aoff + kk * 32);
            ldsm4(a[1], base + aoff + 16 * ROWB + kk * 32);
            ldsm4(bb[0], base + 18432 + boff + kk * 32);
            ldsm4(bb[1], base + 18432 + boff + 16 * ROWB + kk * 32);
            #pragma unroll
            for (int mt = 0; mt < 2; mt++)
                #pragma unroll
                for (int ng = 0; ng < 2; ng++)
                    #pragma unroll
                    for (int hh = 0; hh < 2; hh++)
                        mma_f16(acc[mt][ng * 2 + hh], a[mt], &bb[ng][hh * 2]);
        }
    }

    // epilogue: scatter-accumulate weighted result directly into out
    #pragma unroll
    for (int mt = 0; mt < 2; mt++) {
        int r0 = moff + wm * 32 + mt * 16 + (lane >> 2);
        int r1 = r0 + 8;
        int   t0 = 0, t1 = 0;
        float w0 = 0.f, w1 = 0.f;
        bool ok0 = r0 < cnt, ok1 = r1 < cnt;
        if (ok0) { t0 = g_pair_token[off + r0]; w0 = g_pair_w[off + r0]; }
        if (ok1) { t1 = g_pair_token[off + r1]; w1 = g_pair_w[off + r1]; }
        #pragma unroll
        for (int nt = 0; nt < 4; nt++) {
            int c = n0 + wn * 32 + nt * 8 + 2 * (lane & 3);
            if (ok0) {
                float* dst = out + (size_t)t0 * HIDDEN + c;
                atomicAdd(dst + 0, w0 * acc[mt][nt][0]);
                atomicAdd(dst + 1, w0 * acc[mt][nt][1]);
            }
            if (ok1) {
                float* dst = out + (size_t)t1 * HIDDEN + c;
                atomicAdd(dst + 0, w1 * acc[mt][nt][2]);
                atomicAdd(dst + 1, w1 * acc[mt][nt][3]);
            }
        }
    }
}

// ---------------------------------------------------------------------------
extern "C" void kernel_launch(void* const* d_in, const int* in_sizes, int n_in,
                              void* d_out, int out_size) {
    const float* hs   = (const float*)d_in[0];
    const int*   tid  = (const int*)d_in[1];
    const float* temb = (const float*)d_in[2];
    const float* trw  = (const float*)d_in[3];
    const float* gw   = (const float*)d_in[4];
    const float* gp   = (const float*)d_in[5];
    const float* up   = (const float*)d_in[6];
    const float* dp   = (const float*)d_in[7];
    float* out = (float*)d_out;

    cudaFuncSetAttribute(k_ffn1, cudaFuncAttributeMaxDynamicSharedMemorySize, SMEM1);
    cudaFuncSetAttribute(k_ffn2, cudaFuncAttributeMaxDynamicSharedMemorySize, SMEM2);

    __half* gph; __half* uph; __half* dph;
    cudaGetSymbolAddress((void**)&gph, g_gp_h);
    cudaGetSymbolAddress((void**)&uph, g_up_h);
    cudaGetSymbolAddress((void**)&dph, g_dp_h);

    k_zero<<<1024, 256>>>((float4*)out);
    k_task_route<<<1, 256>>>(temb, tid, trw);

    dim3 gc(440, 3, NE);
    k_cvt3<<<gc, 256>>>((const float4*)gp, (const float4*)up, (const float4*)dp,
                        (uint2*)gph, (uint2*)uph, (uint2*)dph);

    k_gate<<<NTOK / 8, 256>>>(hs, temb, tid, gw);
    k_prefix<<<1, 32>>>();
    k_place<<<NTOK / 256, 256>>>();

    dim3 g1(NTOK / BM, INTER / BN, NE);   // 64 x 44 x 8, M fastest
    k_ffn1<<<g1, 256, SMEM1>>>();
    dim3 g2(NTOK / BM, HIDDEN / BN, NE);  // 64 x 16 x 8, M fastest
    k_ffn2<<<g2, 256, SMEM2>>>(out);
}

// round 11
// speedup vs baseline: 7.3023x; 1.0173x over previous
#include <cuda_runtime.h>
#include <cuda_fp16.h>
#include <math.h>
#include <stdint.h>

#define HIDDEN 1024
#define INTER  2816
#define NE     8
#define TOPK   2
#define NTASKEXP 4
#define NGEN   2
#define NTOK   8192
#define NPAIR  (NTOK*TOPK)
#define WELEM  (NE*INTER*HIDDEN)

#define BM 128
#define BN 64
#define BKH 64            // K halves per stage (128B row)
#define ROWB 144          // row stride bytes (128 data + 16 pad)
#define STG1 36864        // (128+64+64) rows * 144B
#define STG2 27648        // (128+64) rows * 144B
#define SMEM1 (3*STG1)    // 110592 -> 2 blocks/SM
#define SMEM2 (3*STG2)    // 82944  -> 2 blocks/SM

// ---- scratch (static device memory; no runtime allocation) ----
__device__ int    g_active[NE];
__device__ int    g_counts[NE];
__device__ int    g_offsets[NE];
__device__ int    g_cursor[NE];
__device__ int    g_pair_token[NPAIR];
__device__ float  g_pair_w[NPAIR];
__device__ int    g_tok_e[NTOK * TOPK];
__device__ float  g_tok_w[NTOK * TOPK];
__device__ __half g_act[(size_t)NPAIR * INTER];
__device__ __half g_hs_h[(size_t)NTOK * HIDDEN];
__device__ __half g_gp_h[(size_t)WELEM];
__device__ __half g_up_h[(size_t)WELEM];
__device__ __half g_dp_h[(size_t)WELEM];

// ---------------------------------------------------------------------------
__device__ __forceinline__ void cp16(void* smem_ptr, const void* gptr) {
    uint32_t s = (uint32_t)__cvta_generic_to_shared(smem_ptr);
    asm volatile("cp.async.cg.shared.global [%0], [%1], 16;\n" :: "r"(s), "l"(gptr));
}
__device__ __forceinline__ void cp_commit() { asm volatile("cp.async.commit_group;\n"); }
__device__ __forceinline__ void cp_wait0()  { asm volatile("cp.async.wait_group 0;\n" ::: "memory"); }
__device__ __forceinline__ void cp_wait1()  { asm volatile("cp.async.wait_group 1;\n" ::: "memory"); }

__device__ __forceinline__ uint32_t smem_u32(const void* p) {
    return (uint32_t)__cvta_generic_to_shared(p);
}
__device__ __forceinline__ void ldsm4(uint32_t* r, uint32_t addr) {
    asm volatile("ldmatrix.sync.aligned.m8n8.x4.shared.b16 {%0,%1,%2,%3}, [%4];"
                 : "=r"(r[0]), "=r"(r[1]), "=r"(r[2]), "=r"(r[3]) : "r"(addr));
}
__device__ __forceinline__ void mma_f16(float* c, const uint32_t* a, const uint32_t* b) {
    asm volatile(
        "mma.sync.aligned.m16n8k16.row.col.f32.f16.f16.f32 "
        "{%0,%1,%2,%3}, {%4,%5,%6,%7}, {%8,%9}, {%0,%1,%2,%3};"
        : "+f"(c[0]), "+f"(c[1]), "+f"(c[2]), "+f"(c[3])
        : "r"(a[0]), "r"(a[1]), "r"(a[2]), "r"(a[3]), "r"(b[0]), "r"(b[1]));
}

// ---------------------------------------------------------------------------
// K1: task routing + counter reset
// ---------------------------------------------------------------------------
__global__ void k_task_route(const float* __restrict__ task_emb,
                             const int* __restrict__ task_id_p,
                             const float* __restrict__ trw) {
    __shared__ float sc[NE];
    int tid  = threadIdx.x;
    int e    = tid / 32;
    int lane = tid % 32;
    const float* tv = task_emb + (size_t)task_id_p[0] * HIDDEN;
    float acc = 0.f;
    if (e < NE) {
        for (int d = lane; d < HIDDEN; d += 32)
            acc += trw[(size_t)e * HIDDEN + d] * tv[d];
        #pragma unroll
        for (int o = 16; o > 0; o >>= 1)
            acc += __shfl_xor_sync(0xFFFFFFFFu, acc, o);
        if (lane == 0) sc[e] = acc;
    }
    __syncthreads();
    if (tid == 0) {
        float s[NE]; bool act[NE];
        for (int i = 0; i < NE; i++) { s[i] = sc[i]; act[i] = false; }
        for (int k = 0; k < NTASKEXP; k++) {
            int best = 0; float bv = -1e30f;
            for (int i = 0; i < NE; i++)
                if (!act[i] && s[i] > bv) { bv = s[i]; best = i; }
            act[best] = true;
        }
        for (int i = NE - NGEN; i < NE; i++) act[i] = true;
        for (int i = 0; i < NE; i++) {
            g_active[i] = act[i] ? 1 : 0;
            g_counts[i] = 0;
            g_cursor[i] = 0;
        }
    }
}

// ---------------------------------------------------------------------------
// K2: token gating (exact fp32, gw cached in smem) + fp16 hs copy + zero out
// ---------------------------------------------------------------------------
__global__ void __launch_bounds__(256)
k_gate(const float* __restrict__ hs,
       const float* __restrict__ task_emb,
       const int* __restrict__ task_id_p,
       const float* __restrict__ gw,
       float* __restrict__ out) {
    __shared__ float4 s_gw[NE * HIDDEN / 4];   // 32 KB
    int tid = threadIdx.x;
    int wid = tid >> 5;
    int lane = tid & 31;
    int token = blockIdx.x * 8 + wid;

    // block-cooperative load of gw into smem (2048 float4)
    #pragma unroll
    for (int t = 0; t < 8; t++)
        s_gw[tid + t * 256] = ((const float4*)gw)[tid + t * 256];

    // zero this token's output row (1024 floats -> 8 float4/lane)
    float4* oz = (float4*)(out + (size_t)token * HIDDEN);
    #pragma unroll
    for (int t = 0; t < 8; t++)
        oz[lane + t * 32] = make_float4(0.f, 0.f, 0.f, 0.f);

    __syncthreads();

    const float4* tv4 = (const float4*)(task_emb + (size_t)task_id_p[0] * HIDDEN);
    const float4* h4  = (const float4*)(hs + (size_t)token * HIDDEN);
    uint2* ht4 = (uint2*)(g_hs_h + (size_t)token * HIDDEN);

    float acc[NE];
    #pragma unroll
    for (int e = 0; e < NE; e++) acc[e] = 0.f;

    #pragma unroll
    for (int it = 0; it < 8; it++) {
        int d4 = lane + it * 32;
        float4 hv = h4[d4];
        float4 tq = tv4[d4];
        __half2 lo = __floats2half2_rn(hv.x, hv.y);
        __half2 hi = __floats2half2_rn(hv.z, hv.w);
        uint2 o;
        o.x = *(const uint32_t*)&lo;
        o.y = *(const uint32_t*)&hi;
        ht4[d4] = o;
        float x0 = hv.x + tq.x, x1 = hv.y + tq.y, x2 = hv.z + tq.z, x3 = hv.w + tq.w;
        #pragma unroll
        for (int e = 0; e < NE; e++) {
            float4 wv = s_gw[e * (HIDDEN / 4) + d4];
            acc[e] += x0 * wv.x + x1 * wv.y + x2 * wv.z + x3 * wv.w;
        }
    }
    #pragma unroll
    for (int e = 0; e < NE; e++) {
        #pragma unroll
        for (int o = 16; o > 0; o >>= 1)
            acc[e] += __shfl_xor_sync(0xFFFFFFFFu, acc[e], o);
    }
    if (lane == 0) {
        float m = -1e30f;
        #pragma unroll
        for (int e = 0; e < NE; e++)
            if (g_active[e] && acc[e] > m) m = acc[e];
        float p[NE]; float Z = 0.f;
        #pragma unroll
        for (int e = 0; e < NE; e++) {
            p[e] = g_active[e] ? expf(acc[e] - m) : 0.f;
            Z += p[e];
        }
        float inv = 1.f / Z;
        int i0 = 0; float v0 = -1.f;
        #pragma unroll
        for (int e = 0; e < NE; e++) {
            float s = p[e] * inv;
            if (s > v0) { v0 = s; i0 = e; }
        }
        int i1 = -1; float v1 = -1.f;
        #pragma unroll
        for (int e = 0; e < NE; e++) {
            if (e == i0) continue;
            float s = p[e] * inv;
            if (s > v1) { v1 = s; i1 = e; }
        }
        float ws = v0 + v1 + 1e-6f;
        g_tok_e[token * 2 + 0] = i0;
        g_tok_e[token * 2 + 1] = i1;
        g_tok_w[token * 2 + 0] = v0 / ws;
        g_tok_w[token * 2 + 1] = v1 / ws;
        atomicAdd(&g_counts[i0], 1);
        atomicAdd(&g_counts[i1], 1);
    }
}

__global__ void k_prefix() {
    if (threadIdx.x == 0) {
        int o = 0;
        for (int e = 0; e < NE; e++) { g_offsets[e] = o; o += g_counts[e]; }
    }
}

__global__ void k_place() {
    int n = blockIdx.x * blockDim.x + threadIdx.x;
    if (n >= NTOK) return;
    #pragma unroll
    for (int k = 0; k < TOPK; k++) {
        int e = g_tok_e[n * 2 + k];
        int slot = atomicAdd(&g_cursor[e], 1);
        int idx = g_offsets[e] + slot;
        g_pair_token[idx] = n;
        g_pair_w[idx] = g_tok_w[n * 2 + k];
    }
}

// ---------------------------------------------------------------------------
// all-weights fp32 -> fp16 (active experts only), 16B stores
// ---------------------------------------------------------------------------
__global__ void k_cvt3(const float4* __restrict__ gp, const float4* __restrict__ up,
                       const float4* __restrict__ dp,
                       uint4* __restrict__ gph, uint4* __restrict__ uph,
                       uint4* __restrict__ dph) {
    int e = blockIdx.z;
    if (!g_active[e]) return;
    const int n8 = INTER * HIDDEN / 8;
    const float4* in = (blockIdx.y == 0) ? gp : (blockIdx.y == 1) ? up : dp;
    uint4* out = (blockIdx.y == 0) ? gph : (blockIdx.y == 1) ? uph : dph;
    const float4* src = in + (size_t)e * n8 * 2;
    uint4* dst = out + (size_t)e * n8;
    for (int i = blockIdx.x * blockDim.x + threadIdx.x; i < n8; i += gridDim.x * blockDim.x) {
        float4 v0 = src[i * 2 + 0];
        float4 v1 = src[i * 2 + 1];
        __half2 a = __floats2half2_rn(v0.x, v0.y);
        __half2 b = __floats2half2_rn(v0.z, v0.w);
        __half2 c = __floats2half2_rn(v1.x, v1.y);
        __half2 d = __floats2half2_rn(v1.z, v1.w);
        uint4 o;
        o.x = *(const uint32_t*)&a;
        o.y = *(const uint32_t*)&b;
        o.z = *(const uint32_t*)&c;
        o.w = *(const uint32_t*)&d;
        dst[i] = o;
    }
}

// ---------------------------------------------------------------------------
// K5: GEMM1 (gate & up fused) + SwiGLU. BK=64, 3-stage, 2 blocks/SM.
// ---------------------------------------------------------------------------
__global__ void __launch_bounds__(256, 2)
k_ffn1() {
    extern __shared__ __align__(16) char sm[];
    int e    = blockIdx.z;
    int cnt  = g_counts[e];
    int moff = blockIdx.x * BM;
    if (moff >= cnt) return;
    int off = g_offsets[e];
    int n0  = blockIdx.y * BN;
    int tid = threadIdx.x;

    int c16 = tid & 7;
    int rb  = tid >> 3;
    const char* srcA[4];
    uint32_t dA[4];
    #pragma unroll
    for (int t = 0; t < 4; t++) {
        int row = rb + 32 * t;
        dA[t] = (uint32_t)row * ROWB + c16 * 16u;
        int r = moff + row; if (r > cnt - 1) r = cnt - 1;
        srcA[t] = (const char*)(g_hs_h + (size_t)g_pair_token[off + r] * HIDDEN) + c16 * 16;
    }
    const char* srcG = (const char*)(g_gp_h + (size_t)e * INTER * HIDDEN +
                                     (size_t)(n0 + rb) * HIDDEN) + c16 * 16;
    const char* srcU = (const char*)(g_up_h + (size_t)e * INTER * HIDDEN +
                                     (size_t)(n0 + rb) * HIDDEN) + c16 * 16;
    const uint32_t dG = 18432u + (uint32_t)rb * ROWB + c16 * 16u;
    const uint32_t dU = 27648u + (uint32_t)rb * ROWB + c16 * 16u;
    const size_t BROW32 = (size_t)32 * HIDDEN * 2;

    #pragma unroll
    for (int s = 0; s < 2; s++) {
        char* st = sm + s * STG1;
        int adv = s * 128;
        #pragma unroll
        for (int t = 0; t < 4; t++) cp16(st + dA[t], srcA[t] + adv);
        cp16(st + dG, srcG + adv); cp16(st + dG + 32 * ROWB, srcG + BROW32 + adv);
        cp16(st + dU, srcU + adv); cp16(st + dU + 32 * ROWB, srcU + BROW32 + adv);
        cp_commit();
    }

    uint32_t sb = smem_u32(sm);
    int w = tid >> 5, lane = tid & 31;
    int wm = w >> 1, wn = w & 1;
    uint32_t aoff = (uint32_t)(wm * 32 + (lane & 15)) * ROWB + (lane >> 4) * 16u;
    uint32_t boff = (uint32_t)(wn * 32 + (lane & 7) + ((lane >> 4) << 3)) * ROWB
                    + ((lane >> 3) & 1) * 16u;

    float accg[2][4][4], accu[2][4][4];
    #pragma unroll
    for (int mt = 0; mt < 2; mt++)
        #pragma unroll
        for (int nt = 0; nt < 4; nt++)
            #pragma unroll
            for (int q = 0; q < 4; q++) { accg[mt][nt][q] = 0.f; accu[mt][nt][q] = 0.f; }

    const int T = HIDDEN / BKH;  // 16
    for (int j = 0; j < T; j++) {
        if (j < T - 1) cp_wait1(); else cp_wait0();
        __syncthreads();
        if (j + 2 < T) {
            char* st = sm + ((j + 2) % 3) * STG1;
            int adv = (j + 2) * 128;
            #pragma unroll
            for (int t = 0; t < 4; t++) cp16(st + dA[t], srcA[t] + adv);
            cp16(st + dG, srcG + adv); cp16(st + dG + 32 * ROWB, srcG + BROW32 + adv);
            cp16(st + dU, srcU + adv); cp16(st + dU + 32 * ROWB, srcU + BROW32 + adv);
            cp_commit();
        }
        uint32_t base = sb + (uint32_t)(j % 3) * STG1;
        #pragma unroll
        for (int kk = 0; kk < 4; kk++) {
            uint32_t a[2][4], bg[2][4], bu[2][4];
            ldsm4(a[0], base + aoff + kk * 32);
            ldsm4(a[1], base + aoff + 16 * ROWB + kk * 32);
            ldsm4(bg[0], base + 18432 + boff + kk * 32);
            ldsm4(bg[1], base + 18432 + boff + 16 * ROWB + kk * 32);
            ldsm4(bu[0], base + 27648 + boff + kk * 32);
            ldsm4(bu[1], base + 27648 + boff + 16 * ROWB + kk * 32);
            #pragma unroll
            for (int mt = 0; mt < 2; mt++)
                #pragma unroll
                for (int ng = 0; ng < 2; ng++)
                    #pragma unroll
                    for (int hh = 0; hh < 2; hh++) {
                        mma_f16(accg[mt][ng * 2 + hh], a[mt], &bg[ng][hh * 2]);
                        mma_f16(accu[mt][ng * 2 + hh], a[mt], &bu[ng][hh * 2]);
                    }
        }
    }

    #pragma unroll
    for (int mt = 0; mt < 2; mt++) {
        #pragma unroll
        for (int nt = 0; nt < 4; nt++) {
            int r0 = moff + wm * 32 + mt * 16 + (lane >> 2);
            int c  = n0 + wn * 32 + nt * 8 + 2 * (lane & 3);
            if (r0 < cnt) {
                __half* dst = g_act + (size_t)(off + r0) * INTER + c;
                float g0 = accg[mt][nt][0], u0 = accu[mt][nt][0];
                float g1 = accg[mt][nt][1], u1 = accu[mt][nt][1];
                *(__half2*)dst = __floats2half2_rn((g0 / (1.f + __expf(-g0))) * u0,
                                                   (g1 / (1.f + __expf(-g1))) * u1);
            }
            int r1 = r0 + 8;
            if (r1 < cnt) {
                __half* dst = g_act + (size_t)(off + r1) * INTER + c;
                float g0 = accg[mt][nt][2], u0 = accu[mt][nt][2];
                float g1 = accg[mt][nt][3], u1 = accu[mt][nt][3];
                *(__half2*)dst = __floats2half2_rn((g0 / (1.f + __expf(-g0))) * u0,
                                                   (g1 / (1.f + __expf(-g1))) * u1);
            }
        }
    }
}

// ---------------------------------------------------------------------------
// K6: GEMM2 (down) + fused weighted combine via atomicAdd.
// ---------------------------------------------------------------------------
__global__ void __launch_bounds__(256, 2)
k_ffn2(float* __restrict__ out) {
    extern __shared__ __align__(16) char sm[];
    int e    = blockIdx.z;
    int cnt  = g_counts[e];
    int moff = blockIdx.x * BM;
    if (moff >= cnt) return;
    int off = g_offsets[e];
    int n0  = blockIdx.y * BN;
    int tid = threadIdx.x;

    int c16 = tid & 7;
    int rb  = tid >> 3;
    const char* srcA[4];
    uint32_t dA[4];
    #pragma unroll
    for (int t = 0; t < 4; t++) {
        int row = rb + 32 * t;
        dA[t] = (uint32_t)row * ROWB + c16 * 16u;
        int r = moff + row; if (r > cnt - 1) r = cnt - 1;
        srcA[t] = (const char*)(g_act + (size_t)(off + r) * INTER) + c16 * 16;
    }
    const char* srcB = (const char*)(g_dp_h + (size_t)e * HIDDEN * INTER +
                                     (size_t)(n0 + rb) * INTER) + c16 * 16;
    const uint32_t dB = 18432u + (uint32_t)rb * ROWB + c16 * 16u;
    const size_t BROW32 = (size_t)32 * INTER * 2;

    #pragma unroll
    for (int s = 0; s < 2; s++) {
        char* st = sm + s * STG2;
        int adv = s * 128;
        #pragma unroll
        for (int t = 0; t < 4; t++) cp16(st + dA[t], srcA[t] + adv);
        cp16(st + dB, srcB + adv); cp16(st + dB + 32 * ROWB, srcB + BROW32 + adv);
        cp_commit();
    }

    uint32_t sb = smem_u32(sm);
    int w = tid >> 5, lane = tid & 31;
    int wm = w >> 1, wn = w & 1;
    uint32_t aoff = (uint32_t)(wm * 32 + (lane & 15)) * ROWB + (lane >> 4) * 16u;
    uint32_t boff = (uint32_t)(wn * 32 + (lane & 7) + ((lane >> 4) << 3)) * ROWB
                    + ((lane >> 3) & 1) * 16u;

    float acc[2][4][4];
    #pragma unroll
    for (int mt = 0; mt < 2; mt++)
        #pragma unroll
        for (int nt = 0; nt < 4; nt++)
            #pragma unroll
            for (int q = 0; q < 4; q++) acc[mt][nt][q] = 0.f;

    const int T = INTER / BKH;  // 44
    for (int j = 0; j < T; j++) {
        if (j < T - 1) cp_wait1(); else cp_wait0();
        __syncthreads();
        if (j + 2 < T) {
            char* st = sm + ((j + 2) % 3) * STG2;
            int adv = (j + 2) * 128;
            #pragma unroll
            for (int t = 0; t < 4; t++) cp16(st + dA[t], srcA[t] + adv);
            cp16(st + dB, srcB + adv); cp16(st + dB + 32 * ROWB, srcB + BROW32 + adv);
            cp_commit();
        }
        uint32_t base = sb + (uint32_t)(j % 3) * STG2;
        #pragma unroll
        for (int kk = 0; kk < 4; kk++) {
            uint32_t a[2][4], bb[2][4];
            ldsm4(a[0], base + aoff + kk * 32);
            ldsm4(a[1], base + aoff + 16 * ROWB + kk * 32);
            ldsm4(bb[0], base + 18432 + boff + kk * 32);
            ldsm4(bb[1], base + 18432 + boff + 16 * ROWB + kk * 32);
            #pragma unroll
            for (int mt = 0; mt < 2; mt++)
                #pragma unroll
                for (int ng = 0; ng < 2; ng++)
                    #pragma unroll
                    for (int hh = 0; hh < 2; hh++)
                        mma_f16(acc[mt][ng * 2 + hh], a[mt], &bb[ng][hh * 2]);
        }
    }

    #pragma unroll
    for (int mt = 0; mt < 2; mt++) {
        int r0 = moff + wm * 32 + mt * 16 + (lane >> 2);
        int r1 = r0 + 8;
        int   t0 = 0, t1 = 0;
        float w0 = 0.f, w1 = 0.f;
        bool ok0 = r0 < cnt, ok1 = r1 < cnt;
        if (ok0) { t0 = g_pair_token[off + r0]; w0 = g_pair_w[off + r0]; }
        if (ok1) { t1 = g_pair_token[off + r1]; w1 = g_pair_w[off + r1]; }
        #pragma unroll
        for (int nt = 0; nt < 4; nt++) {
            int c = n0 + wn * 32 + nt * 8 + 2 * (lane & 3);
            if (ok0) {
                float* dst = out + (size_t)t0 * HIDDEN + c;
                atomicAdd(dst + 0, w0 * acc[mt][nt][0]);
                atomicAdd(dst + 1, w0 * acc[mt][nt][1]);
            }
            if (ok1) {
                float* dst = out + (size_t)t1 * HIDDEN + c;
                atomicAdd(dst + 0, w1 * acc[mt][nt][2]);
                atomicAdd(dst + 1, w1 * acc[mt][nt][3]);
            }
        }
    }
}

// ---------------------------------------------------------------------------
extern "C" void kernel_launch(void* const* d_in, const int* in_sizes, int n_in,
                              void* d_out, int out_size) {
    const float* hs   = (const float*)d_in[0];
    const int*   tid  = (const int*)d_in[1];
    const float* temb = (const float*)d_in[2];
    const float* trw  = (const float*)d_in[3];
    const float* gw   = (const float*)d_in[4];
    const float* gp   = (const float*)d_in[5];
    const float* up   = (const float*)d_in[6];
    const float* dp   = (const float*)d_in[7];
    float* out = (float*)d_out;

    cudaFuncSetAttribute(k_ffn1, cudaFuncAttributeMaxDynamicSharedMemorySize, SMEM1);
    cudaFuncSetAttribute(k_ffn2, cudaFuncAttributeMaxDynamicSharedMemorySize, SMEM2);

    __half* gph; __half* uph; __half* dph;
    cudaGetSymbolAddress((void**)&gph, g_gp_h);
    cudaGetSymbolAddress((void**)&uph, g_up_h);
    cudaGetSymbolAddress((void**)&dph, g_dp_h);

    k_task_route<<<1, 256>>>(temb, tid, trw);

    dim3 gc(440, 3, NE);
    k_cvt3<<<gc, 256>>>((const float4*)gp, (const float4*)up, (const float4*)dp,
                        (uint4*)gph, (uint4*)uph, (uint4*)dph);

    k_gate<<<NTOK / 8, 256>>>(hs, temb, tid, gw, out);
    k_prefix<<<1, 32>>>();
    k_place<<<NTOK / 256, 256>>>();

    dim3 g1(NTOK / BM, INTER / BN, NE);   // 64 x 44 x 8, M fastest
    k_ffn1<<<g1, 256, SMEM1>>>();
    dim3 g2(NTOK / BM, HIDDEN / BN, NE);  // 64 x 16 x 8, M fastest
    k_ffn2<<<g2, 256, SMEM2>>>(out);
}

// round 12
// speedup vs baseline: 7.3795x; 1.0106x over previous
#include <cuda_runtime.h>
#include <cuda_fp16.h>
#include <math.h>
#include <stdint.h>

#define HIDDEN 1024
#define INTER  2816
#define NE     8
#define TOPK   2
#define NTASKEXP 4
#define NGEN   2
#define NTOK   8192
#define NPAIR  (NTOK*TOPK)
#define WELEM  (NE*INTER*HIDDEN)

#define BM 128
#define BN 64
#define BKH 64            // K halves per stage (128B row)
#define ROWB 144          // row stride bytes (128 data + 16 pad)
#define STG1 36864        // (128+64+64) rows * 144B
#define STG2 27648        // (128+64) rows * 144B
#define SMEM1 (3*STG1)    // 110592 -> 2 blocks/SM
#define SMEM2 (3*STG2)    // 82944  -> 2 blocks/SM

// ---- scratch (static device memory; no runtime allocation) ----
__device__ int    g_active[NE];
__device__ int    g_counts[NE];
__device__ int    g_offsets[NE];
__device__ int    g_cursor[NE];
__device__ int    g_pair_token[NPAIR];
__device__ float  g_pair_w[NPAIR];
__device__ int    g_tok_e[NTOK * TOPK];
__device__ float  g_tok_w[NTOK * TOPK];
__device__ __half g_act[(size_t)NPAIR * INTER];
__device__ __half g_hs_h[(size_t)NTOK * HIDDEN];
__device__ __half g_gp_h[(size_t)WELEM];
__device__ __half g_up_h[(size_t)WELEM];
__device__ __half g_dp_h[(size_t)WELEM];

// ---- streams/events (created once at static init; no device memory) ----
static cudaStream_t s_cvt, s_exp[4];
static cudaEvent_t  ev_route, ev_cvt, ev_prep, ev_done[4];
namespace {
struct StreamInit {
    StreamInit() {
        cudaStreamCreateWithFlags(&s_cvt, cudaStreamNonBlocking);
        for (int i = 0; i < 4; i++)
            cudaStreamCreateWithFlags(&s_exp[i], cudaStreamNonBlocking);
        cudaEventCreateWithFlags(&ev_route, cudaEventDisableTiming);
        cudaEventCreateWithFlags(&ev_cvt,   cudaEventDisableTiming);
        cudaEventCreateWithFlags(&ev_prep,  cudaEventDisableTiming);
        for (int i = 0; i < 4; i++)
            cudaEventCreateWithFlags(&ev_done[i], cudaEventDisableTiming);
    }
};
static StreamInit s_stream_init;
}

// ---------------------------------------------------------------------------
__device__ __forceinline__ void cp16(void* smem_ptr, const void* gptr) {
    uint32_t s = (uint32_t)__cvta_generic_to_shared(smem_ptr);
    asm volatile("cp.async.cg.shared.global [%0], [%1], 16;\n" :: "r"(s), "l"(gptr));
}
__device__ __forceinline__ void cp_commit() { asm volatile("cp.async.commit_group;\n"); }
__device__ __forceinline__ void cp_wait0()  { asm volatile("cp.async.wait_group 0;\n" ::: "memory"); }
__device__ __forceinline__ void cp_wait1()  { asm volatile("cp.async.wait_group 1;\n" ::: "memory"); }

__device__ __forceinline__ uint32_t smem_u32(const void* p) {
    return (uint32_t)__cvta_generic_to_shared(p);
}
__device__ __forceinline__ void ldsm4(uint32_t* r, uint32_t addr) {
    asm volatile("ldmatrix.sync.aligned.m8n8.x4.shared.b16 {%0,%1,%2,%3}, [%4];"
                 : "=r"(r[0]), "=r"(r[1]), "=r"(r[2]), "=r"(r[3]) : "r"(addr));
}
__device__ __forceinline__ void mma_f16(float* c, const uint32_t* a, const uint32_t* b) {
    asm volatile(
        "mma.sync.aligned.m16n8k16.row.col.f32.f16.f16.f32 "
        "{%0,%1,%2,%3}, {%4,%5,%6,%7}, {%8,%9}, {%0,%1,%2,%3};"
        : "+f"(c[0]), "+f"(c[1]), "+f"(c[2]), "+f"(c[3])
        : "r"(a[0]), "r"(a[1]), "r"(a[2]), "r"(a[3]), "r"(b[0]), "r"(b[1]));
}

// ---------------------------------------------------------------------------
// K1: task routing + counter reset
// ---------------------------------------------------------------------------
__global__ void k_task_route(const float* __restrict__ task_emb,
                             const int* __restrict__ task_id_p,
                             const float* __restrict__ trw) {
    __shared__ float sc[NE];
    int tid  = threadIdx.x;
    int e    = tid / 32;
    int lane = tid % 32;
    const float* tv = task_emb + (size_t)task_id_p[0] * HIDDEN;
    float acc = 0.f;
    if (e < NE) {
        for (int d = lane; d < HIDDEN; d += 32)
            acc += trw[(size_t)e * HIDDEN + d] * tv[d];
        #pragma unroll
        for (int o = 16; o > 0; o >>= 1)
            acc += __shfl_xor_sync(0xFFFFFFFFu, acc, o);
        if (lane == 0) sc[e] = acc;
    }
    __syncthreads();
    if (tid == 0) {
        float s[NE]; bool act[NE];
        for (int i = 0; i < NE; i++) { s[i] = sc[i]; act[i] = false; }
        for (int k = 0; k < NTASKEXP; k++) {
            int best = 0; float bv = -1e30f;
            for (int i = 0; i < NE; i++)
                if (!act[i] && s[i] > bv) { bv = s[i]; best = i; }
            act[best] = true;
        }
        for (int i = NE - NGEN; i < NE; i++) act[i] = true;
        for (int i = 0; i < NE; i++) {
            g_active[i] = act[i] ? 1 : 0;
            g_counts[i] = 0;
            g_cursor[i] = 0;
        }
    }
}

// ---------------------------------------------------------------------------
// K2: token gating (exact fp32, gw cached in smem) + fp16 hs copy + zero out
// ---------------------------------------------------------------------------
__global__ void __launch_bounds__(256)
k_gate(const float* __restrict__ hs,
       const float* __restrict__ task_emb,
       const int* __restrict__ task_id_p,
       const float* __restrict__ gw,
       float* __restrict__ out) {
    __shared__ float4 s_gw[NE * HIDDEN / 4];   // 32 KB
    int tid = threadIdx.x;
    int wid = tid >> 5;
    int lane = tid & 31;
    int token = blockIdx.x * 8 + wid;

    #pragma unroll
    for (int t = 0; t < 8; t++)
        s_gw[tid + t * 256] = ((const float4*)gw)[tid + t * 256];

    float4* oz = (float4*)(out + (size_t)token * HIDDEN);
    #pragma unroll
    for (int t = 0; t < 8; t++)
        oz[lane + t * 32] = make_float4(0.f, 0.f, 0.f, 0.f);

    __syncthreads();

    const float4* tv4 = (const float4*)(task_emb + (size_t)task_id_p[0] * HIDDEN);
    const float4* h4  = (const float4*)(hs + (size_t)token * HIDDEN);
    uint2* ht4 = (uint2*)(g_hs_h + (size_t)token * HIDDEN);

    float acc[NE];
    #pragma unroll
    for (int e = 0; e < NE; e++) acc[e] = 0.f;

    #pragma unroll
    for (int it = 0; it < 8; it++) {
        int d4 = lane + it * 32;
        float4 hv = h4[d4];
        float4 tq = tv4[d4];
        __half2 lo = __floats2half2_rn(hv.x, hv.y);
        __half2 hi = __floats2half2_rn(hv.z, hv.w);
        uint2 o;
        o.x = *(const uint32_t*)&lo;
        o.y = *(const uint32_t*)&hi;
        ht4[d4] = o;
        float x0 = hv.x + tq.x, x1 = hv.y + tq.y, x2 = hv.z + tq.z, x3 = hv.w + tq.w;
        #pragma unroll
        for (int e = 0; e < NE; e++) {
            float4 wv = s_gw[e * (HIDDEN / 4) + d4];
            acc[e] += x0 * wv.x + x1 * wv.y + x2 * wv.z + x3 * wv.w;
        }
    }
    #pragma unroll
    for (int e = 0; e < NE; e++) {
        #pragma unroll
        for (int o = 16; o > 0; o >>= 1)
            acc[e] += __shfl_xor_sync(0xFFFFFFFFu, acc[e], o);
    }
    if (lane == 0) {
        float m = -1e30f;
        #pragma unroll
        for (int e = 0; e < NE; e++)
            if (g_active[e] && acc[e] > m) m = acc[e];
        float p[NE]; float Z = 0.f;
        #pragma unroll
        for (int e = 0; e < NE; e++) {
            p[e] = g_active[e] ? expf(acc[e] - m) : 0.f;
            Z += p[e];
        }
        float inv = 1.f / Z;
        int i0 = 0; float v0 = -1.f;
        #pragma unroll
        for (int e = 0; e < NE; e++) {
            float s = p[e] * inv;
            if (s > v0) { v0 = s; i0 = e; }
        }
        int i1 = -1; float v1 = -1.f;
        #pragma unroll
        for (int e = 0; e < NE; e++) {
            if (e == i0) continue;
            float s = p[e] * inv;
            if (s > v1) { v1 = s; i1 = e; }
        }
        float ws = v0 + v1 + 1e-6f;
        g_tok_e[token * 2 + 0] = i0;
        g_tok_e[token * 2 + 1] = i1;
        g_tok_w[token * 2 + 0] = v0 / ws;
        g_tok_w[token * 2 + 1] = v1 / ws;
        atomicAdd(&g_counts[i0], 1);
        atomicAdd(&g_counts[i1], 1);
    }
}

__global__ void k_prefix() {
    if (threadIdx.x == 0) {
        int o = 0;
        for (int e = 0; e < NE; e++) { g_offsets[e] = o; o += g_counts[e]; }
    }
}

__global__ void k_place() {
    int n = blockIdx.x * blockDim.x + threadIdx.x;
    if (n >= NTOK) return;
    #pragma unroll
    for (int k = 0; k < TOPK; k++) {
        int e = g_tok_e[n * 2 + k];
        int slot = atomicAdd(&g_cursor[e], 1);
        int idx = g_offsets[e] + slot;
        g_pair_token[idx] = n;
        g_pair_w[idx] = g_tok_w[n * 2 + k];
    }
}

// ---------------------------------------------------------------------------
// all-weights fp32 -> fp16 (active experts only), 16B stores
// ---------------------------------------------------------------------------
__global__ void k_cvt3(const float4* __restrict__ gp, const float4* __restrict__ up,
                       const float4* __restrict__ dp,
                       uint4* __restrict__ gph, uint4* __restrict__ uph,
                       uint4* __restrict__ dph) {
    int e = blockIdx.z;
    if (!g_active[e]) return;
    const int n8 = INTER * HIDDEN / 8;
    const float4* in = (blockIdx.y == 0) ? gp : (blockIdx.y == 1) ? up : dp;
    uint4* out = (blockIdx.y == 0) ? gph : (blockIdx.y == 1) ? uph : dph;
    const float4* src = in + (size_t)e * n8 * 2;
    uint4* dst = out + (size_t)e * n8;
    for (int i = blockIdx.x * blockDim.x + threadIdx.x; i < n8; i += gridDim.x * blockDim.x) {
        float4 v0 = src[i * 2 + 0];
        float4 v1 = src[i * 2 + 1];
        __half2 a = __floats2half2_rn(v0.x, v0.y);
        __half2 b = __floats2half2_rn(v0.z, v0.w);
        __half2 c = __floats2half2_rn(v1.x, v1.y);
        __half2 d = __floats2half2_rn(v1.z, v1.w);
        uint4 o;
        o.x = *(const uint32_t*)&a;
        o.y = *(const uint32_t*)&b;
        o.z = *(const uint32_t*)&c;
        o.w = *(const uint32_t*)&d;
        dst[i] = o;
    }
}

// ---------------------------------------------------------------------------
// K5: GEMM1 (gate & up fused) + SwiGLU. BK=64, 3-stage, 2 blocks/SM.
//     Per-expert launch: expert index passed as arg.
// ---------------------------------------------------------------------------
__global__ void __launch_bounds__(256, 2)
k_ffn1(int e) {
    extern __shared__ __align__(16) char sm[];
    int cnt  = g_counts[e];
    int moff = blockIdx.x * BM;
    if (moff >= cnt) return;
    int off = g_offsets[e];
    int n0  = blockIdx.y * BN;
    int tid = threadIdx.x;

    int c16 = tid & 7;
    int rb  = tid >> 3;
    const char* srcA[4];
    uint32_t dA[4];
    #pragma unroll
    for (int t = 0; t < 4; t++) {
        int row = rb + 32 * t;
        dA[t] = (uint32_t)row * ROWB + c16 * 16u;
        int r = moff + row; if (r > cnt - 1) r = cnt - 1;
        srcA[t] = (const char*)(g_hs_h + (size_t)g_pair_token[off + r] * HIDDEN) + c16 * 16;
    }
    const char* srcG = (const char*)(g_gp_h + (size_t)e * INTER * HIDDEN +
                                     (size_t)(n0 + rb) * HIDDEN) + c16 * 16;
    const char* srcU = (const char*)(g_up_h + (size_t)e * INTER * HIDDEN +
                                     (size_t)(n0 + rb) * HIDDEN) + c16 * 16;
    const uint32_t dG = 18432u + (uint32_t)rb * ROWB + c16 * 16u;
    const uint32_t dU = 27648u + (uint32_t)rb * ROWB + c16 * 16u;
    const size_t BROW32 = (size_t)32 * HIDDEN * 2;

    #pragma unroll
    for (int s = 0; s < 2; s++) {
        char* st = sm + s * STG1;
        int adv = s * 128;
        #pragma unroll
        for (int t = 0; t < 4; t++) cp16(st + dA[t], srcA[t] + adv);
        cp16(st + dG, srcG + adv); cp16(st + dG + 32 * ROWB, srcG + BROW32 + adv);
        cp16(st + dU, srcU + adv); cp16(st + dU + 32 * ROWB, srcU + BROW32 + adv);
        cp_commit();
    }

    uint32_t sb = smem_u32(sm);
    int w = tid >> 5, lane = tid & 31;
    int wm = w >> 1, wn = w & 1;
    uint32_t aoff = (uint32_t)(wm * 32 + (lane & 15)) * ROWB + (lane >> 4) * 16u;
    uint32_t boff = (uint32_t)(wn * 32 + (lane & 7) + ((lane >> 4) << 3)) * ROWB
                    + ((lane >> 3) & 1) * 16u;

    float accg[2][4][4], accu[2][4][4];
    #pragma unroll
    for (int mt = 0; mt < 2; mt++)
        #pragma unroll
        for (int nt = 0; nt < 4; nt++)
            #pragma unroll
            for (int q = 0; q < 4; q++) { accg[mt][nt][q] = 0.f; accu[mt][nt][q] = 0.f; }

    const int T = HIDDEN / BKH;  // 16
    for (int j = 0; j < T; j++) {
        if (j < T - 1) cp_wait1(); else cp_wait0();
        __syncthreads();
        if (j + 2 < T) {
            char* st = sm + ((j + 2) % 3) * STG1;
            int adv = (j + 2) * 128;
            #pragma unroll
            for (int t = 0; t < 4; t++) cp16(st + dA[t], srcA[t] + adv);
            cp16(st + dG, srcG + adv); cp16(st + dG + 32 * ROWB, srcG + BROW32 + adv);
            cp16(st + dU, srcU + adv); cp16(st + dU + 32 * ROWB, srcU + BROW32 + adv);
            cp_commit();
        }
        uint32_t base = sb + (uint32_t)(j % 3) * STG1;
        #pragma unroll
        for (int kk = 0; kk < 4; kk++) {
            uint32_t a[2][4], bg[2][4], bu[2][4];
            ldsm4(a[0], base + aoff + kk * 32);
            ldsm4(a[1], base + aoff + 16 * ROWB + kk * 32);
            ldsm4(bg[0], base + 18432 + boff + kk * 32);
            ldsm4(bg[1], base + 18432 + boff + 16 * ROWB + kk * 32);
            ldsm4(bu[0], base + 27648 + boff + kk * 32);
            ldsm4(bu[1], base + 27648 + boff + 16 * ROWB + kk * 32);
            #pragma unroll
            for (int mt = 0; mt < 2; mt++)
                #pragma unroll
                for (int ng = 0; ng < 2; ng++)
                    #pragma unroll
                    for (int hh = 0; hh < 2; hh++) {
                        mma_f16(accg[mt][ng * 2 + hh], a[mt], &bg[ng][hh * 2]);
                        mma_f16(accu[mt][ng * 2 + hh], a[mt], &bu[ng][hh * 2]);
                    }
        }
    }

    #pragma unroll
    for (int mt = 0; mt < 2; mt++) {
        #pragma unroll
        for (int nt = 0; nt < 4; nt++) {
            int r0 = moff + wm * 32 + mt * 16 + (lane >> 2);
            int c  = n0 + wn * 32 + nt * 8 + 2 * (lane & 3);
            if (r0 < cnt) {
                __half* dst = g_act + (size_t)(off + r0) * INTER + c;
                float g0 = accg[mt][nt][0], u0 = accu[mt][nt][0];
                float g1 = accg[mt][nt][1], u1 = accu[mt][nt][1];
                *(__half2*)dst = __floats2half2_rn((g0 / (1.f + __expf(-g0))) * u0,
                                                   (g1 / (1.f + __expf(-g1))) * u1);
            }
            int r1 = r0 + 8;
            if (r1 < cnt) {
                __half* dst = g_act + (size_t)(off + r1) * INTER + c;
                float g0 = accg[mt][nt][2], u0 = accu[mt][nt][2];
                float g1 = accg[mt][nt][3], u1 = accu[mt][nt][3];
                *(__half2*)dst = __floats2half2_rn((g0 / (1.f + __expf(-g0))) * u0,
                                                   (g1 / (1.f + __expf(-g1))) * u1);
            }
        }
    }
}

// ---------------------------------------------------------------------------
// K6: GEMM2 (down) + fused weighted combine via atomicAdd. Per-expert launch.
// ---------------------------------------------------------------------------
__global__ void __launch_bounds__(256, 2)
k_ffn2(float* __restrict__ out, int e) {
    extern __shared__ __align__(16) char sm[];
    int cnt  = g_counts[e];
    int moff = blockIdx.x * BM;
    if (moff >= cnt) return;
    int off = g_offsets[e];
    int n0  = blockIdx.y * BN;
    int tid = threadIdx.x;

    int c16 = tid & 7;
    int rb  = tid >> 3;
    const char* srcA[4];
    uint32_t dA[4];
    #pragma unroll
    for (int t = 0; t < 4; t++) {
        int row = rb + 32 * t;
        dA[t] = (uint32_t)row * ROWB + c16 * 16u;
        int r = moff + row; if (r > cnt - 1) r = cnt - 1;
        srcA[t] = (const char*)(g_act + (size_t)(off + r) * INTER) + c16 * 16;
    }
    const char* srcB = (const char*)(g_dp_h + (size_t)e * HIDDEN * INTER +
                                     (size_t)(n0 + rb) * INTER) + c16 * 16;
    const uint32_t dB = 18432u + (uint32_t)rb * ROWB + c16 * 16u;
    const size_t BROW32 = (size_t)32 * INTER * 2;

    #pragma unroll
    for (int s = 0; s < 2; s++) {
        char* st = sm + s * STG2;
        int adv = s * 128;
        #pragma unroll
        for (int t = 0; t < 4; t++) cp16(st + dA[t], srcA[t] + adv);
        cp16(st + dB, srcB + adv); cp16(st + dB + 32 * ROWB, srcB + BROW32 + adv);
        cp_commit();
    }

    uint32_t sb = smem_u32(sm);
    int w = tid >> 5, lane = tid & 31;
    int wm = w >> 1, wn = w & 1;
    uint32_t aoff = (uint32_t)(wm * 32 + (lane & 15)) * ROWB + (lane >> 4) * 16u;
    uint32_t boff = (uint32_t)(wn * 32 + (lane & 7) + ((lane >> 4) << 3)) * ROWB
                    + ((lane >> 3) & 1) * 16u;

    float acc[2][4][4];
    #pragma unroll
    for (int mt = 0; mt < 2; mt++)
        #pragma unroll
        for (int nt = 0; nt < 4; nt++)
            #pragma unroll
            for (int q = 0; q < 4; q++) acc[mt][nt][q] = 0.f;

    const int T = INTER / BKH;  // 44
    for (int j = 0; j < T; j++) {
        if (j < T - 1) cp_wait1(); else cp_wait0();
        __syncthreads();
        if (j + 2 < T) {
            char* st = sm + ((j + 2) % 3) * STG2;
            int adv = (j + 2) * 128;
            #pragma unroll
            for (int t = 0; t < 4; t++) cp16(st + dA[t], srcA[t] + adv);
            cp16(st + dB, srcB + adv); cp16(st + dB + 32 * ROWB, srcB + BROW32 + adv);
            cp_commit();
        }
        uint32_t base = sb + (uint32_t)(j % 3) * STG2;
        #pragma unroll
        for (int kk = 0; kk < 4; kk++) {
            uint32_t a[2][4], bb[2][4];
            ldsm4(a[0], base + aoff + kk * 32);
            ldsm4(a[1], base + aoff + 16 * ROWB + kk * 32);
            ldsm4(bb[0], base + 18432 + boff + kk * 32);
            ldsm4(bb[1], base + 18432 + boff + 16 * ROWB + kk * 32);
            #pragma unroll
            for (int mt = 0; mt < 2; mt++)
                #pragma unroll
                for (int ng = 0; ng < 2; ng++)
                    #pragma unroll
                    for (int hh = 0; hh < 2; hh++)
                        mma_f16(acc[mt][ng * 2 + hh], a[mt], &bb[ng][hh * 2]);
        }
    }

    #pragma unroll
    for (int mt = 0; mt < 2; mt++) {
        int r0 = moff + wm * 32 + mt * 16 + (lane >> 2);
        int r1 = r0 + 8;
        int   t0 = 0, t1 = 0;
        float w0 = 0.f, w1 = 0.f;
        bool ok0 = r0 < cnt, ok1 = r1 < cnt;
        if (ok0) { t0 = g_pair_token[off + r0]; w0 = g_pair_w[off + r0]; }
        if (ok1) { t1 = g_pair_token[off + r1]; w1 = g_pair_w[off + r1]; }
        #pragma unroll
        for (int nt = 0; nt < 4; nt++) {
            int c = n0 + wn * 32 + nt * 8 + 2 * (lane & 3);
            if (ok0) {
                float* dst = out + (size_t)t0 * HIDDEN + c;
                atomicAdd(dst + 0, w0 * acc[mt][nt][0]);
                atomicAdd(dst + 1, w0 * acc[mt][nt][1]);
            }
            if (ok1) {
                float* dst = out + (size_t)t1 * HIDDEN + c;
                atomicAdd(dst + 0, w1 * acc[mt][nt][2]);
                atomicAdd(dst + 1, w1 * acc[mt][nt][3]);
            }
        }
    }
}

// ---------------------------------------------------------------------------
extern "C" void kernel_launch(void* const* d_in, const int* in_sizes, int n_in,
                              void* d_out, int out_size) {
    const float* hs   = (const float*)d_in[0];
    const int*   tid  = (const int*)d_in[1];
    const float* temb = (const float*)d_in[2];
    const float* trw  = (const float*)d_in[3];
    const float* gw   = (const float*)d_in[4];
    const float* gp   = (const float*)d_in[5];
    const float* up   = (const float*)d_in[6];
    const float* dp   = (const float*)d_in[7];
    float* out = (float*)d_out;

    cudaFuncSetAttribute(k_ffn1, cudaFuncAttributeMaxDynamicSharedMemorySize, SMEM1);
    cudaFuncSetAttribute(k_ffn2, cudaFuncAttributeMaxDynamicSharedMemorySize, SMEM2);

    __half* gph; __half* uph; __half* dph;
    cudaGetSymbolAddress((void**)&gph, g_gp_h);
    cudaGetSymbolAddress((void**)&uph, g_up_h);
    cudaGetSymbolAddress((void**)&dph, g_dp_h);

    // route on default stream; fork cvt to side stream
    k_task_route<<<1, 256>>>(temb, tid, trw);
    cudaEventRecord(ev_route, 0);
    cudaStreamWaitEvent(s_cvt, ev_route, 0);

    dim3 gc(440, 3, NE);
    k_cvt3<<<gc, 256, 0, s_cvt>>>((const float4*)gp, (const float4*)up, (const float4*)dp,
                                  (uint4*)gph, (uint4*)uph, (uint4*)dph);
    cudaEventRecord(ev_cvt, s_cvt);

    // gating chain on default stream, concurrent with cvt
    k_gate<<<NTOK / 8, 256>>>(hs, temb, tid, gw, out);
    k_prefix<<<1, 32>>>();
    k_place<<<NTOK / 256, 256>>>();
    cudaEventRecord(ev_prep, 0);

    // per-expert GEMM chains on 4 streams (stream i: experts i, i+4)
    dim3 g1(NTOK / BM, INTER / BN);   // 64 x 44
    dim3 g2(NTOK / BM, HIDDEN / BN);  // 64 x 16
    for (int i = 0; i < 4; i++) {
        cudaStreamWaitEvent(s_exp[i], ev_cvt, 0);
        cudaStreamWaitEvent(s_exp[i], ev_prep, 0);
        k_ffn1<<<g1, 256, SMEM1, s_exp[i]>>>(i);
        k_ffn2<<<g2, 256, SMEM2, s_exp[i]>>>(out, i);
        k_ffn1<<<g1, 256, SMEM1, s_exp[i]>>>(i + 4);
        k_ffn2<<<g2, 256, SMEM2, s_exp[i]>>>(out, i + 4);
        cudaEventRecord(ev_done[i], s_exp[i]);
    }
    for (int i = 0; i < 4; i++)
        cudaStreamWaitEvent(0, ev_done[i], 0);
}

// round 13
// speedup vs baseline: 7.4575x; 1.0106x over previous
#include <cuda_runtime.h>
#include <cuda_fp16.h>
#include <math.h>
#include <stdint.h>

#define HIDDEN 1024
#define INTER  2816
#define NE     8
#define TOPK   2
#define NTASKEXP 4
#define NGEN   2
#define NTOK   8192
#define NPAIR  (NTOK*TOPK)
#define WELEM  (NE*INTER*HIDDEN)

#define BM 128
#define BN 64
#define BKH 64            // K halves per stage (128B row)
#define ROWB 144          // row stride bytes (128 data + 16 pad)
#define STG1 36864        // (128+64+64) rows * 144B
#define STG2 27648        // (128+64) rows * 144B
#define SMEM1 (3*STG1)    // 110592 -> 2 blocks/SM
#define SMEM2 (3*STG2)    // 82944  -> 2 blocks/SM

// ---- scratch (static device memory; no runtime allocation) ----
__device__ int    g_active[NE];
__device__ int    g_counts[NE];
__device__ int    g_offsets[NE];
__device__ int    g_cursor[NE];
__device__ int    g_pair_token[NPAIR];
__device__ float  g_pair_w[NPAIR];
__device__ int    g_tok_e[NTOK * TOPK];
__device__ float  g_tok_w[NTOK * TOPK];
__device__ __half g_act[(size_t)NPAIR * INTER];
__device__ __half g_hs_h[(size_t)NTOK * HIDDEN];
__device__ __half g_gp_h[(size_t)WELEM];
__device__ __half g_up_h[(size_t)WELEM];
__device__ __half g_dp_h[(size_t)WELEM];

// ---- streams/events (created once at static init; no device memory) ----
static cudaStream_t s_cvt, s_exp[4];
static cudaEvent_t  ev_route, ev_cvt, ev_prep, ev_done[4];
namespace {
struct StreamInit {
    StreamInit() {
        cudaStreamCreateWithFlags(&s_cvt, cudaStreamNonBlocking);
        for (int i = 0; i < 4; i++)
            cudaStreamCreateWithFlags(&s_exp[i], cudaStreamNonBlocking);
        cudaEventCreateWithFlags(&ev_route, cudaEventDisableTiming);
        cudaEventCreateWithFlags(&ev_cvt,   cudaEventDisableTiming);
        cudaEventCreateWithFlags(&ev_prep,  cudaEventDisableTiming);
        for (int i = 0; i < 4; i++)
            cudaEventCreateWithFlags(&ev_done[i], cudaEventDisableTiming);
    }
};
static StreamInit s_stream_init;
}

// ---------------------------------------------------------------------------
__device__ __forceinline__ void cp16(void* smem_ptr, const void* gptr) {
    uint32_t s = (uint32_t)__cvta_generic_to_shared(smem_ptr);
    asm volatile("cp.async.cg.shared.global [%0], [%1], 16;\n" :: "r"(s), "l"(gptr));
}
__device__ __forceinline__ void cp_commit() { asm volatile("cp.async.commit_group;\n"); }
__device__ __forceinline__ void cp_wait0()  { asm volatile("cp.async.wait_group 0;\n" ::: "memory"); }
__device__ __forceinline__ void cp_wait1()  { asm volatile("cp.async.wait_group 1;\n" ::: "memory"); }

__device__ __forceinline__ uint32_t smem_u32(const void* p) {
    return (uint32_t)__cvta_generic_to_shared(p);
}
__device__ __forceinline__ void ldsm4(uint32_t* r, uint32_t addr) {
    asm volatile("ldmatrix.sync.aligned.m8n8.x4.shared.b16 {%0,%1,%2,%3}, [%4];"
                 : "=r"(r[0]), "=r"(r[1]), "=r"(r[2]), "=r"(r[3]) : "r"(addr));
}
__device__ __forceinline__ void mma_f16(float* c, const uint32_t* a, const uint32_t* b) {
    asm volatile(
        "mma.sync.aligned.m16n8k16.row.col.f32.f16.f16.f32 "
        "{%0,%1,%2,%3}, {%4,%5,%6,%7}, {%8,%9}, {%0,%1,%2,%3};"
        : "+f"(c[0]), "+f"(c[1]), "+f"(c[2]), "+f"(c[3])
        : "r"(a[0]), "r"(a[1]), "r"(a[2]), "r"(a[3]), "r"(b[0]), "r"(b[1]));
}

// ---------------------------------------------------------------------------
// K1: task routing + counter reset
// ---------------------------------------------------------------------------
__global__ void k_task_route(const float* __restrict__ task_emb,
                             const int* __restrict__ task_id_p,
                             const float* __restrict__ trw) {
    __shared__ float sc[NE];
    int tid  = threadIdx.x;
    int e    = tid / 32;
    int lane = tid % 32;
    const float* tv = task_emb + (size_t)task_id_p[0] * HIDDEN;
    float acc = 0.f;
    if (e < NE) {
        for (int d = lane; d < HIDDEN; d += 32)
            acc += trw[(size_t)e * HIDDEN + d] * tv[d];
        #pragma unroll
        for (int o = 16; o > 0; o >>= 1)
            acc += __shfl_xor_sync(0xFFFFFFFFu, acc, o);
        if (lane == 0) sc[e] = acc;
    }
    __syncthreads();
    if (tid == 0) {
        float s[NE]; bool act[NE];
        for (int i = 0; i < NE; i++) { s[i] = sc[i]; act[i] = false; }
        for (int k = 0; k < NTASKEXP; k++) {
            int best = 0; float bv = -1e30f;
            for (int i = 0; i < NE; i++)
                if (!act[i] && s[i] > bv) { bv = s[i]; best = i; }
            act[best] = true;
        }
        for (int i = NE - NGEN; i < NE; i++) act[i] = true;
        for (int i = 0; i < NE; i++) {
            g_active[i] = act[i] ? 1 : 0;
            g_counts[i] = 0;
            g_cursor[i] = 0;
        }
    }
}

// ---------------------------------------------------------------------------
// K2: token gating (exact fp32, gw cached in smem) + fp16 hs copy + zero out
// ---------------------------------------------------------------------------
__global__ void __launch_bounds__(256)
k_gate(const float* __restrict__ hs,
       const float* __restrict__ task_emb,
       const int* __restrict__ task_id_p,
       const float* __restrict__ gw,
       float* __restrict__ out) {
    __shared__ float4 s_gw[NE * HIDDEN / 4];   // 32 KB
    int tid = threadIdx.x;
    int wid = tid >> 5;
    int lane = tid & 31;
    int token = blockIdx.x * 8 + wid;

    #pragma unroll
    for (int t = 0; t < 8; t++)
        s_gw[tid + t * 256] = ((const float4*)gw)[tid + t * 256];

    float4* oz = (float4*)(out + (size_t)token * HIDDEN);
    #pragma unroll
    for (int t = 0; t < 8; t++)
        oz[lane + t * 32] = make_float4(0.f, 0.f, 0.f, 0.f);

    __syncthreads();

    const float4* tv4 = (const float4*)(task_emb + (size_t)task_id_p[0] * HIDDEN);
    const float4* h4  = (const float4*)(hs + (size_t)token * HIDDEN);
    uint2* ht4 = (uint2*)(g_hs_h + (size_t)token * HIDDEN);

    float acc[NE];
    #pragma unroll
    for (int e = 0; e < NE; e++) acc[e] = 0.f;

    #pragma unroll
    for (int it = 0; it < 8; it++) {
        int d4 = lane + it * 32;
        float4 hv = h4[d4];
        float4 tq = tv4[d4];
        __half2 lo = __floats2half2_rn(hv.x, hv.y);
        __half2 hi = __floats2half2_rn(hv.z, hv.w);
        uint2 o;
        o.x = *(const uint32_t*)&lo;
        o.y = *(const uint32_t*)&hi;
        ht4[d4] = o;
        float x0 = hv.x + tq.x, x1 = hv.y + tq.y, x2 = hv.z + tq.z, x3 = hv.w + tq.w;
        #pragma unroll
        for (int e = 0; e < NE; e++) {
            float4 wv = s_gw[e * (HIDDEN / 4) + d4];
            acc[e] += x0 * wv.x + x1 * wv.y + x2 * wv.z + x3 * wv.w;
        }
    }
    #pragma unroll
    for (int e = 0; e < NE; e++) {
        #pragma unroll
        for (int o = 16; o > 0; o >>= 1)
            acc[e] += __shfl_xor_sync(0xFFFFFFFFu, acc[e], o);
    }
    if (lane == 0) {
        float m = -1e30f;
        #pragma unroll
        for (int e = 0; e < NE; e++)
            if (g_active[e] && acc[e] > m) m = acc[e];
        float p[NE]; float Z = 0.f;
        #pragma unroll
        for (int e = 0; e < NE; e++) {
            p[e] = g_active[e] ? expf(acc[e] - m) : 0.f;
            Z += p[e];
        }
        float inv = 1.f / Z;
        int i0 = 0; float v0 = -1.f;
        #pragma unroll
        for (int e = 0; e < NE; e++) {
            float s = p[e] * inv;
            if (s > v0) { v0 = s; i0 = e; }
        }
        int i1 = -1; float v1 = -1.f;
        #pragma unroll
        for (int e = 0; e < NE; e++) {
            if (e == i0) continue;
            float s = p[e] * inv;
            if (s > v1) { v1 = s; i1 = e; }
        }
        float ws = v0 + v1 + 1e-6f;
        g_tok_e[token * 2 + 0] = i0;
        g_tok_e[token * 2 + 1] = i1;
        g_tok_w[token * 2 + 0] = v0 / ws;
        g_tok_w[token * 2 + 1] = v1 / ws;
        atomicAdd(&g_counts[i0], 1);
        atomicAdd(&g_counts[i1], 1);
    }
}

__global__ void k_prefix() {
    if (threadIdx.x == 0) {
        int o = 0;
        for (int e = 0; e < NE; e++) { g_offsets[e] = o; o += g_counts[e]; }
    }
}

__global__ void k_place() {
    int n = blockIdx.x * blockDim.x + threadIdx.x;
    if (n >= NTOK) return;
    #pragma unroll
    for (int k = 0; k < TOPK; k++) {
        int e = g_tok_e[n * 2 + k];
        int slot = atomicAdd(&g_cursor[e], 1);
        int idx = g_offsets[e] + slot;
        g_pair_token[idx] = n;
        g_pair_w[idx] = g_tok_w[n * 2 + k];
    }
}

// ---------------------------------------------------------------------------
// per-expert weight fp32 -> fp16 (gp, up, dp for one expert; active only)
// ---------------------------------------------------------------------------
__global__ void k_cvt_e(const float4* __restrict__ gp, const float4* __restrict__ up,
                        const float4* __restrict__ dp,
                        uint4* __restrict__ gph, uint4* __restrict__ uph,
                        uint4* __restrict__ dph, int e) {
    if (!g_active[e]) return;
    const int n8 = INTER * HIDDEN / 8;
    const float4* in = (blockIdx.y == 0) ? gp : (blockIdx.y == 1) ? up : dp;
    uint4* out = (blockIdx.y == 0) ? gph : (blockIdx.y == 1) ? uph : dph;
    const float4* src = in + (size_t)e * n8 * 2;
    uint4* dst = out + (size_t)e * n8;
    for (int i = blockIdx.x * blockDim.x + threadIdx.x; i < n8; i += gridDim.x * blockDim.x) {
        float4 v0 = src[i * 2 + 0];
        float4 v1 = src[i * 2 + 1];
        __half2 a = __floats2half2_rn(v0.x, v0.y);
        __half2 b = __floats2half2_rn(v0.z, v0.w);
        __half2 c = __floats2half2_rn(v1.x, v1.y);
        __half2 d = __floats2half2_rn(v1.z, v1.w);
        uint4 o;
        o.x = *(const uint32_t*)&a;
        o.y = *(const uint32_t*)&b;
        o.z = *(const uint32_t*)&c;
        o.w = *(const uint32_t*)&d;
        dst[i] = o;
    }
}

// ---------------------------------------------------------------------------
// K5: GEMM1 (gate & up fused) + SwiGLU. BK=64, 3-stage, 2 blocks/SM.
// ---------------------------------------------------------------------------
__global__ void __launch_bounds__(256, 2)
k_ffn1(int e) {
    extern __shared__ __align__(16) char sm[];
    int cnt  = g_counts[e];
    int moff = blockIdx.x * BM;
    if (moff >= cnt) return;
    int off = g_offsets[e];
    int n0  = blockIdx.y * BN;
    int tid = threadIdx.x;

    int c16 = tid & 7;
    int rb  = tid >> 3;
    const char* srcA[4];
    uint32_t dA[4];
    #pragma unroll
    for (int t = 0; t < 4; t++) {
        int row = rb + 32 * t;
        dA[t] = (uint32_t)row * ROWB + c16 * 16u;
        int r = moff + row; if (r > cnt - 1) r = cnt - 1;
        srcA[t] = (const char*)(g_hs_h + (size_t)g_pair_token[off + r] * HIDDEN) + c16 * 16;
    }
    const char* srcG = (const char*)(g_gp_h + (size_t)e * INTER * HIDDEN +
                                     (size_t)(n0 + rb) * HIDDEN) + c16 * 16;
    const char* srcU = (const char*)(g_up_h + (size_t)e * INTER * HIDDEN +
                                     (size_t)(n0 + rb) * HIDDEN) + c16 * 16;
    const uint32_t dG = 18432u + (uint32_t)rb * ROWB + c16 * 16u;
    const uint32_t dU = 27648u + (uint32_t)rb * ROWB + c16 * 16u;
    const size_t BROW32 = (size_t)32 * HIDDEN * 2;

    #pragma unroll
    for (int s = 0; s < 2; s++) {
        char* st = sm + s * STG1;
        int adv = s * 128;
        #pragma unroll
        for (int t = 0; t < 4; t++) cp16(st + dA[t], srcA[t] + adv);
        cp16(st + dG, srcG + adv); cp16(st + dG + 32 * ROWB, srcG + BROW32 + adv);
        cp16(st + dU, srcU + adv); cp16(st + dU + 32 * ROWB, srcU + BROW32 + adv);
        cp_commit();
    }

    uint32_t sb = smem_u32(sm);
    int w = tid >> 5, lane = tid & 31;
    int wm = w >> 1, wn = w & 1;
    uint32_t aoff = (uint32_t)(wm * 32 + (lane & 15)) * ROWB + (lane >> 4) * 16u;
    uint32_t boff = (uint32_t)(wn * 32 + (lane & 7) + ((lane >> 4) << 3)) * ROWB
                    + ((lane >> 3) & 1) * 16u;

    float accg[2][4][4], accu[2][4][4];
    #pragma unroll
    for (int mt = 0; mt < 2; mt++)
        #pragma unroll
        for (int nt = 0; nt < 4; nt++)
            #pragma unroll
            for (int q = 0; q < 4; q++) { accg[mt][nt][q] = 0.f; accu[mt][nt][q] = 0.f; }

    const int T = HIDDEN / BKH;  // 16
    for (int j = 0; j < T; j++) {
        if (j < T - 1) cp_wait1(); else cp_wait0();
        __syncthreads();
        if (j + 2 < T) {
            char* st = sm + ((j + 2) % 3) * STG1;
            int adv = (j + 2) * 128;
            #pragma unroll
            for (int t = 0; t < 4; t++) cp16(st + dA[t], srcA[t] + adv);
            cp16(st + dG, srcG + adv); cp16(st + dG + 32 * ROWB, srcG + BROW32 + adv);
            cp16(st + dU, srcU + adv); cp16(st + dU + 32 * ROWB, srcU + BROW32 + adv);
            cp_commit();
        }
        uint32_t base = sb + (uint32_t)(j % 3) * STG1;
        #pragma unroll
        for (int kk = 0; kk < 4; kk++) {
            uint32_t a[2][4], bg[2][4], bu[2][4];
            ldsm4(a[0], base + aoff + kk * 32);
            ldsm4(a[1], base + aoff + 16 * ROWB + kk * 32);
            ldsm4(bg[0], base + 18432 + boff + kk * 32);
            ldsm4(bg[1], base + 18432 + boff + 16 * ROWB + kk * 32);
            ldsm4(bu[0], base + 27648 + boff + kk * 32);
            ldsm4(bu[1], base + 27648 + boff + 16 * ROWB + kk * 32);
            #pragma unroll
            for (int mt = 0; mt < 2; mt++)
                #pragma unroll
                for (int ng = 0; ng < 2; ng++)
                    #pragma unroll
                    for (int hh = 0; hh < 2; hh++) {
                        mma_f16(accg[mt][ng * 2 + hh], a[mt], &bg[ng][hh * 2]);
                        mma_f16(accu[mt][ng * 2 + hh], a[mt], &bu[ng][hh * 2]);
                    }
        }
    }

    #pragma unroll
    for (int mt = 0; mt < 2; mt++) {
        #pragma unroll
        for (int nt = 0; nt < 4; nt++) {
            int r0 = moff + wm * 32 + mt * 16 + (lane >> 2);
            int c  = n0 + wn * 32 + nt * 8 + 2 * (lane & 3);
            if (r0 < cnt) {
                __half* dst = g_act + (size_t)(off + r0) * INTER + c;
                float g0 = accg[mt][nt][0], u0 = accu[mt][nt][0];
                float g1 = accg[mt][nt][1], u1 = accu[mt][nt][1];
                *(__half2*)dst = __floats2half2_rn((g0 / (1.f + __expf(-g0))) * u0,
                                                   (g1 / (1.f + __expf(-g1))) * u1);
            }
            int r1 = r0 + 8;
            if (r1 < cnt) {
                __half* dst = g_act + (size_t)(off + r1) * INTER + c;
                float g0 = accg[mt][nt][2], u0 = accu[mt][nt][2];
                float g1 = accg[mt][nt][3], u1 = accu[mt][nt][3];
                *(__half2*)dst = __floats2half2_rn((g0 / (1.f + __expf(-g0))) * u0,
                                                   (g1 / (1.f + __expf(-g1))) * u1);
            }
        }
    }
}

// ---------------------------------------------------------------------------
// K6: GEMM2 (down) + fused weighted combine via atomicAdd.
// ---------------------------------------------------------------------------
__global__ void __launch_bounds__(256, 2)
k_ffn2(float* __restrict__ out, int e) {
    extern __shared__ __align__(16) char sm[];
    int cnt  = g_counts[e];
    int moff = blockIdx.x * BM;
    if (moff >= cnt) return;
    int off = g_offsets[e];
    int n0  = blockIdx.y * BN;
    int tid = threadIdx.x;

    int c16 = tid & 7;
    int rb  = tid >> 3;
    const char* srcA[4];
    uint32_t dA[4];
    #pragma unroll
    for (int t = 0; t < 4; t++) {
        int row = rb + 32 * t;
        dA[t] = (uint32_t)row * ROWB + c16 * 16u;
        int r = moff + row; if (r > cnt - 1) r = cnt - 1;
        srcA[t] = (const char*)(g_act + (size_t)(off + r) * INTER) + c16 * 16;
    }
    const char* srcB = (const char*)(g_dp_h + (size_t)e * HIDDEN * INTER +
                                     (size_t)(n0 + rb) * INTER) + c16 * 16;
    const uint32_t dB = 18432u + (uint32_t)rb * ROWB + c16 * 16u;
    const size_t BROW32 = (size_t)32 * INTER * 2;

    #pragma unroll
    for (int s = 0; s < 2; s++) {
        char* st = sm + s * STG2;
        int adv = s * 128;
        #pragma unroll
        for (int t = 0; t < 4; t++) cp16(st + dA[t], srcA[t] + adv);
        cp16(st + dB, srcB + adv); cp16(st + dB + 32 * ROWB, srcB + BROW32 + adv);
        cp_commit();
    }

    uint32_t sb = smem_u32(sm);
    int w = tid >> 5, lane = tid & 31;
    int wm = w >> 1, wn = w & 1;
    uint32_t aoff = (uint32_t)(wm * 32 + (lane & 15)) * ROWB + (lane >> 4) * 16u;
    uint32_t boff = (uint32_t)(wn * 32 + (lane & 7) + ((lane >> 4) << 3)) * ROWB
                    + ((lane >> 3) & 1) * 16u;

    float acc[2][4][4];
    #pragma unroll
    for (int mt = 0; mt < 2; mt++)
        #pragma unroll
        for (int nt = 0; nt < 4; nt++)
            #pragma unroll
            for (int q = 0; q < 4; q++) acc[mt][nt][q] = 0.f;

    const int T = INTER / BKH;  // 44
    for (int j = 0; j < T; j++) {
        if (j < T - 1) cp_wait1(); else cp_wait0();
        __syncthreads();
        if (j + 2 < T) {
            char* st = sm + ((j + 2) % 3) * STG2;
            int adv = (j + 2) * 128;
            #pragma unroll
            for (int t = 0; t < 4; t++) cp16(st + dA[t], srcA[t] + adv);
            cp16(st + dB, srcB + adv); cp16(st + dB + 32 * ROWB, srcB + BROW32 + adv);
            cp_commit();
        }
        uint32_t base = sb + (uint32_t)(j % 3) * STG2;
        #pragma unroll
        for (int kk = 0; kk < 4; kk++) {
            uint32_t a[2][4], bb[2][4];
            ldsm4(a[0], base + aoff + kk * 32);
            ldsm4(a[1], base + aoff + 16 * ROWB + kk * 32);
            ldsm4(bb[0], base + 18432 + boff + kk * 32);
            ldsm4(bb[1], base + 18432 + boff + 16 * ROWB + kk * 32);
            #pragma unroll
            for (int mt = 0; mt < 2; mt++)
                #pragma unroll
                for (int ng = 0; ng < 2; ng++)
                    #pragma unroll
                    for (int hh = 0; hh < 2; hh++)
                        mma_f16(acc[mt][ng * 2 + hh], a[mt], &bb[ng][hh * 2]);
        }
    }

    #pragma unroll
    for (int mt = 0; mt < 2; mt++) {
        int r0 = moff + wm * 32 + mt * 16 + (lane >> 2);
        int r1 = r0 + 8;
        int   t0 = 0, t1 = 0;
        float w0 = 0.f, w1 = 0.f;
        bool ok0 = r0 < cnt, ok1 = r1 < cnt;
        if (ok0) { t0 = g_pair_token[off + r0]; w0 = g_pair_w[off + r0]; }
        if (ok1) { t1 = g_pair_token[off + r1]; w1 = g_pair_w[off + r1]; }
        #pragma unroll
        for (int nt = 0; nt < 4; nt++) {
            int c = n0 + wn * 32 + nt * 8 + 2 * (lane & 3);
            if (ok0) {
                float* dst = out + (size_t)t0 * HIDDEN + c;
                atomicAdd(dst + 0, w0 * acc[mt][nt][0]);
                atomicAdd(dst + 1, w0 * acc[mt][nt][1]);
            }
            if (ok1) {
                float* dst = out + (size_t)t1 * HIDDEN + c;
                atomicAdd(dst + 0, w1 * acc[mt][nt][2]);
                atomicAdd(dst + 1, w1 * acc[mt][nt][3]);
            }
        }
    }
}

// ---------------------------------------------------------------------------
extern "C" void kernel_launch(void* const* d_in, const int* in_sizes, int n_in,
                              void* d_out, int out_size) {
    const float* hs   = (const float*)d_in[0];
    const int*   tid  = (const int*)d_in[1];
    const float* temb = (const float*)d_in[2];
    const float* trw  = (const float*)d_in[3];
    const float* gw   = (const float*)d_in[4];
    const float* gp   = (const float*)d_in[5];
    const float* up   = (const float*)d_in[6];
    const float* dp   = (const float*)d_in[7];
    float* out = (float*)d_out;

    cudaFuncSetAttribute(k_ffn1, cudaFuncAttributeMaxDynamicSharedMemorySize, SMEM1);
    cudaFuncSetAttribute(k_ffn2, cudaFuncAttributeMaxDynamicSharedMemorySize, SMEM2);

    __half* gph; __half* uph; __half* dph;
    cudaGetSymbolAddress((void**)&gph, g_gp_h);
    cudaGetSymbolAddress((void**)&uph, g_up_h);
    cudaGetSymbolAddress((void**)&dph, g_dp_h);

    // route on default stream; everything depends on it
    k_task_route<<<1, 256>>>(temb, tid, trw);
    cudaEventRecord(ev_route, 0);

    // gating chain on default stream (concurrent with per-expert cvts)
    k_gate<<<NTOK / 8, 256>>>(hs, temb, tid, gw, out);
    k_prefix<<<1, 32>>>();
    k_place<<<NTOK / 256, 256>>>();
    cudaEventRecord(ev_prep, 0);

    dim3 gc(256, 3);                  // per-expert cvt: 3 tensors
    dim3 g1(NTOK / BM, INTER / BN);   // 64 x 44
    dim3 g2(NTOK / BM, HIDDEN / BN);  // 64 x 16

    // experts 4..7 weights convert on side stream (hidden under first GEMM wave)
    cudaStreamWaitEvent(s_cvt, ev_route, 0);
    for (int e = 4; e < 8; e++)
        k_cvt_e<<<gc, 256, 0, s_cvt>>>((const float4*)gp, (const float4*)up, (const float4*)dp,
                                       (uint4*)gph, (uint4*)uph, (uint4*)dph, e);
    cudaEventRecord(ev_cvt, s_cvt);

    // per-expert chains: stream i handles experts i and i+4
    for (int i = 0; i < 4; i++) {
        cudaStreamWaitEvent(s_exp[i], ev_route, 0);
        k_cvt_e<<<gc, 256, 0, s_exp[i]>>>((const float4*)gp, (const float4*)up, (const float4*)dp,
                                          (uint4*)gph, (uint4*)uph, (uint4*)dph, i);
        cudaStreamWaitEvent(s_exp[i], ev_prep, 0);
        k_ffn1<<<g1, 256, SMEM1, s_exp[i]>>>(i);
        k_ffn2<<<g2, 256, SMEM2, s_exp[i]>>>(out, i);
        cudaStreamWaitEvent(s_exp[i], ev_cvt, 0);
        k_ffn1<<<g1, 256, SMEM1, s_exp[i]>>>(i + 4);
        k_ffn2<<<g2, 256, SMEM2, s_exp[i]>>>(out, i + 4);
        cudaEventRecord(ev_done[i], s_exp[i]);
    }
    for (int i = 0; i < 4; i++)
        cudaStreamWaitEvent(0, ev_done[i], 0);
}